// round 11
// baseline (speedup 1.0000x reference)
#include <cuda_runtime.h>
#include <cuda_fp16.h>
#include <mma.h>
#include <cstdint>
#include <math_constants.h>
#include <math.h>

using namespace nvcuda;

// ---------------- problem constants ----------------
#define CC 180
#define NHD 6
#define HDIM 30
#define NWIN 768
#define NTOK 128
#define M_ROWS 98304
#define C3 540
#define C2 360
#define HID 360
#define QKV_STR 576
#define HID_STR 384
#define Y_STR 192
#define ATT_SCALE 0.18257418583505536f

// ---------------- scratch ----------------
__device__ __half g_xw_h[M_ROWS * CC];
__device__ float  g_qkvS[M_ROWS * QKV_STR];
__device__ float  g_qkvM[M_ROWS * QKV_STR];
__device__ __half g_xo_h[M_ROWS * C2];
__device__ float  g_y[M_ROWS * Y_STR];
__device__ __half g_h2_h[M_ROWS * CC];
__device__ __half g_hid1_h[M_ROWS * HID_STR];
__device__ float  g_bias6[NHD * NTOK * NTOK];
__device__ __half g_wT_qs[576 * 192];
__device__ __half g_wT_qm[576 * 192];
__device__ __half g_wT_pr[192 * 384];
__device__ __half g_wT_f11[384 * 192];
__device__ __half g_wT_f12[384 * 192];
__device__ __half g_wT_f2[192 * 384];

__device__ __forceinline__ int row_to_img(int r) {
    int win = r >> 7, n = r & 127;
    int dwin = win >> 8, rem = win & 255;
    int hwin = rem >> 4, wwin = rem & 15;
    int nd = n >> 6, nh = (n >> 3) & 7, nw = n & 7;
    int sd = dwin * 2 + nd + 1; if (sd >= 6) sd -= 6;
    int sh = (hwin * 8 + nh + 4) & 127;
    int sw = (wwin * 8 + nw + 4) & 127;
    return (sd * 128 + sh) * 128 + sw;
}

// ---------------- weight prep + rel-pos bias (fused) ----------------
__device__ __forceinline__ void prep_one(const float* w, __half* wt, int idx,
                                         int K, int N, int Kpad, int Npad) {
    int n = idx / Kpad, k = idx % Kpad;
    wt[idx] = (n < N && k < K) ? __float2half(w[(long)k * N + n]) : __float2half(0.f);
}
__global__ void prep_qkv_kernel(const float* __restrict__ wqs, const float* __restrict__ wqm,
                                const float* __restrict__ rpb, const int* __restrict__ rpi) {
    int idx = blockIdx.x * blockDim.x + threadIdx.x;
    const int S1 = 576 * 192;
    if (idx < S1) { prep_one(wqs, g_wT_qs, idx, CC, C3, 192, 576); return; }
    idx -= S1;
    if (idx < S1) { prep_one(wqm, g_wT_qm, idx, CC, C3, 192, 576); return; }
    idx -= S1;
    if (idx < NHD * NTOK * NTOK) {
        int h = idx / (NTOK * NTOK), ij = idx % (NTOK * NTOK);
        g_bias6[idx] = rpb[rpi[ij] * NHD + h];
    }
}
__global__ void prep_rest_kernel(const float* __restrict__ wproj, const float* __restrict__ w11,
                                 const float* __restrict__ w12, const float* __restrict__ w2) {
    int idx = blockIdx.x * blockDim.x + threadIdx.x;
    const int S = 192 * 384;
    if (idx < S) prep_one(wproj, g_wT_pr, idx, C2, CC, 384, 192);
    else if (idx < 2 * S) prep_one(w11, g_wT_f11, idx - S, CC, HID, 192, 384);
    else if (idx < 3 * S) prep_one(w12, g_wT_f12, idx - 2 * S, CC, HID, 192, 384);
    else if (idx < 4 * S) prep_one(w2, g_wT_f2, idx - 3 * S, HID, CC, 384, 192);
}

// ---------------- LayerNorm: fp32 in -> fp16 out ----------------
template <int MODE>
__global__ __launch_bounds__(256) void ln_kernel(const float* __restrict__ in,
                                                 const float* __restrict__ gg,
                                                 const float* __restrict__ bb) {
    int gw = (blockIdx.x * blockDim.x + threadIdx.x) >> 5;
    int lane = threadIdx.x & 31;
    if (gw >= M_ROWS) return;
    const float* rowp;
    __half* orow;
    if (MODE == 0) {
        rowp = in + (long)row_to_img(gw) * CC;
        orow = g_xw_h + (long)gw * CC;
    } else {
        rowp = g_y + (long)gw * Y_STR;
        orow = g_h2_h + (long)gw * CC;
    }
    float vals[6];
    float s = 0.f, ss = 0.f;
    int cnt = 0;
    for (int c = lane; c < CC; c += 32) { float v = rowp[c]; vals[cnt++] = v; s += v; ss += v * v; }
#pragma unroll
    for (int o = 16; o > 0; o >>= 1) {
        s  += __shfl_xor_sync(0xffffffffu, s, o);
        ss += __shfl_xor_sync(0xffffffffu, ss, o);
    }
    float mean = s * (1.f / CC);
    float var = ss * (1.f / CC) - mean * mean;
    float rstd = rsqrtf(var + 1e-5f);
    cnt = 0;
    for (int c = lane; c < CC; c += 32)
        orow[c] = __float2half((vals[cnt++] - mean) * rstd * gg[c] + bb[c]);
}

// ---------------- qkv GEMM (unchanged from R10) ----------------
template <int WID, int ADD_PB, int DSTID>
__global__ __launch_bounds__(256) void gemm_qkv(const float* __restrict__ bias,
                                                const float* __restrict__ pb) {
    constexpr int KPAD = 192, LDA = 200, LDC = 68, NTILES = 9;
    const __half* A = g_xw_h;
    const __half* BT = (WID == 0) ? g_wT_qs : g_wT_qm;
    float* Cout = (DSTID == 0) ? g_qkvS : g_qkvM;
    extern __shared__ __align__(16) char smem[];
    __half* As = (__half*)smem;
    __half* Bs0 = As + 128 * LDA;
    __half* Bs1 = Bs0 + 64 * LDA;
    float* bias0 = (float*)(Bs1 + 64 * LDA);
    float* bias1 = bias0 + 16 * LDC;

    int tid = threadIdx.x, wid = tid >> 5;
    int m0 = blockIdx.x * 128;
    int wm = (wid & 3) * 32, wn = (wid >> 2) * 32;

    constexpr int KF4 = KPAD / 4;
    constexpr int KR4 = CC / 4;
    for (int idx = tid; idx < 128 * KF4; idx += 256) {
        int row = idx / KF4, c4 = idx % KF4;
        uint2 val = make_uint2(0u, 0u);
        if (c4 < KR4) {
            val = *(const uint2*)(A + (long)(m0 + row) * CC + c4 * 4);
            if (ADD_PB) {
                __half2 h0 = *(__half2*)&val.x, h1 = *(__half2*)&val.y;
                float4 p = *(const float4*)(pb + ((m0 + row) & 63) * CC + c4 * 4);
                float2 f0 = __half22float2(h0), f1 = __half22float2(h1);
                __half2 r0 = __floats2half2_rn(f0.x + p.x, f0.y + p.y);
                __half2 r1 = __floats2half2_rn(f1.x + p.z, f1.y + p.w);
                val.x = *(uint32_t*)&r0; val.y = *(uint32_t*)&r1;
            }
        }
        *(uint2*)(As + row * LDA + c4 * 4) = val;
    }

    constexpr int BU4 = KPAD / 8;
    constexpr int NB = (64 * BU4) / 256;
    for (int i = 0; i < NB; i++) {
        int idx = tid + i * 256;
        int n = idx / BU4, c = idx % BU4;
        *(uint4*)(Bs0 + n * LDA + c * 8) = *(const uint4*)(BT + (long)n * KPAD + c * 8);
    }
    for (int i = 0; i < 4; i++) {
        int idx = tid + i * 256;
        int row = idx >> 6, c = idx & 63;
        bias0[row * LDC + c] = bias[c];
    }
    __syncthreads();

    for (int t = 0; t < NTILES; t++) {
        __half* Bcur = (t & 1) ? Bs1 : Bs0;
        __half* Bnxt = (t & 1) ? Bs0 : Bs1;
        float* bcur = (t & 1) ? bias1 : bias0;
        float* bnxt = (t & 1) ? bias0 : bias1;
        int n0 = t * 64;
        bool has_next = (t + 1 < NTILES);

        uint4 breg[NB];
        float creg[4];
        if (has_next) {
            int n0n = n0 + 64;
#pragma unroll
            for (int i = 0; i < NB; i++) {
                int idx = tid + i * 256;
                int n = idx / BU4, c = idx % BU4;
                breg[i] = *(const uint4*)(BT + (long)(n0n + n) * KPAD + c * 8);
            }
#pragma unroll
            for (int i = 0; i < 4; i++) {
                int idx = tid + i * 256;
                int c = idx & 63;
                creg[i] = (n0n + c < C3) ? bias[n0n + c] : 0.f;
            }
        }

        wmma::fragment<wmma::accumulator, 16, 16, 16, float> acc[2][2];
#pragma unroll
        for (int i = 0; i < 2; i++)
#pragma unroll
            for (int j = 0; j < 2; j++)
                wmma::load_matrix_sync(acc[i][j], bcur + wn + j * 16, LDC, wmma::mem_row_major);
#pragma unroll
        for (int k = 0; k < KPAD; k += 16) {
            wmma::fragment<wmma::matrix_a, 16, 16, 16, __half, wmma::row_major> af[2];
            wmma::fragment<wmma::matrix_b, 16, 16, 16, __half, wmma::col_major> bf[2];
#pragma unroll
            for (int i = 0; i < 2; i++)
                wmma::load_matrix_sync(af[i], As + (wm + i * 16) * LDA + k, LDA);
#pragma unroll
            for (int j = 0; j < 2; j++)
                wmma::load_matrix_sync(bf[j], Bcur + (wn + j * 16) * LDA + k, LDA);
#pragma unroll
            for (int i = 0; i < 2; i++)
#pragma unroll
                for (int j = 0; j < 2; j++)
                    wmma::mma_sync(acc[i][j], af[i], bf[j], acc[i][j]);
        }
#pragma unroll
        for (int i = 0; i < 2; i++)
#pragma unroll
            for (int j = 0; j < 2; j++)
                wmma::store_matrix_sync(Cout + (long)(m0 + wm + i * 16) * QKV_STR + n0 + wn + j * 16,
                                        acc[i][j], QKV_STR, wmma::mem_row_major);
        if (has_next) {
#pragma unroll
            for (int i = 0; i < NB; i++) {
                int idx = tid + i * 256;
                int n = idx / BU4, c = idx % BU4;
                *(uint4*)(Bnxt + n * LDA + c * 8) = breg[i];
            }
#pragma unroll
            for (int i = 0; i < 4; i++) {
                int idx = tid + i * 256;
                int row = idx >> 6, c = idx & 63;
                bnxt[row * LDC + c] = creg[i];
            }
        }
        __syncthreads();
    }
}

// ---------------- proj GEMM (unchanged from R10) ----------------
__global__ __launch_bounds__(256) void gemm_proj(const float* __restrict__ bias,
                                                 const float* __restrict__ x) {
    constexpr int KPAD = 384, LDA = 392, LDC = 68, NTILES = 3;
    extern __shared__ __align__(16) char smem[];
    __half* As = (__half*)smem;
    __half* Bs = As + 128 * LDA;
    float* resT = (float*)(Bs + 64 * LDA);
    int* imgIdx = (int*)(resT + 128 * LDC);

    int tid = threadIdx.x, wid = tid >> 5;
    int m0 = blockIdx.x * 128;
    int wm = (wid & 3) * 32, wn = (wid >> 2) * 32;

    if (tid < 128) imgIdx[tid] = row_to_img(m0 + tid);

    constexpr int KF4 = KPAD / 4;
    constexpr int KR4 = C2 / 4;
    for (int idx = tid; idx < 128 * KF4; idx += 256) {
        int row = idx / KF4, c4 = idx % KF4;
        uint2 val = make_uint2(0u, 0u);
        if (c4 < KR4)
            val = *(const uint2*)(g_xo_h + (long)(m0 + row) * C2 + c4 * 4);
        *(uint2*)(As + row * LDA + c4 * 4) = val;
    }

    constexpr int BU4 = KPAD / 8;
    for (int t = 0; t < NTILES; t++) {
        int n0 = t * 64;
        for (int idx = tid; idx < 64 * BU4; idx += 256) {
            int n = idx / BU4, c = idx % BU4;
            *(uint4*)(Bs + n * LDA + c * 8) = *(const uint4*)(g_wT_pr + (long)(n0 + n) * KPAD + c * 8);
        }
        for (int idx = tid; idx < 128 * 16; idx += 256) {
            int row = idx >> 4, c4 = (idx & 15) * 4;
            int n = n0 + c4;
            float4 v = make_float4(0.f, 0.f, 0.f, 0.f);
            if (n + 4 <= CC) {
                const float4 bv = *(const float4*)(bias + n);
                const float4 xr = *(const float4*)(x + (long)imgIdx[row] * CC + n);
                v.x = bv.x + xr.x; v.y = bv.y + xr.y; v.z = bv.z + xr.z; v.w = bv.w + xr.w;
            }
            *(float4*)(resT + row * LDC + c4) = v;
        }
        __syncthreads();

        wmma::fragment<wmma::accumulator, 16, 16, 16, float> acc[2][2];
#pragma unroll
        for (int i = 0; i < 2; i++)
#pragma unroll
            for (int j = 0; j < 2; j++)
                wmma::load_matrix_sync(acc[i][j], resT + (wm + i * 16) * LDC + wn + j * 16, LDC, wmma::mem_row_major);
#pragma unroll
        for (int k = 0; k < KPAD; k += 16) {
            wmma::fragment<wmma::matrix_a, 16, 16, 16, __half, wmma::row_major> af[2];
            wmma::fragment<wmma::matrix_b, 16, 16, 16, __half, wmma::col_major> bf[2];
#pragma unroll
            for (int i = 0; i < 2; i++)
                wmma::load_matrix_sync(af[i], As + (wm + i * 16) * LDA + k, LDA);
#pragma unroll
            for (int j = 0; j < 2; j++)
                wmma::load_matrix_sync(bf[j], Bs + (wn + j * 16) * LDA + k, LDA);
#pragma unroll
            for (int i = 0; i < 2; i++)
#pragma unroll
                for (int j = 0; j < 2; j++)
                    wmma::mma_sync(acc[i][j], af[i], bf[j], acc[i][j]);
        }
#pragma unroll
        for (int i = 0; i < 2; i++)
#pragma unroll
            for (int j = 0; j < 2; j++)
                wmma::store_matrix_sync(g_y + (long)(m0 + wm + i * 16) * Y_STR + n0 + wn + j * 16,
                                        acc[i][j], Y_STR, wmma::mem_row_major);
        __syncthreads();
    }
}

// ---------------- fused MLP GEMM (unchanged from R10) ----------------
__global__ __launch_bounds__(256) void gemm_mlp(const float* __restrict__ bias1,
                                                const float* __restrict__ bias2) {
    constexpr int KPAD = 192, LDA = 200, LDC = 68, NTILES = 6;
    extern __shared__ __align__(16) char smem[];
    __half* As = (__half*)smem;
    __half* Bs = As + 128 * LDA;
    float* Cs = (float*)(Bs + 64 * LDA);
    float* Cs2 = Cs + 128 * LDC;
    float* biasS = Cs2 + 128 * LDC;

    int tid = threadIdx.x, wid = tid >> 5;
    int m0 = blockIdx.x * 128;
    int wm = (wid & 3) * 32, wn = (wid >> 2) * 32;

    constexpr int KF4 = KPAD / 4;
    constexpr int KR4 = CC / 4;
    for (int idx = tid; idx < 128 * KF4; idx += 256) {
        int row = idx / KF4, c4 = idx % KF4;
        uint2 val = make_uint2(0u, 0u);
        if (c4 < KR4)
            val = *(const uint2*)(g_h2_h + (long)(m0 + row) * CC + c4 * 4);
        *(uint2*)(As + row * LDA + c4 * 4) = val;
    }

    constexpr int BU4 = KPAD / 8;
    for (int t = 0; t < NTILES; t++) {
        int n0 = t * 64;
#pragma unroll
        for (int pass = 0; pass < 2; pass++) {
            const __half* Bp = (pass == 0) ? g_wT_f11 : g_wT_f12;
            const float* bp = (pass == 0) ? bias1 : bias2;
            float* Cdst = (pass == 0) ? Cs : Cs2;
            for (int idx = tid; idx < 16 * 64; idx += 256) {
                int row = idx >> 6, c = idx & 63;
                biasS[row * LDC + c] = (n0 + c < HID) ? bp[n0 + c] : 0.f;
            }
            for (int idx = tid; idx < 64 * BU4; idx += 256) {
                int n = idx / BU4, c = idx % BU4;
                *(uint4*)(Bs + n * LDA + c * 8) = *(const uint4*)(Bp + (long)(n0 + n) * KPAD + c * 8);
            }
            __syncthreads();
            wmma::fragment<wmma::accumulator, 16, 16, 16, float> acc[2][2];
#pragma unroll
            for (int i = 0; i < 2; i++)
#pragma unroll
                for (int j = 0; j < 2; j++)
                    wmma::load_matrix_sync(acc[i][j], biasS + wn + j * 16, LDC, wmma::mem_row_major);
#pragma unroll
            for (int k = 0; k < KPAD; k += 16) {
                wmma::fragment<wmma::matrix_a, 16, 16, 16, __half, wmma::row_major> af[2];
                wmma::fragment<wmma::matrix_b, 16, 16, 16, __half, wmma::col_major> bf[2];
#pragma unroll
                for (int i = 0; i < 2; i++)
                    wmma::load_matrix_sync(af[i], As + (wm + i * 16) * LDA + k, LDA);
#pragma unroll
                for (int j = 0; j < 2; j++)
                    wmma::load_matrix_sync(bf[j], Bs + (wn + j * 16) * LDA + k, LDA);
#pragma unroll
                for (int i = 0; i < 2; i++)
#pragma unroll
                    for (int j = 0; j < 2; j++)
                        wmma::mma_sync(acc[i][j], af[i], bf[j], acc[i][j]);
            }
#pragma unroll
            for (int i = 0; i < 2; i++)
#pragma unroll
                for (int j = 0; j < 2; j++)
                    wmma::store_matrix_sync(Cdst + (wm + i * 16) * LDC + wn + j * 16,
                                            acc[i][j], LDC, wmma::mem_row_major);
            __syncthreads();
        }
        for (int idx = tid; idx < 128 * 16; idx += 256) {
            int row = idx >> 4, c4 = (idx & 15) * 4;
            float4 v = *(float4*)(Cs + row * LDC + c4);
            float4 v2 = *(float4*)(Cs2 + row * LDC + c4);
            float4 o;
            o.x = 0.5f * v.x * (1.f + erff(v.x * 0.70710678f)) * v2.x;
            o.y = 0.5f * v.y * (1.f + erff(v.y * 0.70710678f)) * v2.y;
            o.z = 0.5f * v.z * (1.f + erff(v.z * 0.70710678f)) * v2.z;
            o.w = 0.5f * v.w * (1.f + erff(v.w * 0.70710678f)) * v2.w;
            __half2 a = __floats2half2_rn(o.x, o.y);
            __half2 b = __floats2half2_rn(o.z, o.w);
            *(uint2*)(g_hid1_h + (long)(m0 + row) * HID_STR + t * 64 + c4) =
                make_uint2(*(uint32_t*)&a, *(uint32_t*)&b);
        }
        __syncthreads();
    }
}

// ---------------- fc2 GEMM (unchanged from R10) ----------------
__global__ __launch_bounds__(256) void gemm_fc2(const float* __restrict__ bias,
                                                float* __restrict__ out) {
    constexpr int KPAD = 384, LDA = 392, LDC = 68, NTILES = 3;
    extern __shared__ __align__(16) char smem[];
    __half* As = (__half*)smem;
    __half* Bs = As + 128 * LDA;
    float* resT = (float*)(Bs + 64 * LDA);
    float* Cs = resT + 128 * LDC;
    int* imgIdx = (int*)(Cs + 128 * LDC);

    int tid = threadIdx.x, wid = tid >> 5;
    int m0 = blockIdx.x * 128;
    int wm = (wid & 3) * 32, wn = (wid >> 2) * 32;

    if (tid < 128) imgIdx[tid] = row_to_img(m0 + tid);

    constexpr int KF4 = KPAD / 4;
    for (int idx = tid; idx < 128 * KF4; idx += 256) {
        int row = idx / KF4, c4 = idx % KF4;
        *(uint2*)(As + row * LDA + c4 * 4) =
            *(const uint2*)(g_hid1_h + (long)(m0 + row) * HID_STR + c4 * 4);
    }

    constexpr int BU4 = KPAD / 8;
    for (int t = 0; t < NTILES; t++) {
        int n0 = t * 64;
        for (int idx = tid; idx < 64 * BU4; idx += 256) {
            int n = idx / BU4, c = idx % BU4;
            *(uint4*)(Bs + n * LDA + c * 8) = *(const uint4*)(g_wT_f2 + (long)(n0 + n) * KPAD + c * 8);
        }
        for (int idx = tid; idx < 128 * 16; idx += 256) {
            int row = idx >> 4, c4 = (idx & 15) * 4;
            int n = n0 + c4;
            float4 v = make_float4(0.f, 0.f, 0.f, 0.f);
            if (n + 4 <= CC) {
                const float4 bv = *(const float4*)(bias + n);
                const float4 yr = *(const float4*)(g_y + (long)(m0 + row) * Y_STR + n);
                v.x = bv.x + yr.x; v.y = bv.y + yr.y; v.z = bv.z + yr.z; v.w = bv.w + yr.w;
            }
            *(float4*)(resT + row * LDC + c4) = v;
        }
        __syncthreads();

        wmma::fragment<wmma::accumulator, 16, 16, 16, float> acc[2][2];
#pragma unroll
        for (int i = 0; i < 2; i++)
#pragma unroll
            for (int j = 0; j < 2; j++)
                wmma::load_matrix_sync(acc[i][j], resT + (wm + i * 16) * LDC + wn + j * 16, LDC, wmma::mem_row_major);
#pragma unroll
        for (int k = 0; k < KPAD; k += 16) {
            wmma::fragment<wmma::matrix_a, 16, 16, 16, __half, wmma::row_major> af[2];
            wmma::fragment<wmma::matrix_b, 16, 16, 16, __half, wmma::col_major> bf[2];
#pragma unroll
            for (int i = 0; i < 2; i++)
                wmma::load_matrix_sync(af[i], As + (wm + i * 16) * LDA + k, LDA);
#pragma unroll
            for (int j = 0; j < 2; j++)
                wmma::load_matrix_sync(bf[j], Bs + (wn + j * 16) * LDA + k, LDA);
#pragma unroll
            for (int i = 0; i < 2; i++)
#pragma unroll
                for (int j = 0; j < 2; j++)
                    wmma::mma_sync(acc[i][j], af[i], bf[j], acc[i][j]);
        }
#pragma unroll
        for (int i = 0; i < 2; i++)
#pragma unroll
            for (int j = 0; j < 2; j++)
                wmma::store_matrix_sync(Cs + (wm + i * 16) * LDC + wn + j * 16,
                                        acc[i][j], LDC, wmma::mem_row_major);
        __syncthreads();

        for (int idx = tid; idx < 128 * 16; idx += 256) {
            int row = idx >> 4, c4 = (idx & 15) * 4;
            int n = n0 + c4;
            if (n + 4 <= CC) {
                float4 v = *(float4*)(Cs + row * LDC + c4);
                *(float4*)(out + (long)imgIdx[row] * CC + n) = v;
            }
        }
        __syncthreads();
    }
}

// ---------------- self attention: two 64-row S passes, 3 CTAs/SM ----------------
#define LQ 40
#define LS 132
#define LO 36
__global__ __launch_bounds__(256) void self_attn_kernel(const float* __restrict__ mask) {
    int h = blockIdx.x, w = blockIdx.y;
    int tid = threadIdx.x, wid = tid >> 5, lane = tid & 31;
    extern __shared__ __align__(16) char smraw[];
    __half* Qs = (__half*)smraw;                 // [128][LQ]
    __half* Ks = Qs + 128 * LQ;
    __half* Vs = Ks + 128 * LQ;
    float* S = (float*)(Vs + 128 * LQ);          // [64][LS]
    __half* P = (__half*)S;                      // alias, half stride 2*LS
    float* Of = S + 64 * LS;                     // [64][LO]
    float* rsum = Of + 64 * LO;                  // [64]

    const float* base = g_qkvS + (long)w * NTOK * QKV_STR + h * HDIM;

    // stage Q(scaled)/K/V fp16
    {
        int row = tid >> 1, part = tid & 1;
        const float* src = base + (long)row * QKV_STR;
        int d0 = part * 15;
#pragma unroll
        for (int dd = 0; dd < 15; dd++) {
            int d = d0 + dd;
            Qs[row * LQ + d] = __float2half(src[d] * ATT_SCALE);
            Ks[row * LQ + d] = __float2half(src[180 + d]);
            Vs[row * LQ + d] = __float2half(src[360 + d]);
        }
        if (part) {
            Qs[row * LQ + 30] = __float2half(0.f); Qs[row * LQ + 31] = __float2half(0.f);
            Ks[row * LQ + 30] = __float2half(0.f); Ks[row * LQ + 31] = __float2half(0.f);
            Vs[row * LQ + 30] = __float2half(0.f); Vs[row * LQ + 31] = __float2half(0.f);
        }
    }
    __syncthreads();

    int rt = wid & 3, ch = wid >> 2;   // row tile (16 rows), column half

    for (int half = 0; half < 2; half++) {
        int q0 = half * 64;

        // S[0:64][0:128] = Q[q0:q0+64] @ K^T ; warp: rows rt*16, cols ch*64 (4 j-tiles)
        {
            wmma::fragment<wmma::accumulator, 16, 16, 16, float> acc[4];
#pragma unroll
            for (int j = 0; j < 4; j++) wmma::fill_fragment(acc[j], 0.f);
#pragma unroll
            for (int k = 0; k < 2; k++) {
                wmma::fragment<wmma::matrix_a, 16, 16, 16, __half, wmma::row_major> af;
                wmma::load_matrix_sync(af, Qs + (q0 + rt * 16) * LQ + k * 16, LQ);
#pragma unroll
                for (int j = 0; j < 4; j++) {
                    wmma::fragment<wmma::matrix_b, 16, 16, 16, __half, wmma::col_major> bf;
                    wmma::load_matrix_sync(bf, Ks + (ch * 64 + j * 16) * LQ + k * 16, LQ);
                    wmma::mma_sync(acc[j], af, bf, acc[j]);
                }
            }
#pragma unroll
            for (int j = 0; j < 4; j++)
                wmma::store_matrix_sync(S + (rt * 16) * LS + ch * 64 + j * 16, acc[j], LS, wmma::mem_row_major);
        }
        __syncthreads();

        // softmax over 64 rows (8 rows/warp); write P fp16 over S
        {
            const float* bbase = g_bias6 + h * (NTOK * NTOK);
            const float* mbase = mask + (long)w * (NTOK * NTOK);
#pragma unroll
            for (int rr = 0; rr < 8; rr++) {
                int r = wid * 8 + rr;
                int q = q0 + r;
                float4 s4 = *(float4*)(S + r * LS + lane * 4);
                float4 b4 = *(const float4*)(bbase + q * NTOK + lane * 4);
                float4 m4 = *(const float4*)(mbase + q * NTOK + lane * 4);
                float p0 = __expf(s4.x + b4.x + m4.x);
                float p1 = __expf(s4.y + b4.y + m4.y);
                float p2 = __expf(s4.z + b4.z + m4.z);
                float p3 = __expf(s4.w + b4.w + m4.w);
                __half2 h0 = __floats2half2_rn(p0, p1);
                __half2 h1 = __floats2half2_rn(p2, p3);
                *(uint2*)(P + r * (2 * LS) + lane * 4) = make_uint2(*(uint32_t*)&h0, *(uint32_t*)&h1);
                float psum = p0 + p1 + p2 + p3;
#pragma unroll
                for (int o = 16; o > 0; o >>= 1) psum += __shfl_xor_sync(0xffffffffu, psum, o);
                if (lane == 0) rsum[r] = 1.f / psum;
            }
        }
        __syncthreads();

        // O[0:64][0:32] = P @ V ; warp: rows rt*16, col tile ch (16 cols)
        {
            wmma::fragment<wmma::accumulator, 16, 16, 16, float> acc;
            wmma::fill_fragment(acc, 0.f);
#pragma unroll
            for (int k = 0; k < 8; k++) {
                wmma::fragment<wmma::matrix_a, 16, 16, 16, __half, wmma::row_major> pf;
                wmma::load_matrix_sync(pf, P + (rt * 16) * (2 * LS) + k * 16, 2 * LS);
                wmma::fragment<wmma::matrix_b, 16, 16, 16, __half, wmma::row_major> vf;
                wmma::load_matrix_sync(vf, Vs + (k * 16) * LQ + ch * 16, LQ);
                wmma::mma_sync(acc, pf, vf, acc);
            }
            wmma::store_matrix_sync(Of + (rt * 16) * LO + ch * 16, acc, LO, wmma::mem_row_major);
        }
        __syncthreads();

        // scale + write out (64 rows; threads 0..127)
        if (tid < 128) {
            int row = tid >> 1, part = tid & 1;
            float inv = rsum[row];
            __half* orow = g_xo_h + (long)(w * NTOK + q0 + row) * C2 + CC + h * HDIM;
            int d0 = part * 15;
#pragma unroll
            for (int dd = 0; dd < 15; dd++)
                orow[d0 + dd] = __float2half(Of[row * LO + d0 + dd] * inv);
        }
        __syncthreads();
    }
}

// ---------------- mutual attention (unchanged from R10) ----------------
#define LSM 68
__global__ __launch_bounds__(256) void mut_attn_kernel(const float* __restrict__ mask) {
    int h = blockIdx.x, w = blockIdx.y;
    int tid = threadIdx.x, wid = tid >> 5, lane = tid & 31;
    extern __shared__ __align__(16) char smraw[];
    __half* Qs = (__half*)smraw;
    __half* Ks = Qs + 128 * LQ;
    __half* Vs = Ks + 128 * LQ;
    float* S = (float*)(Vs + 128 * LQ);
    __half* P = (__half*)S;
    float* rsum = (float*)(S + 2 * 64 * LSM);
    float* Of = (float*)Qs;

    const float* base = g_qkvM + (long)w * NTOK * QKV_STR + h * HDIM;

    {
        int row = tid >> 1, part = tid & 1;
        int qt = (row < 64) ? (64 + row) : (row - 64);
        const float* qsrc = base + (long)qt * QKV_STR;
        const float* ksrc = base + (long)row * QKV_STR;
        int d0 = part * 15;
#pragma unroll
        for (int dd = 0; dd < 15; dd++) {
            int d = d0 + dd;
            Qs[row * LQ + d] = __float2half(qsrc[d] * ATT_SCALE);
            Ks[row * LQ + d] = __float2half(ksrc[180 + d]);
            Vs[row * LQ + d] = __float2half(ksrc[360 + d]);
        }
        if (part) {
            Qs[row * LQ + 30] = __float2half(0.f); Qs[row * LQ + 31] = __float2half(0.f);
            Ks[row * LQ + 30] = __float2half(0.f); Ks[row * LQ + 31] = __float2half(0.f);
            Vs[row * LQ + 30] = __float2half(0.f); Vs[row * LQ + 31] = __float2half(0.f);
        }
    }
    __syncthreads();

    int g = wid >> 2, mt = wid & 3;

    {
        wmma::fragment<wmma::accumulator, 16, 16, 16, float> acc[4];
#pragma unroll
        for (int j = 0; j < 4; j++) wmma::fill_fragment(acc[j], 0.f);
#pragma unroll
        for (int k = 0; k < 2; k++) {
            wmma::fragment<wmma::matrix_a, 16, 16, 16, __half, wmma::row_major> af;
            wmma::load_matrix_sync(af, Qs + (g * 64 + mt * 16) * LQ + k * 16, LQ);
#pragma unroll
            for (int j = 0; j < 4; j++) {
                wmma::fragment<wmma::matrix_b, 16, 16, 16, __half, wmma::col_major> bf;
                wmma::load_matrix_sync(bf, Ks + (g * 64 + j * 16) * LQ + k * 16, LQ);
                wmma::mma_sync(acc[j], af, bf, acc[j]);
            }
        }
#pragma unroll
        for (int j = 0; j < 4; j++)
            wmma::store_matrix_sync(S + g * 64 * LSM + (mt * 16) * LSM + j * 16, acc[j], LSM, wmma::mem_row_major);
    }
    __syncthreads();

    {
        const float* mbase = mask + (long)w * (NTOK * NTOK);
        for (int rr = 0; rr < 16; rr++) {
            int r = wid * 16 + rr;
            int gg = r >> 6, i = r & 63;
            float2 s2 = *(float2*)(S + gg * 64 * LSM + i * LSM + lane * 2);
            float2 m2 = *(const float2*)(mbase + i * NTOK + lane * 2);
            float p0 = __expf(s2.x + m2.x);
            float p1 = __expf(s2.y + m2.y);
            __half2 hp = __floats2half2_rn(p0, p1);
            *(uint32_t*)(P + gg * 64 * (2 * LSM) + i * (2 * LSM) + lane * 2) = *(uint32_t*)&hp;
            float psum = p0 + p1;
#pragma unroll
            for (int o = 16; o > 0; o >>= 1) psum += __shfl_xor_sync(0xffffffffu, psum, o);
            if (lane == 0) rsum[r] = 1.f / psum;
        }
    }
    __syncthreads();

    {
        wmma::fragment<wmma::accumulator, 16, 16, 16, float> acc[2];
        wmma::fill_fragment(acc[0], 0.f);
        wmma::fill_fragment(acc[1], 0.f);
#pragma unroll
        for (int k = 0; k < 4; k++) {
            wmma::fragment<wmma::matrix_a, 16, 16, 16, __half, wmma::row_major> pf;
            wmma::load_matrix_sync(pf, P + g * 64 * (2 * LSM) + (mt * 16) * (2 * LSM) + k * 16, 2 * LSM);
#pragma unroll
            for (int j = 0; j < 2; j++) {
                wmma::fragment<wmma::matrix_b, 16, 16, 16, __half, wmma::row_major> vf;
                wmma::load_matrix_sync(vf, Vs + (g * 64 + k * 16) * LQ + j * 16, LQ);
                wmma::mma_sync(acc[j], pf, vf, acc[j]);
            }
        }
#pragma unroll
        for (int j = 0; j < 2; j++)
            wmma::store_matrix_sync(Of + (g * 64 + mt * 16) * LO + j * 16, acc[j], LO, wmma::mem_row_major);
    }
    __syncthreads();

    {
        int row = tid >> 1, part = tid & 1;
        float inv = rsum[row];
        __half* orow = g_xo_h + (long)(w * NTOK + row) * C2 + h * HDIM;
        int d0 = part * 15;
#pragma unroll
        for (int dd = 0; dd < 15; dd++)
            orow[d0 + dd] = __float2half(Of[row * LO + d0 + dd] * inv);
    }
}

// ---------------- launcher ----------------
extern "C" void kernel_launch(void* const* d_in, const int* in_sizes, int n_in,
                              void* d_out, int out_size) {
    const float* x     = (const float*)d_in[0];
    const float* mask  = (const float*)d_in[1];
    const float* g1    = (const float*)d_in[2];
    const float* b1    = (const float*)d_in[3];
    const float* g2    = (const float*)d_in[4];
    const float* b2    = (const float*)d_in[5];
    const float* wqs   = (const float*)d_in[6];
    const float* bqs   = (const float*)d_in[7];
    const float* wqm   = (const float*)d_in[8];
    const float* bqm   = (const float*)d_in[9];
    const float* rpb   = (const float*)d_in[10];
    const float* posb  = (const float*)d_in[11];
    const float* wproj = (const float*)d_in[12];
    const float* bproj = (const float*)d_in[13];
    const float* w11   = (const float*)d_in[14];
    const float* b11   = (const float*)d_in[15];
    const float* w12   = (const float*)d_in[16];
    const float* b12   = (const float*)d_in[17];
    const float* w2    = (const float*)d_in[18];
    const float* b2f   = (const float*)d_in[19];
    const int*   rpi   = (const int*)d_in[20];
    float* out = (float*)d_out;

    const int SMEM_QKV  = 128 * 200 * 2 + 2 * 64 * 200 * 2 + 2 * 16 * 68 * 4;            // 111104
    const int SMEM_PROJ = 128 * 392 * 2 + 64 * 392 * 2 + 128 * 68 * 4 + 128 * 4;         // 185856
    const int SMEM_MLP  = 128 * 200 * 2 + 64 * 200 * 2 + 2 * 128 * 68 * 4 + 16 * 68 * 4; // 150784
    const int SMEM_FC2  = 128 * 392 * 2 + 64 * 392 * 2 + 2 * 128 * 68 * 4 + 128 * 4;     // 220672
    const int SMEM_SELF = 3 * 128 * LQ * 2 + 64 * LS * 4 + 64 * LO * 4 + 64 * 4;         // 73984 -> 3 CTAs/SM
    const int SMEM_MUT  = 3 * 128 * LQ * 2 + 2 * 64 * LSM * 4 + 128 * 4;                 // 66048

    cudaFuncSetAttribute(&gemm_qkv<0, 0, 0>, cudaFuncAttributeMaxDynamicSharedMemorySize, SMEM_QKV);
    cudaFuncSetAttribute(&gemm_qkv<1, 1, 1>, cudaFuncAttributeMaxDynamicSharedMemorySize, SMEM_QKV);
    cudaFuncSetAttribute(gemm_proj, cudaFuncAttributeMaxDynamicSharedMemorySize, SMEM_PROJ);
    cudaFuncSetAttribute(gemm_mlp,  cudaFuncAttributeMaxDynamicSharedMemorySize, SMEM_MLP);
    cudaFuncSetAttribute(gemm_fc2,  cudaFuncAttributeMaxDynamicSharedMemorySize, SMEM_FC2);
    cudaFuncSetAttribute(self_attn_kernel, cudaFuncAttributeMaxDynamicSharedMemorySize, SMEM_SELF);
    cudaFuncSetAttribute(mut_attn_kernel,  cudaFuncAttributeMaxDynamicSharedMemorySize, SMEM_MUT);

    dim3 ga(NHD, NWIN);
    prep_qkv_kernel<<<(2 * 576 * 192 + NHD * NTOK * NTOK + 255) / 256, 256>>>(wqs, wqm, rpb, rpi); // 0
    ln_kernel<0><<<(M_ROWS * 32) / 256, 256>>>(x, g1, b1);                       // 1
    gemm_qkv<0, 0, 0><<<768, 256, SMEM_QKV>>>(bqs, nullptr);                     // 2
    self_attn_kernel<<<ga, 256, SMEM_SELF>>>(mask);                              // 3 <- ncu slot
    prep_rest_kernel<<<(4 * 192 * 384 + 255) / 256, 256>>>(wproj, w11, w12, w2); // 4
    gemm_qkv<1, 1, 1><<<768, 256, SMEM_QKV>>>(bqm, posb);                        // 5
    mut_attn_kernel<<<ga, 256, SMEM_MUT>>>(mask);                                // 6
    gemm_proj<<<768, 256, SMEM_PROJ>>>(bproj, x);                                // 7
    ln_kernel<1><<<(M_ROWS * 32) / 256, 256>>>(nullptr, g2, b2);                 // 8
    gemm_mlp<<<768, 256, SMEM_MLP>>>(b11, b12);                                  // 9
    gemm_fc2<<<768, 256, SMEM_FC2>>>(b2f, out);                                  // 10
}

// round 12
// speedup vs baseline: 1.1934x; 1.1934x over previous
#include <cuda_runtime.h>
#include <cuda_fp16.h>
#include <mma.h>
#include <cstdint>
#include <math_constants.h>
#include <math.h>

using namespace nvcuda;

// ---------------- problem constants ----------------
#define CC 180
#define NHD 6
#define HDIM 30
#define NWIN 768
#define NTOK 128
#define M_ROWS 98304
#define C3 540
#define C2 360
#define HID 360
#define QKV_STR 576
#define HID_STR 384
#define Y_STR 192
#define ATT_SCALE 0.18257418583505536f

// ---------------- scratch ----------------
__device__ __half g_xw_h[M_ROWS * CC];
__device__ __half g_qkvS_h[M_ROWS * QKV_STR];
__device__ __half g_qkvM_h[M_ROWS * QKV_STR];
__device__ __half g_xo_h[M_ROWS * C2];
__device__ float  g_y[M_ROWS * Y_STR];
__device__ __half g_h2_h[M_ROWS * CC];
__device__ __half g_hid1_h[M_ROWS * HID_STR];
__device__ __half g_bias6_h[NHD * NTOK * NTOK];
__device__ __half g_mask_h[NWIN * NTOK * NTOK];
__device__ __half g_wT_qs[576 * 192];
__device__ __half g_wT_qm[576 * 192];
__device__ __half g_wT_pr[192 * 384];
__device__ __half g_wT_f11[384 * 192];
__device__ __half g_wT_f12[384 * 192];
__device__ __half g_wT_f2[192 * 384];

__device__ __forceinline__ int row_to_img(int r) {
    int win = r >> 7, n = r & 127;
    int dwin = win >> 8, rem = win & 255;
    int hwin = rem >> 4, wwin = rem & 15;
    int nd = n >> 6, nh = (n >> 3) & 7, nw = n & 7;
    int sd = dwin * 2 + nd + 1; if (sd >= 6) sd -= 6;
    int sh = (hwin * 8 + nh + 4) & 127;
    int sw = (wwin * 8 + nw + 4) & 127;
    return (sd * 128 + sh) * 128 + sw;
}

// ---------------- prep: qkv weights + bias + mask (fp16) ----------------
__device__ __forceinline__ void prep_one(const float* w, __half* wt, int idx,
                                         int K, int N, int Kpad, int Npad) {
    int n = idx / Kpad, k = idx % Kpad;
    wt[idx] = (n < N && k < K) ? __float2half(w[(long)k * N + n]) : __float2half(0.f);
}
__global__ void prep_qkv_kernel(const float* __restrict__ wqs, const float* __restrict__ wqm,
                                const float* __restrict__ rpb, const int* __restrict__ rpi,
                                const float* __restrict__ mask) {
    int idx = blockIdx.x * blockDim.x + threadIdx.x;
    const int S1 = 576 * 192;
    if (idx < S1) { prep_one(wqs, g_wT_qs, idx, CC, C3, 192, 576); return; }
    idx -= S1;
    if (idx < S1) { prep_one(wqm, g_wT_qm, idx, CC, C3, 192, 576); return; }
    idx -= S1;
    if (idx < NHD * NTOK * NTOK) {
        int h = idx / (NTOK * NTOK), ij = idx % (NTOK * NTOK);
        g_bias6_h[idx] = __float2half(rpb[rpi[ij] * NHD + h]);
        return;
    }
    idx -= NHD * NTOK * NTOK;
    if (idx < NWIN * NTOK * NTOK)
        g_mask_h[idx] = __float2half(mask[idx]);
}
__global__ void prep_rest_kernel(const float* __restrict__ wproj, const float* __restrict__ w11,
                                 const float* __restrict__ w12, const float* __restrict__ w2) {
    int idx = blockIdx.x * blockDim.x + threadIdx.x;
    const int S = 192 * 384;
    if (idx < S) prep_one(wproj, g_wT_pr, idx, C2, CC, 384, 192);
    else if (idx < 2 * S) prep_one(w11, g_wT_f11, idx - S, CC, HID, 192, 384);
    else if (idx < 3 * S) prep_one(w12, g_wT_f12, idx - 2 * S, CC, HID, 192, 384);
    else if (idx < 4 * S) prep_one(w2, g_wT_f2, idx - 3 * S, HID, CC, 384, 192);
}

// ---------------- LayerNorm: fp32 in -> fp16 out ----------------
template <int MODE>
__global__ __launch_bounds__(256) void ln_kernel(const float* __restrict__ in,
                                                 const float* __restrict__ gg,
                                                 const float* __restrict__ bb) {
    int gw = (blockIdx.x * blockDim.x + threadIdx.x) >> 5;
    int lane = threadIdx.x & 31;
    if (gw >= M_ROWS) return;
    const float* rowp;
    __half* orow;
    if (MODE == 0) {
        rowp = in + (long)row_to_img(gw) * CC;
        orow = g_xw_h + (long)gw * CC;
    } else {
        rowp = g_y + (long)gw * Y_STR;
        orow = g_h2_h + (long)gw * CC;
    }
    float vals[6];
    float s = 0.f, ss = 0.f;
    int cnt = 0;
    for (int c = lane; c < CC; c += 32) { float v = rowp[c]; vals[cnt++] = v; s += v; ss += v * v; }
#pragma unroll
    for (int o = 16; o > 0; o >>= 1) {
        s  += __shfl_xor_sync(0xffffffffu, s, o);
        ss += __shfl_xor_sync(0xffffffffu, ss, o);
    }
    float mean = s * (1.f / CC);
    float var = ss * (1.f / CC) - mean * mean;
    float rstd = rsqrtf(var + 1e-5f);
    cnt = 0;
    for (int c = lane; c < CC; c += 32)
        orow[c] = __float2half((vals[cnt++] - mean) * rstd * gg[c] + bb[c]);
}

// ---------------- qkv GEMM: half in, half out (direct), double-buffered B ----------------
template <int WID, int ADD_PB, int DSTID>
__global__ __launch_bounds__(256) void gemm_qkv(const float* __restrict__ bias,
                                                const float* __restrict__ pb) {
    constexpr int KPAD = 192, LDA = 200, LDC = 68, NTILES = 9;
    const __half* A = g_xw_h;
    const __half* BT = (WID == 0) ? g_wT_qs : g_wT_qm;
    __half* Cout = (DSTID == 0) ? g_qkvS_h : g_qkvM_h;
    extern __shared__ __align__(16) char smem[];
    __half* As = (__half*)smem;
    __half* Bs0 = As + 128 * LDA;
    __half* Bs1 = Bs0 + 64 * LDA;
    float* bias0 = (float*)(Bs1 + 64 * LDA);
    float* bias1 = bias0 + 16 * LDC;

    int tid = threadIdx.x, wid = tid >> 5;
    int m0 = blockIdx.x * 128;
    int wm = (wid & 3) * 32, wn = (wid >> 2) * 32;

    constexpr int KF4 = KPAD / 4;
    constexpr int KR4 = CC / 4;
    for (int idx = tid; idx < 128 * KF4; idx += 256) {
        int row = idx / KF4, c4 = idx % KF4;
        uint2 val = make_uint2(0u, 0u);
        if (c4 < KR4) {
            val = *(const uint2*)(A + (long)(m0 + row) * CC + c4 * 4);
            if (ADD_PB) {
                __half2 h0 = *(__half2*)&val.x, h1 = *(__half2*)&val.y;
                float4 p = *(const float4*)(pb + ((m0 + row) & 63) * CC + c4 * 4);
                float2 f0 = __half22float2(h0), f1 = __half22float2(h1);
                __half2 r0 = __floats2half2_rn(f0.x + p.x, f0.y + p.y);
                __half2 r1 = __floats2half2_rn(f1.x + p.z, f1.y + p.w);
                val.x = *(uint32_t*)&r0; val.y = *(uint32_t*)&r1;
            }
        }
        *(uint2*)(As + row * LDA + c4 * 4) = val;
    }

    constexpr int BU4 = KPAD / 8;
    constexpr int NB = (64 * BU4) / 256;
    for (int i = 0; i < NB; i++) {
        int idx = tid + i * 256;
        int n = idx / BU4, c = idx % BU4;
        *(uint4*)(Bs0 + n * LDA + c * 8) = *(const uint4*)(BT + (long)n * KPAD + c * 8);
    }
    for (int i = 0; i < 4; i++) {
        int idx = tid + i * 256;
        int row = idx >> 6, c = idx & 63;
        bias0[row * LDC + c] = bias[c];
    }
    __syncthreads();

    for (int t = 0; t < NTILES; t++) {
        __half* Bcur = (t & 1) ? Bs1 : Bs0;
        __half* Bnxt = (t & 1) ? Bs0 : Bs1;
        float* bcur = (t & 1) ? bias1 : bias0;
        float* bnxt = (t & 1) ? bias0 : bias1;
        int n0 = t * 64;
        bool has_next = (t + 1 < NTILES);

        uint4 breg[NB];
        float creg[4];
        if (has_next) {
            int n0n = n0 + 64;
#pragma unroll
            for (int i = 0; i < NB; i++) {
                int idx = tid + i * 256;
                int n = idx / BU4, c = idx % BU4;
                breg[i] = *(const uint4*)(BT + (long)(n0n + n) * KPAD + c * 8);
            }
#pragma unroll
            for (int i = 0; i < 4; i++) {
                int idx = tid + i * 256;
                int c = idx & 63;
                creg[i] = (n0n + c < C3) ? bias[n0n + c] : 0.f;
            }
        }

        wmma::fragment<wmma::accumulator, 16, 16, 16, float> acc[2][2];
#pragma unroll
        for (int i = 0; i < 2; i++)
#pragma unroll
            for (int j = 0; j < 2; j++)
                wmma::load_matrix_sync(acc[i][j], bcur + wn + j * 16, LDC, wmma::mem_row_major);
#pragma unroll
        for (int k = 0; k < KPAD; k += 16) {
            wmma::fragment<wmma::matrix_a, 16, 16, 16, __half, wmma::row_major> af[2];
            wmma::fragment<wmma::matrix_b, 16, 16, 16, __half, wmma::col_major> bf[2];
#pragma unroll
            for (int i = 0; i < 2; i++)
                wmma::load_matrix_sync(af[i], As + (wm + i * 16) * LDA + k, LDA);
#pragma unroll
            for (int j = 0; j < 2; j++)
                wmma::load_matrix_sync(bf[j], Bcur + (wn + j * 16) * LDA + k, LDA);
#pragma unroll
            for (int i = 0; i < 2; i++)
#pragma unroll
                for (int j = 0; j < 2; j++)
                    wmma::mma_sync(acc[i][j], af[i], bf[j], acc[i][j]);
        }
        // convert to half and store direct
#pragma unroll
        for (int i = 0; i < 2; i++)
#pragma unroll
            for (int j = 0; j < 2; j++) {
                wmma::fragment<wmma::accumulator, 16, 16, 16, __half> hacc;
#pragma unroll
                for (int e = 0; e < hacc.num_elements; e++)
                    hacc.x[e] = __float2half(acc[i][j].x[e]);
                wmma::store_matrix_sync(Cout + (long)(m0 + wm + i * 16) * QKV_STR + n0 + wn + j * 16,
                                        hacc, QKV_STR, wmma::mem_row_major);
            }
        if (has_next) {
#pragma unroll
            for (int i = 0; i < NB; i++) {
                int idx = tid + i * 256;
                int n = idx / BU4, c = idx % BU4;
                *(uint4*)(Bnxt + n * LDA + c * 8) = breg[i];
            }
#pragma unroll
            for (int i = 0; i < 4; i++) {
                int idx = tid + i * 256;
                int row = idx >> 6, c = idx & 63;
                bnxt[row * LDC + c] = creg[i];
            }
        }
        __syncthreads();
    }
}

// ---------------- proj GEMM (unchanged) ----------------
__global__ __launch_bounds__(256) void gemm_proj(const float* __restrict__ bias,
                                                 const float* __restrict__ x) {
    constexpr int KPAD = 384, LDA = 392, LDC = 68, NTILES = 3;
    extern __shared__ __align__(16) char smem[];
    __half* As = (__half*)smem;
    __half* Bs = As + 128 * LDA;
    float* resT = (float*)(Bs + 64 * LDA);
    int* imgIdx = (int*)(resT + 128 * LDC);

    int tid = threadIdx.x, wid = tid >> 5;
    int m0 = blockIdx.x * 128;
    int wm = (wid & 3) * 32, wn = (wid >> 2) * 32;

    if (tid < 128) imgIdx[tid] = row_to_img(m0 + tid);

    constexpr int KF4 = KPAD / 4;
    constexpr int KR4 = C2 / 4;
    for (int idx = tid; idx < 128 * KF4; idx += 256) {
        int row = idx / KF4, c4 = idx % KF4;
        uint2 val = make_uint2(0u, 0u);
        if (c4 < KR4)
            val = *(const uint2*)(g_xo_h + (long)(m0 + row) * C2 + c4 * 4);
        *(uint2*)(As + row * LDA + c4 * 4) = val;
    }

    constexpr int BU4 = KPAD / 8;
    for (int t = 0; t < NTILES; t++) {
        int n0 = t * 64;
        for (int idx = tid; idx < 64 * BU4; idx += 256) {
            int n = idx / BU4, c = idx % BU4;
            *(uint4*)(Bs + n * LDA + c * 8) = *(const uint4*)(g_wT_pr + (long)(n0 + n) * KPAD + c * 8);
        }
        for (int idx = tid; idx < 128 * 16; idx += 256) {
            int row = idx >> 4, c4 = (idx & 15) * 4;
            int n = n0 + c4;
            float4 v = make_float4(0.f, 0.f, 0.f, 0.f);
            if (n + 4 <= CC) {
                const float4 bv = *(const float4*)(bias + n);
                const float4 xr = *(const float4*)(x + (long)imgIdx[row] * CC + n);
                v.x = bv.x + xr.x; v.y = bv.y + xr.y; v.z = bv.z + xr.z; v.w = bv.w + xr.w;
            }
            *(float4*)(resT + row * LDC + c4) = v;
        }
        __syncthreads();

        wmma::fragment<wmma::accumulator, 16, 16, 16, float> acc[2][2];
#pragma unroll
        for (int i = 0; i < 2; i++)
#pragma unroll
            for (int j = 0; j < 2; j++)
                wmma::load_matrix_sync(acc[i][j], resT + (wm + i * 16) * LDC + wn + j * 16, LDC, wmma::mem_row_major);
#pragma unroll
        for (int k = 0; k < KPAD; k += 16) {
            wmma::fragment<wmma::matrix_a, 16, 16, 16, __half, wmma::row_major> af[2];
            wmma::fragment<wmma::matrix_b, 16, 16, 16, __half, wmma::col_major> bf[2];
#pragma unroll
            for (int i = 0; i < 2; i++)
                wmma::load_matrix_sync(af[i], As + (wm + i * 16) * LDA + k, LDA);
#pragma unroll
            for (int j = 0; j < 2; j++)
                wmma::load_matrix_sync(bf[j], Bs + (wn + j * 16) * LDA + k, LDA);
#pragma unroll
            for (int i = 0; i < 2; i++)
#pragma unroll
                for (int j = 0; j < 2; j++)
                    wmma::mma_sync(acc[i][j], af[i], bf[j], acc[i][j]);
        }
#pragma unroll
        for (int i = 0; i < 2; i++)
#pragma unroll
            for (int j = 0; j < 2; j++)
                wmma::store_matrix_sync(g_y + (long)(m0 + wm + i * 16) * Y_STR + n0 + wn + j * 16,
                                        acc[i][j], Y_STR, wmma::mem_row_major);
        __syncthreads();
    }
}

// ---------------- fused MLP GEMM (unchanged) ----------------
__global__ __launch_bounds__(256) void gemm_mlp(const float* __restrict__ bias1,
                                                const float* __restrict__ bias2) {
    constexpr int KPAD = 192, LDA = 200, LDC = 68, NTILES = 6;
    extern __shared__ __align__(16) char smem[];
    __half* As = (__half*)smem;
    __half* Bs = As + 128 * LDA;
    float* Cs = (float*)(Bs + 64 * LDA);
    float* Cs2 = Cs + 128 * LDC;
    float* biasS = Cs2 + 128 * LDC;

    int tid = threadIdx.x, wid = tid >> 5;
    int m0 = blockIdx.x * 128;
    int wm = (wid & 3) * 32, wn = (wid >> 2) * 32;

    constexpr int KF4 = KPAD / 4;
    constexpr int KR4 = CC / 4;
    for (int idx = tid; idx < 128 * KF4; idx += 256) {
        int row = idx / KF4, c4 = idx % KF4;
        uint2 val = make_uint2(0u, 0u);
        if (c4 < KR4)
            val = *(const uint2*)(g_h2_h + (long)(m0 + row) * CC + c4 * 4);
        *(uint2*)(As + row * LDA + c4 * 4) = val;
    }

    constexpr int BU4 = KPAD / 8;
    for (int t = 0; t < NTILES; t++) {
        int n0 = t * 64;
#pragma unroll
        for (int pass = 0; pass < 2; pass++) {
            const __half* Bp = (pass == 0) ? g_wT_f11 : g_wT_f12;
            const float* bp = (pass == 0) ? bias1 : bias2;
            float* Cdst = (pass == 0) ? Cs : Cs2;
            for (int idx = tid; idx < 16 * 64; idx += 256) {
                int row = idx >> 6, c = idx & 63;
                biasS[row * LDC + c] = (n0 + c < HID) ? bp[n0 + c] : 0.f;
            }
            for (int idx = tid; idx < 64 * BU4; idx += 256) {
                int n = idx / BU4, c = idx % BU4;
                *(uint4*)(Bs + n * LDA + c * 8) = *(const uint4*)(Bp + (long)(n0 + n) * KPAD + c * 8);
            }
            __syncthreads();
            wmma::fragment<wmma::accumulator, 16, 16, 16, float> acc[2][2];
#pragma unroll
            for (int i = 0; i < 2; i++)
#pragma unroll
                for (int j = 0; j < 2; j++)
                    wmma::load_matrix_sync(acc[i][j], biasS + wn + j * 16, LDC, wmma::mem_row_major);
#pragma unroll
            for (int k = 0; k < KPAD; k += 16) {
                wmma::fragment<wmma::matrix_a, 16, 16, 16, __half, wmma::row_major> af[2];
                wmma::fragment<wmma::matrix_b, 16, 16, 16, __half, wmma::col_major> bf[2];
#pragma unroll
                for (int i = 0; i < 2; i++)
                    wmma::load_matrix_sync(af[i], As + (wm + i * 16) * LDA + k, LDA);
#pragma unroll
                for (int j = 0; j < 2; j++)
                    wmma::load_matrix_sync(bf[j], Bs + (wn + j * 16) * LDA + k, LDA);
#pragma unroll
                for (int i = 0; i < 2; i++)
#pragma unroll
                    for (int j = 0; j < 2; j++)
                        wmma::mma_sync(acc[i][j], af[i], bf[j], acc[i][j]);
            }
#pragma unroll
            for (int i = 0; i < 2; i++)
#pragma unroll
                for (int j = 0; j < 2; j++)
                    wmma::store_matrix_sync(Cdst + (wm + i * 16) * LDC + wn + j * 16,
                                            acc[i][j], LDC, wmma::mem_row_major);
            __syncthreads();
        }
        for (int idx = tid; idx < 128 * 16; idx += 256) {
            int row = idx >> 4, c4 = (idx & 15) * 4;
            float4 v = *(float4*)(Cs + row * LDC + c4);
            float4 v2 = *(float4*)(Cs2 + row * LDC + c4);
            float4 o;
            o.x = 0.5f * v.x * (1.f + erff(v.x * 0.70710678f)) * v2.x;
            o.y = 0.5f * v.y * (1.f + erff(v.y * 0.70710678f)) * v2.y;
            o.z = 0.5f * v.z * (1.f + erff(v.z * 0.70710678f)) * v2.z;
            o.w = 0.5f * v.w * (1.f + erff(v.w * 0.70710678f)) * v2.w;
            __half2 a = __floats2half2_rn(o.x, o.y);
            __half2 b = __floats2half2_rn(o.z, o.w);
            *(uint2*)(g_hid1_h + (long)(m0 + row) * HID_STR + t * 64 + c4) =
                make_uint2(*(uint32_t*)&a, *(uint32_t*)&b);
        }
        __syncthreads();
    }
}

// ---------------- fc2 GEMM (unchanged) ----------------
__global__ __launch_bounds__(256) void gemm_fc2(const float* __restrict__ bias,
                                                float* __restrict__ out) {
    constexpr int KPAD = 384, LDA = 392, LDC = 68, NTILES = 3;
    extern __shared__ __align__(16) char smem[];
    __half* As = (__half*)smem;
    __half* Bs = As + 128 * LDA;
    float* resT = (float*)(Bs + 64 * LDA);
    float* Cs = resT + 128 * LDC;
    int* imgIdx = (int*)(Cs + 128 * LDC);

    int tid = threadIdx.x, wid = tid >> 5;
    int m0 = blockIdx.x * 128;
    int wm = (wid & 3) * 32, wn = (wid >> 2) * 32;

    if (tid < 128) imgIdx[tid] = row_to_img(m0 + tid);

    constexpr int KF4 = KPAD / 4;
    for (int idx = tid; idx < 128 * KF4; idx += 256) {
        int row = idx / KF4, c4 = idx % KF4;
        *(uint2*)(As + row * LDA + c4 * 4) =
            *(const uint2*)(g_hid1_h + (long)(m0 + row) * HID_STR + c4 * 4);
    }

    constexpr int BU4 = KPAD / 8;
    for (int t = 0; t < NTILES; t++) {
        int n0 = t * 64;
        for (int idx = tid; idx < 64 * BU4; idx += 256) {
            int n = idx / BU4, c = idx % BU4;
            *(uint4*)(Bs + n * LDA + c * 8) = *(const uint4*)(g_wT_f2 + (long)(n0 + n) * KPAD + c * 8);
        }
        for (int idx = tid; idx < 128 * 16; idx += 256) {
            int row = idx >> 4, c4 = (idx & 15) * 4;
            int n = n0 + c4;
            float4 v = make_float4(0.f, 0.f, 0.f, 0.f);
            if (n + 4 <= CC) {
                const float4 bv = *(const float4*)(bias + n);
                const float4 yr = *(const float4*)(g_y + (long)(m0 + row) * Y_STR + n);
                v.x = bv.x + yr.x; v.y = bv.y + yr.y; v.z = bv.z + yr.z; v.w = bv.w + yr.w;
            }
            *(float4*)(resT + row * LDC + c4) = v;
        }
        __syncthreads();

        wmma::fragment<wmma::accumulator, 16, 16, 16, float> acc[2][2];
#pragma unroll
        for (int i = 0; i < 2; i++)
#pragma unroll
            for (int j = 0; j < 2; j++)
                wmma::load_matrix_sync(acc[i][j], resT + (wm + i * 16) * LDC + wn + j * 16, LDC, wmma::mem_row_major);
#pragma unroll
        for (int k = 0; k < KPAD; k += 16) {
            wmma::fragment<wmma::matrix_a, 16, 16, 16, __half, wmma::row_major> af[2];
            wmma::fragment<wmma::matrix_b, 16, 16, 16, __half, wmma::col_major> bf[2];
#pragma unroll
            for (int i = 0; i < 2; i++)
                wmma::load_matrix_sync(af[i], As + (wm + i * 16) * LDA + k, LDA);
#pragma unroll
            for (int j = 0; j < 2; j++)
                wmma::load_matrix_sync(bf[j], Bs + (wn + j * 16) * LDA + k, LDA);
#pragma unroll
            for (int i = 0; i < 2; i++)
#pragma unroll
                for (int j = 0; j < 2; j++)
                    wmma::mma_sync(acc[i][j], af[i], bf[j], acc[i][j]);
        }
#pragma unroll
        for (int i = 0; i < 2; i++)
#pragma unroll
            for (int j = 0; j < 2; j++)
                wmma::store_matrix_sync(Cs + (wm + i * 16) * LDC + wn + j * 16,
                                        acc[i][j], LDC, wmma::mem_row_major);
        __syncthreads();

        for (int idx = tid; idx < 128 * 16; idx += 256) {
            int row = idx >> 4, c4 = (idx & 15) * 4;
            int n = n0 + c4;
            if (n + 4 <= CC) {
                float4 v = *(float4*)(Cs + row * LDC + c4);
                *(float4*)(out + (long)imgIdx[row] * CC + n) = v;
            }
        }
        __syncthreads();
    }
}

// ---------------- self attention: single-pass S, half sources ----------------
#define LQ 40
#define LS 132
#define LO 36
__global__ __launch_bounds__(256) void self_attn_kernel() {
    int h = blockIdx.x, w = blockIdx.y;
    int tid = threadIdx.x, wid = tid >> 5, lane = tid & 31;
    extern __shared__ __align__(16) char smraw[];
    __half* Qs = (__half*)smraw;
    __half* Ks = Qs + 128 * LQ;
    __half* Vs = Ks + 128 * LQ;
    float* S = (float*)(Vs + 128 * LQ);
    __half* P = (__half*)S;
    float* rsum = (float*)(S + 128 * LS);
    float* Of = (float*)Qs;

    const __half* base = g_qkvS_h + (long)w * NTOK * QKV_STR + h * HDIM;
    const float scl = ATT_SCALE;

    // staging: 3 regions x 128 rows x 15 uints (2 halves each)
    for (int idx = tid; idx < 3 * 128 * 15; idx += 256) {
        int region = idx / (128 * 15);
        int rem = idx - region * (128 * 15);
        int row = rem / 15, c = rem - row * 15;
        uint32_t v = *(const uint32_t*)(base + (long)row * QKV_STR + region * 180 + c * 2);
        __half* dst = (region == 0) ? Qs : (region == 1) ? Ks : Vs;
        if (region == 0) {
            float2 f = __half22float2(*(__half2*)&v);
            __half2 r = __floats2half2_rn(f.x * scl, f.y * scl);
            v = *(uint32_t*)&r;
        }
        *(uint32_t*)(dst + row * LQ + c * 2) = v;
    }
    if (tid < 128) {
        uint32_t z = 0;
        *(uint32_t*)(Qs + tid * LQ + 30) = z;
        *(uint32_t*)(Ks + tid * LQ + 30) = z;
        *(uint32_t*)(Vs + tid * LQ + 30) = z;
    }
    __syncthreads();

    // S = Q @ K^T
    {
        wmma::fragment<wmma::accumulator, 16, 16, 16, float> acc[8];
#pragma unroll
        for (int j = 0; j < 8; j++) wmma::fill_fragment(acc[j], 0.f);
#pragma unroll
        for (int k = 0; k < 2; k++) {
            wmma::fragment<wmma::matrix_a, 16, 16, 16, __half, wmma::row_major> af;
            wmma::load_matrix_sync(af, Qs + (wid * 16) * LQ + k * 16, LQ);
#pragma unroll
            for (int j = 0; j < 8; j++) {
                wmma::fragment<wmma::matrix_b, 16, 16, 16, __half, wmma::col_major> bf;
                wmma::load_matrix_sync(bf, Ks + (j * 16) * LQ + k * 16, LQ);
                wmma::mma_sync(acc[j], af, bf, acc[j]);
            }
        }
#pragma unroll
        for (int j = 0; j < 8; j++)
            wmma::store_matrix_sync(S + (wid * 16) * LS + j * 16, acc[j], LS, wmma::mem_row_major);
    }
    __syncthreads();

    // softmax (no max pass); half bias/mask; P fp16 over S
    {
        const __half* bbase = g_bias6_h + h * (NTOK * NTOK);
        const __half* mbase = g_mask_h + (long)w * (NTOK * NTOK);
        for (int rr = 0; rr < 16; rr++) {
            int r = wid * 16 + rr;
            float4 s4 = *(float4*)(S + r * LS + lane * 4);
            uint2 bu = *(const uint2*)(bbase + r * NTOK + lane * 4);
            uint2 mu = *(const uint2*)(mbase + r * NTOK + lane * 4);
            float2 b0 = __half22float2(*(__half2*)&bu.x), b1 = __half22float2(*(__half2*)&bu.y);
            float2 m0 = __half22float2(*(__half2*)&mu.x), m1 = __half22float2(*(__half2*)&mu.y);
            float p0 = __expf(s4.x + b0.x + m0.x);
            float p1 = __expf(s4.y + b0.y + m0.y);
            float p2 = __expf(s4.z + b1.x + m1.x);
            float p3 = __expf(s4.w + b1.y + m1.y);
            __half2 h0 = __floats2half2_rn(p0, p1);
            __half2 h1 = __floats2half2_rn(p2, p3);
            *(uint2*)(P + r * (2 * LS) + lane * 4) = make_uint2(*(uint32_t*)&h0, *(uint32_t*)&h1);
            float psum = p0 + p1 + p2 + p3;
#pragma unroll
            for (int o = 16; o > 0; o >>= 1) psum += __shfl_xor_sync(0xffffffffu, psum, o);
            if (lane == 0) rsum[r] = 1.f / psum;
        }
    }
    __syncthreads();

    // O = P @ V
    {
        wmma::fragment<wmma::accumulator, 16, 16, 16, float> acc[2];
        wmma::fill_fragment(acc[0], 0.f);
        wmma::fill_fragment(acc[1], 0.f);
#pragma unroll
        for (int k = 0; k < 8; k++) {
            wmma::fragment<wmma::matrix_a, 16, 16, 16, __half, wmma::row_major> pf;
            wmma::load_matrix_sync(pf, P + (wid * 16) * (2 * LS) + k * 16, 2 * LS);
#pragma unroll
            for (int j = 0; j < 2; j++) {
                wmma::fragment<wmma::matrix_b, 16, 16, 16, __half, wmma::row_major> vf;
                wmma::load_matrix_sync(vf, Vs + (k * 16) * LQ + j * 16, LQ);
                wmma::mma_sync(acc[j], pf, vf, acc[j]);
            }
        }
#pragma unroll
        for (int j = 0; j < 2; j++)
            wmma::store_matrix_sync(Of + (wid * 16) * LO + j * 16, acc[j], LO, wmma::mem_row_major);
    }
    __syncthreads();

    {
        int row = tid >> 1, part = tid & 1;
        float inv = rsum[row];
        __half* orow = g_xo_h + (long)(w * NTOK + row) * C2 + CC + h * HDIM;
        int d0 = part * 15;
#pragma unroll
        for (int dd = 0; dd < 15; dd++)
            orow[d0 + dd] = __float2half(Of[row * LO + d0 + dd] * inv);
    }
}

// ---------------- mutual attention: half sources ----------------
#define LSM 68
__global__ __launch_bounds__(256) void mut_attn_kernel() {
    int h = blockIdx.x, w = blockIdx.y;
    int tid = threadIdx.x, wid = tid >> 5, lane = tid & 31;
    extern __shared__ __align__(16) char smraw[];
    __half* Qs = (__half*)smraw;
    __half* Ks = Qs + 128 * LQ;
    __half* Vs = Ks + 128 * LQ;
    float* S = (float*)(Vs + 128 * LQ);
    __half* P = (__half*)S;
    float* rsum = (float*)(S + 2 * 64 * LSM);
    float* Of = (float*)Qs;

    const __half* base = g_qkvM_h + (long)w * NTOK * QKV_STR + h * HDIM;
    const float scl = ATT_SCALE;

    for (int idx = tid; idx < 3 * 128 * 15; idx += 256) {
        int region = idx / (128 * 15);
        int rem = idx - region * (128 * 15);
        int row = rem / 15, c = rem - row * 15;
        int srow = row;
        if (region == 0) srow = (row < 64) ? (64 + row) : (row - 64);   // cross queries
        uint32_t v = *(const uint32_t*)(base + (long)srow * QKV_STR + region * 180 + c * 2);
        __half* dst = (region == 0) ? Qs : (region == 1) ? Ks : Vs;
        if (region == 0) {
            float2 f = __half22float2(*(__half2*)&v);
            __half2 r = __floats2half2_rn(f.x * scl, f.y * scl);
            v = *(uint32_t*)&r;
        }
        *(uint32_t*)(dst + row * LQ + c * 2) = v;
    }
    if (tid < 128) {
        uint32_t z = 0;
        *(uint32_t*)(Qs + tid * LQ + 30) = z;
        *(uint32_t*)(Ks + tid * LQ + 30) = z;
        *(uint32_t*)(Vs + tid * LQ + 30) = z;
    }
    __syncthreads();

    int g = wid >> 2, mt = wid & 3;

    {
        wmma::fragment<wmma::accumulator, 16, 16, 16, float> acc[4];
#pragma unroll
        for (int j = 0; j < 4; j++) wmma::fill_fragment(acc[j], 0.f);
#pragma unroll
        for (int k = 0; k < 2; k++) {
            wmma::fragment<wmma::matrix_a, 16, 16, 16, __half, wmma::row_major> af;
            wmma::load_matrix_sync(af, Qs + (g * 64 + mt * 16) * LQ + k * 16, LQ);
#pragma unroll
            for (int j = 0; j < 4; j++) {
                wmma::fragment<wmma::matrix_b, 16, 16, 16, __half, wmma::col_major> bf;
                wmma::load_matrix_sync(bf, Ks + (g * 64 + j * 16) * LQ + k * 16, LQ);
                wmma::mma_sync(acc[j], af, bf, acc[j]);
            }
        }
#pragma unroll
        for (int j = 0; j < 4; j++)
            wmma::store_matrix_sync(S + g * 64 * LSM + (mt * 16) * LSM + j * 16, acc[j], LSM, wmma::mem_row_major);
    }
    __syncthreads();

    {
        const __half* mbase = g_mask_h + (long)w * (NTOK * NTOK);
        for (int rr = 0; rr < 16; rr++) {
            int r = wid * 16 + rr;
            int gg = r >> 6, i = r & 63;
            float2 s2 = *(float2*)(S + gg * 64 * LSM + i * LSM + lane * 2);
            uint32_t mu = *(const uint32_t*)(mbase + i * NTOK + lane * 2);
            float2 m2 = __half22float2(*(__half2*)&mu);
            float p0 = __expf(s2.x + m2.x);
            float p1 = __expf(s2.y + m2.y);
            __half2 hp = __floats2half2_rn(p0, p1);
            *(uint32_t*)(P + gg * 64 * (2 * LSM) + i * (2 * LSM) + lane * 2) = *(uint32_t*)&hp;
            float psum = p0 + p1;
#pragma unroll
            for (int o = 16; o > 0; o >>= 1) psum += __shfl_xor_sync(0xffffffffu, psum, o);
            if (lane == 0) rsum[r] = 1.f / psum;
        }
    }
    __syncthreads();

    {
        wmma::fragment<wmma::accumulator, 16, 16, 16, float> acc[2];
        wmma::fill_fragment(acc[0], 0.f);
        wmma::fill_fragment(acc[1], 0.f);
#pragma unroll
        for (int k = 0; k < 4; k++) {
            wmma::fragment<wmma::matrix_a, 16, 16, 16, __half, wmma::row_major> pf;
            wmma::load_matrix_sync(pf, P + g * 64 * (2 * LSM) + (mt * 16) * (2 * LSM) + k * 16, 2 * LSM);
#pragma unroll
            for (int j = 0; j < 2; j++) {
                wmma::fragment<wmma::matrix_b, 16, 16, 16, __half, wmma::row_major> vf;
                wmma::load_matrix_sync(vf, Vs + (g * 64 + k * 16) * LQ + j * 16, LQ);
                wmma::mma_sync(acc[j], pf, vf, acc[j]);
            }
        }
#pragma unroll
        for (int j = 0; j < 2; j++)
            wmma::store_matrix_sync(Of + (g * 64 + mt * 16) * LO + j * 16, acc[j], LO, wmma::mem_row_major);
    }
    __syncthreads();

    {
        int row = tid >> 1, part = tid & 1;
        float inv = rsum[row];
        __half* orow = g_xo_h + (long)(w * NTOK + row) * C2 + h * HDIM;
        int d0 = part * 15;
#pragma unroll
        for (int dd = 0; dd < 15; dd++)
            orow[d0 + dd] = __float2half(Of[row * LO + d0 + dd] * inv);
    }
}

// ---------------- launcher ----------------
extern "C" void kernel_launch(void* const* d_in, const int* in_sizes, int n_in,
                              void* d_out, int out_size) {
    const float* x     = (const float*)d_in[0];
    const float* mask  = (const float*)d_in[1];
    const float* g1    = (const float*)d_in[2];
    const float* b1    = (const float*)d_in[3];
    const float* g2    = (const float*)d_in[4];
    const float* b2    = (const float*)d_in[5];
    const float* wqs   = (const float*)d_in[6];
    const float* bqs   = (const float*)d_in[7];
    const float* wqm   = (const float*)d_in[8];
    const float* bqm   = (const float*)d_in[9];
    const float* rpb   = (const float*)d_in[10];
    const float* posb  = (const float*)d_in[11];
    const float* wproj = (const float*)d_in[12];
    const float* bproj = (const float*)d_in[13];
    const float* w11   = (const float*)d_in[14];
    const float* b11   = (const float*)d_in[15];
    const float* w12   = (const float*)d_in[16];
    const float* b12   = (const float*)d_in[17];
    const float* w2    = (const float*)d_in[18];
    const float* b2f   = (const float*)d_in[19];
    const int*   rpi   = (const int*)d_in[20];
    float* out = (float*)d_out;

    const int SMEM_QKV  = 128 * 200 * 2 + 2 * 64 * 200 * 2 + 2 * 16 * 68 * 4;            // 111104
    const int SMEM_PROJ = 128 * 392 * 2 + 64 * 392 * 2 + 128 * 68 * 4 + 128 * 4;         // 185856
    const int SMEM_MLP  = 128 * 200 * 2 + 64 * 200 * 2 + 2 * 128 * 68 * 4 + 16 * 68 * 4; // 150784
    const int SMEM_FC2  = 128 * 392 * 2 + 64 * 392 * 2 + 2 * 128 * 68 * 4 + 128 * 4;     // 220672
    const int SMEM_SELF = 3 * 128 * LQ * 2 + 128 * LS * 4 + 128 * 4;                     // 98816
    const int SMEM_MUT  = 3 * 128 * LQ * 2 + 2 * 64 * LSM * 4 + 128 * 4;                 // 66048

    cudaFuncSetAttribute(&gemm_qkv<0, 0, 0>, cudaFuncAttributeMaxDynamicSharedMemorySize, SMEM_QKV);
    cudaFuncSetAttribute(&gemm_qkv<1, 1, 1>, cudaFuncAttributeMaxDynamicSharedMemorySize, SMEM_QKV);
    cudaFuncSetAttribute(gemm_proj, cudaFuncAttributeMaxDynamicSharedMemorySize, SMEM_PROJ);
    cudaFuncSetAttribute(gemm_mlp,  cudaFuncAttributeMaxDynamicSharedMemorySize, SMEM_MLP);
    cudaFuncSetAttribute(gemm_fc2,  cudaFuncAttributeMaxDynamicSharedMemorySize, SMEM_FC2);
    cudaFuncSetAttribute(self_attn_kernel, cudaFuncAttributeMaxDynamicSharedMemorySize, SMEM_SELF);
    cudaFuncSetAttribute(mut_attn_kernel,  cudaFuncAttributeMaxDynamicSharedMemorySize, SMEM_MUT);

    dim3 ga(NHD, NWIN);
    int prep_n = 2 * 576 * 192 + NHD * NTOK * NTOK + NWIN * NTOK * NTOK;
    prep_qkv_kernel<<<(prep_n + 255) / 256, 256>>>(wqs, wqm, rpb, rpi, mask);   // 0
    ln_kernel<0><<<(M_ROWS * 32) / 256, 256>>>(x, g1, b1);                      // 1
    gemm_qkv<0, 0, 0><<<768, 256, SMEM_QKV>>>(bqs, nullptr);                    // 2
    self_attn_kernel<<<ga, 256, SMEM_SELF>>>();                                 // 3 <- ncu slot
    prep_rest_kernel<<<(4 * 192 * 384 + 255) / 256, 256>>>(wproj, w11, w12, w2);// 4
    gemm_qkv<1, 1, 1><<<768, 256, SMEM_QKV>>>(bqm, posb);                       // 5
    mut_attn_kernel<<<ga, 256, SMEM_MUT>>>();                                   // 6
    gemm_proj<<<768, 256, SMEM_PROJ>>>(bproj, x);                               // 7
    ln_kernel<1><<<(M_ROWS * 32) / 256, 256>>>(nullptr, g2, b2);                // 8
    gemm_mlp<<<768, 256, SMEM_MLP>>>(b11, b12);                                 // 9
    gemm_fc2<<<768, 256, SMEM_FC2>>>(b2f, out);                                 // 10
}

// round 13
// speedup vs baseline: 1.2622x; 1.0576x over previous
#include <cuda_runtime.h>
#include <cuda_fp16.h>
#include <mma.h>
#include <cstdint>
#include <math_constants.h>
#include <math.h>

using namespace nvcuda;

// ---------------- problem constants ----------------
#define CC 180
#define NHD 6
#define HDIM 30
#define NWIN 768
#define NTOK 128
#define M_ROWS 98304
#define C3 540
#define C2 360
#define HID 360
#define QKV_STR 576
#define HID_STR 384
#define Y_STR 192
#define ATT_SCALE 0.18257418583505536f

// ---------------- scratch ----------------
__device__ __half g_xw_h[M_ROWS * CC];
__device__ __half g_qkvS_h[M_ROWS * QKV_STR];
__device__ __half g_qkvM_h[M_ROWS * QKV_STR];
__device__ __half g_xo_h[M_ROWS * C2];
__device__ float  g_y[M_ROWS * Y_STR];
__device__ __half g_h2_h[M_ROWS * CC];
__device__ __half g_hid1_h[M_ROWS * HID_STR];
__device__ __half g_bias6_h[NHD * NTOK * NTOK];
__device__ __half g_mask_h[NWIN * NTOK * NTOK];
__device__ __half g_wT_qs[576 * 192];
__device__ __half g_wT_qm[576 * 192];
__device__ __half g_wT_pr[192 * 384];
__device__ __half g_wT_f11[384 * 192];
__device__ __half g_wT_f12[384 * 192];
__device__ __half g_wT_f2[192 * 384];

__device__ __forceinline__ int row_to_img(int r) {
    int win = r >> 7, n = r & 127;
    int dwin = win >> 8, rem = win & 255;
    int hwin = rem >> 4, wwin = rem & 15;
    int nd = n >> 6, nh = (n >> 3) & 7, nw = n & 7;
    int sd = dwin * 2 + nd + 1; if (sd >= 6) sd -= 6;
    int sh = (hwin * 8 + nh + 4) & 127;
    int sw = (wwin * 8 + nw + 4) & 127;
    return (sd * 128 + sh) * 128 + sw;
}

// ---------------- prep: qkv weights + bias + mask (fp16) ----------------
__device__ __forceinline__ void prep_one(const float* w, __half* wt, int idx,
                                         int K, int N, int Kpad, int Npad) {
    int n = idx / Kpad, k = idx % Kpad;
    wt[idx] = (n < N && k < K) ? __float2half(w[(long)k * N + n]) : __float2half(0.f);
}
__global__ void prep_qkv_kernel(const float* __restrict__ wqs, const float* __restrict__ wqm,
                                const float* __restrict__ rpb, const int* __restrict__ rpi,
                                const float* __restrict__ mask) {
    int idx = blockIdx.x * blockDim.x + threadIdx.x;
    const int S1 = 576 * 192;
    if (idx < S1) { prep_one(wqs, g_wT_qs, idx, CC, C3, 192, 576); return; }
    idx -= S1;
    if (idx < S1) { prep_one(wqm, g_wT_qm, idx, CC, C3, 192, 576); return; }
    idx -= S1;
    if (idx < NHD * NTOK * NTOK) {
        int h = idx / (NTOK * NTOK), ij = idx % (NTOK * NTOK);
        g_bias6_h[idx] = __float2half(rpb[rpi[ij] * NHD + h]);
        return;
    }
    idx -= NHD * NTOK * NTOK;
    if (idx < NWIN * NTOK * NTOK)
        g_mask_h[idx] = __float2half(mask[idx]);
}
__global__ void prep_rest_kernel(const float* __restrict__ wproj, const float* __restrict__ w11,
                                 const float* __restrict__ w12, const float* __restrict__ w2) {
    int idx = blockIdx.x * blockDim.x + threadIdx.x;
    const int S = 192 * 384;
    if (idx < S) prep_one(wproj, g_wT_pr, idx, C2, CC, 384, 192);
    else if (idx < 2 * S) prep_one(w11, g_wT_f11, idx - S, CC, HID, 192, 384);
    else if (idx < 3 * S) prep_one(w12, g_wT_f12, idx - 2 * S, CC, HID, 192, 384);
    else if (idx < 4 * S) prep_one(w2, g_wT_f2, idx - 3 * S, HID, CC, 384, 192);
}

// ---------------- LayerNorm: fp32 in -> fp16 out ----------------
template <int MODE>
__global__ __launch_bounds__(256) void ln_kernel(const float* __restrict__ in,
                                                 const float* __restrict__ gg,
                                                 const float* __restrict__ bb) {
    int gw = (blockIdx.x * blockDim.x + threadIdx.x) >> 5;
    int lane = threadIdx.x & 31;
    if (gw >= M_ROWS) return;
    const float* rowp;
    __half* orow;
    if (MODE == 0) {
        rowp = in + (long)row_to_img(gw) * CC;
        orow = g_xw_h + (long)gw * CC;
    } else {
        rowp = g_y + (long)gw * Y_STR;
        orow = g_h2_h + (long)gw * CC;
    }
    float vals[6];
    float s = 0.f, ss = 0.f;
    int cnt = 0;
    for (int c = lane; c < CC; c += 32) { float v = rowp[c]; vals[cnt++] = v; s += v; ss += v * v; }
#pragma unroll
    for (int o = 16; o > 0; o >>= 1) {
        s  += __shfl_xor_sync(0xffffffffu, s, o);
        ss += __shfl_xor_sync(0xffffffffu, ss, o);
    }
    float mean = s * (1.f / CC);
    float var = ss * (1.f / CC) - mean * mean;
    float rstd = rsqrtf(var + 1e-5f);
    cnt = 0;
    for (int c = lane; c < CC; c += 32)
        orow[c] = __float2half((vals[cnt++] - mean) * rstd * gg[c] + bb[c]);
}

// ---------------- qkv GEMM: half in, half out (direct), double-buffered B ----------------
template <int WID, int ADD_PB, int DSTID>
__global__ __launch_bounds__(256) void gemm_qkv(const float* __restrict__ bias,
                                                const float* __restrict__ pb) {
    constexpr int KPAD = 192, LDA = 200, LDC = 68, NTILES = 9;
    const __half* A = g_xw_h;
    const __half* BT = (WID == 0) ? g_wT_qs : g_wT_qm;
    __half* Cout = (DSTID == 0) ? g_qkvS_h : g_qkvM_h;
    extern __shared__ __align__(16) char smem[];
    __half* As = (__half*)smem;
    __half* Bs0 = As + 128 * LDA;
    __half* Bs1 = Bs0 + 64 * LDA;
    float* bias0 = (float*)(Bs1 + 64 * LDA);
    float* bias1 = bias0 + 16 * LDC;

    int tid = threadIdx.x, wid = tid >> 5;
    int m0 = blockIdx.x * 128;
    int wm = (wid & 3) * 32, wn = (wid >> 2) * 32;

    constexpr int KF4 = KPAD / 4;
    constexpr int KR4 = CC / 4;
    for (int idx = tid; idx < 128 * KF4; idx += 256) {
        int row = idx / KF4, c4 = idx % KF4;
        uint2 val = make_uint2(0u, 0u);
        if (c4 < KR4) {
            val = *(const uint2*)(A + (long)(m0 + row) * CC + c4 * 4);
            if (ADD_PB) {
                __half2 h0 = *(__half2*)&val.x, h1 = *(__half2*)&val.y;
                float4 p = *(const float4*)(pb + ((m0 + row) & 63) * CC + c4 * 4);
                float2 f0 = __half22float2(h0), f1 = __half22float2(h1);
                __half2 r0 = __floats2half2_rn(f0.x + p.x, f0.y + p.y);
                __half2 r1 = __floats2half2_rn(f1.x + p.z, f1.y + p.w);
                val.x = *(uint32_t*)&r0; val.y = *(uint32_t*)&r1;
            }
        }
        *(uint2*)(As + row * LDA + c4 * 4) = val;
    }

    constexpr int BU4 = KPAD / 8;
    constexpr int NB = (64 * BU4) / 256;
    for (int i = 0; i < NB; i++) {
        int idx = tid + i * 256;
        int n = idx / BU4, c = idx % BU4;
        *(uint4*)(Bs0 + n * LDA + c * 8) = *(const uint4*)(BT + (long)n * KPAD + c * 8);
    }
    for (int i = 0; i < 4; i++) {
        int idx = tid + i * 256;
        int row = idx >> 6, c = idx & 63;
        bias0[row * LDC + c] = bias[c];
    }
    __syncthreads();

    for (int t = 0; t < NTILES; t++) {
        __half* Bcur = (t & 1) ? Bs1 : Bs0;
        __half* Bnxt = (t & 1) ? Bs0 : Bs1;
        float* bcur = (t & 1) ? bias1 : bias0;
        float* bnxt = (t & 1) ? bias0 : bias1;
        int n0 = t * 64;
        bool has_next = (t + 1 < NTILES);

        uint4 breg[NB];
        float creg[4];
        if (has_next) {
            int n0n = n0 + 64;
#pragma unroll
            for (int i = 0; i < NB; i++) {
                int idx = tid + i * 256;
                int n = idx / BU4, c = idx % BU4;
                breg[i] = *(const uint4*)(BT + (long)(n0n + n) * KPAD + c * 8);
            }
#pragma unroll
            for (int i = 0; i < 4; i++) {
                int idx = tid + i * 256;
                int c = idx & 63;
                creg[i] = (n0n + c < C3) ? bias[n0n + c] : 0.f;
            }
        }

        wmma::fragment<wmma::accumulator, 16, 16, 16, float> acc[2][2];
#pragma unroll
        for (int i = 0; i < 2; i++)
#pragma unroll
            for (int j = 0; j < 2; j++)
                wmma::load_matrix_sync(acc[i][j], bcur + wn + j * 16, LDC, wmma::mem_row_major);
#pragma unroll
        for (int k = 0; k < KPAD; k += 16) {
            wmma::fragment<wmma::matrix_a, 16, 16, 16, __half, wmma::row_major> af[2];
            wmma::fragment<wmma::matrix_b, 16, 16, 16, __half, wmma::col_major> bf[2];
#pragma unroll
            for (int i = 0; i < 2; i++)
                wmma::load_matrix_sync(af[i], As + (wm + i * 16) * LDA + k, LDA);
#pragma unroll
            for (int j = 0; j < 2; j++)
                wmma::load_matrix_sync(bf[j], Bcur + (wn + j * 16) * LDA + k, LDA);
#pragma unroll
            for (int i = 0; i < 2; i++)
#pragma unroll
                for (int j = 0; j < 2; j++)
                    wmma::mma_sync(acc[i][j], af[i], bf[j], acc[i][j]);
        }
#pragma unroll
        for (int i = 0; i < 2; i++)
#pragma unroll
            for (int j = 0; j < 2; j++) {
                wmma::fragment<wmma::accumulator, 16, 16, 16, __half> hacc;
#pragma unroll
                for (int e = 0; e < hacc.num_elements; e++)
                    hacc.x[e] = __float2half(acc[i][j].x[e]);
                wmma::store_matrix_sync(Cout + (long)(m0 + wm + i * 16) * QKV_STR + n0 + wn + j * 16,
                                        hacc, QKV_STR, wmma::mem_row_major);
            }
        if (has_next) {
#pragma unroll
            for (int i = 0; i < NB; i++) {
                int idx = tid + i * 256;
                int n = idx / BU4, c = idx % BU4;
                *(uint4*)(Bnxt + n * LDA + c * 8) = breg[i];
            }
#pragma unroll
            for (int i = 0; i < 4; i++) {
                int idx = tid + i * 256;
                int row = idx >> 6, c = idx & 63;
                bnxt[row * LDC + c] = creg[i];
            }
        }
        __syncthreads();
    }
}

// ---------------- proj GEMM (unchanged) ----------------
__global__ __launch_bounds__(256) void gemm_proj(const float* __restrict__ bias,
                                                 const float* __restrict__ x) {
    constexpr int KPAD = 384, LDA = 392, LDC = 68, NTILES = 3;
    extern __shared__ __align__(16) char smem[];
    __half* As = (__half*)smem;
    __half* Bs = As + 128 * LDA;
    float* resT = (float*)(Bs + 64 * LDA);
    int* imgIdx = (int*)(resT + 128 * LDC);

    int tid = threadIdx.x, wid = tid >> 5;
    int m0 = blockIdx.x * 128;
    int wm = (wid & 3) * 32, wn = (wid >> 2) * 32;

    if (tid < 128) imgIdx[tid] = row_to_img(m0 + tid);

    constexpr int KF4 = KPAD / 4;
    constexpr int KR4 = C2 / 4;
    for (int idx = tid; idx < 128 * KF4; idx += 256) {
        int row = idx / KF4, c4 = idx % KF4;
        uint2 val = make_uint2(0u, 0u);
        if (c4 < KR4)
            val = *(const uint2*)(g_xo_h + (long)(m0 + row) * C2 + c4 * 4);
        *(uint2*)(As + row * LDA + c4 * 4) = val;
    }

    constexpr int BU4 = KPAD / 8;
    for (int t = 0; t < NTILES; t++) {
        int n0 = t * 64;
        for (int idx = tid; idx < 64 * BU4; idx += 256) {
            int n = idx / BU4, c = idx % BU4;
            *(uint4*)(Bs + n * LDA + c * 8) = *(const uint4*)(g_wT_pr + (long)(n0 + n) * KPAD + c * 8);
        }
        for (int idx = tid; idx < 128 * 16; idx += 256) {
            int row = idx >> 4, c4 = (idx & 15) * 4;
            int n = n0 + c4;
            float4 v = make_float4(0.f, 0.f, 0.f, 0.f);
            if (n + 4 <= CC) {
                const float4 bv = *(const float4*)(bias + n);
                const float4 xr = *(const float4*)(x + (long)imgIdx[row] * CC + n);
                v.x = bv.x + xr.x; v.y = bv.y + xr.y; v.z = bv.z + xr.z; v.w = bv.w + xr.w;
            }
            *(float4*)(resT + row * LDC + c4) = v;
        }
        __syncthreads();

        wmma::fragment<wmma::accumulator, 16, 16, 16, float> acc[2][2];
#pragma unroll
        for (int i = 0; i < 2; i++)
#pragma unroll
            for (int j = 0; j < 2; j++)
                wmma::load_matrix_sync(acc[i][j], resT + (wm + i * 16) * LDC + wn + j * 16, LDC, wmma::mem_row_major);
#pragma unroll
        for (int k = 0; k < KPAD; k += 16) {
            wmma::fragment<wmma::matrix_a, 16, 16, 16, __half, wmma::row_major> af[2];
            wmma::fragment<wmma::matrix_b, 16, 16, 16, __half, wmma::col_major> bf[2];
#pragma unroll
            for (int i = 0; i < 2; i++)
                wmma::load_matrix_sync(af[i], As + (wm + i * 16) * LDA + k, LDA);
#pragma unroll
            for (int j = 0; j < 2; j++)
                wmma::load_matrix_sync(bf[j], Bs + (wn + j * 16) * LDA + k, LDA);
#pragma unroll
            for (int i = 0; i < 2; i++)
#pragma unroll
                for (int j = 0; j < 2; j++)
                    wmma::mma_sync(acc[i][j], af[i], bf[j], acc[i][j]);
        }
#pragma unroll
        for (int i = 0; i < 2; i++)
#pragma unroll
            for (int j = 0; j < 2; j++)
                wmma::store_matrix_sync(g_y + (long)(m0 + wm + i * 16) * Y_STR + n0 + wn + j * 16,
                                        acc[i][j], Y_STR, wmma::mem_row_major);
        __syncthreads();
    }
}

// ---------------- fused MLP GEMM (unchanged) ----------------
__global__ __launch_bounds__(256) void gemm_mlp(const float* __restrict__ bias1,
                                                const float* __restrict__ bias2) {
    constexpr int KPAD = 192, LDA = 200, LDC = 68, NTILES = 6;
    extern __shared__ __align__(16) char smem[];
    __half* As = (__half*)smem;
    __half* Bs = As + 128 * LDA;
    float* Cs = (float*)(Bs + 64 * LDA);
    float* Cs2 = Cs + 128 * LDC;
    float* biasS = Cs2 + 128 * LDC;

    int tid = threadIdx.x, wid = tid >> 5;
    int m0 = blockIdx.x * 128;
    int wm = (wid & 3) * 32, wn = (wid >> 2) * 32;

    constexpr int KF4 = KPAD / 4;
    constexpr int KR4 = CC / 4;
    for (int idx = tid; idx < 128 * KF4; idx += 256) {
        int row = idx / KF4, c4 = idx % KF4;
        uint2 val = make_uint2(0u, 0u);
        if (c4 < KR4)
            val = *(const uint2*)(g_h2_h + (long)(m0 + row) * CC + c4 * 4);
        *(uint2*)(As + row * LDA + c4 * 4) = val;
    }

    constexpr int BU4 = KPAD / 8;
    for (int t = 0; t < NTILES; t++) {
        int n0 = t * 64;
#pragma unroll
        for (int pass = 0; pass < 2; pass++) {
            const __half* Bp = (pass == 0) ? g_wT_f11 : g_wT_f12;
            const float* bp = (pass == 0) ? bias1 : bias2;
            float* Cdst = (pass == 0) ? Cs : Cs2;
            for (int idx = tid; idx < 16 * 64; idx += 256) {
                int row = idx >> 6, c = idx & 63;
                biasS[row * LDC + c] = (n0 + c < HID) ? bp[n0 + c] : 0.f;
            }
            for (int idx = tid; idx < 64 * BU4; idx += 256) {
                int n = idx / BU4, c = idx % BU4;
                *(uint4*)(Bs + n * LDA + c * 8) = *(const uint4*)(Bp + (long)(n0 + n) * KPAD + c * 8);
            }
            __syncthreads();
            wmma::fragment<wmma::accumulator, 16, 16, 16, float> acc[2][2];
#pragma unroll
            for (int i = 0; i < 2; i++)
#pragma unroll
                for (int j = 0; j < 2; j++)
                    wmma::load_matrix_sync(acc[i][j], biasS + wn + j * 16, LDC, wmma::mem_row_major);
#pragma unroll
            for (int k = 0; k < KPAD; k += 16) {
                wmma::fragment<wmma::matrix_a, 16, 16, 16, __half, wmma::row_major> af[2];
                wmma::fragment<wmma::matrix_b, 16, 16, 16, __half, wmma::col_major> bf[2];
#pragma unroll
                for (int i = 0; i < 2; i++)
                    wmma::load_matrix_sync(af[i], As + (wm + i * 16) * LDA + k, LDA);
#pragma unroll
                for (int j = 0; j < 2; j++)
                    wmma::load_matrix_sync(bf[j], Bs + (wn + j * 16) * LDA + k, LDA);
#pragma unroll
                for (int i = 0; i < 2; i++)
#pragma unroll
                    for (int j = 0; j < 2; j++)
                        wmma::mma_sync(acc[i][j], af[i], bf[j], acc[i][j]);
            }
#pragma unroll
            for (int i = 0; i < 2; i++)
#pragma unroll
                for (int j = 0; j < 2; j++)
                    wmma::store_matrix_sync(Cdst + (wm + i * 16) * LDC + wn + j * 16,
                                            acc[i][j], LDC, wmma::mem_row_major);
            __syncthreads();
        }
        for (int idx = tid; idx < 128 * 16; idx += 256) {
            int row = idx >> 4, c4 = (idx & 15) * 4;
            float4 v = *(float4*)(Cs + row * LDC + c4);
            float4 v2 = *(float4*)(Cs2 + row * LDC + c4);
            float4 o;
            o.x = 0.5f * v.x * (1.f + erff(v.x * 0.70710678f)) * v2.x;
            o.y = 0.5f * v.y * (1.f + erff(v.y * 0.70710678f)) * v2.y;
            o.z = 0.5f * v.z * (1.f + erff(v.z * 0.70710678f)) * v2.z;
            o.w = 0.5f * v.w * (1.f + erff(v.w * 0.70710678f)) * v2.w;
            __half2 a = __floats2half2_rn(o.x, o.y);
            __half2 b = __floats2half2_rn(o.z, o.w);
            *(uint2*)(g_hid1_h + (long)(m0 + row) * HID_STR + t * 64 + c4) =
                make_uint2(*(uint32_t*)&a, *(uint32_t*)&b);
        }
        __syncthreads();
    }
}

// ---------------- fc2 GEMM (unchanged) ----------------
__global__ __launch_bounds__(256) void gemm_fc2(const float* __restrict__ bias,
                                                float* __restrict__ out) {
    constexpr int KPAD = 384, LDA = 392, LDC = 68, NTILES = 3;
    extern __shared__ __align__(16) char smem[];
    __half* As = (__half*)smem;
    __half* Bs = As + 128 * LDA;
    float* resT = (float*)(Bs + 64 * LDA);
    float* Cs = resT + 128 * LDC;
    int* imgIdx = (int*)(Cs + 128 * LDC);

    int tid = threadIdx.x, wid = tid >> 5;
    int m0 = blockIdx.x * 128;
    int wm = (wid & 3) * 32, wn = (wid >> 2) * 32;

    if (tid < 128) imgIdx[tid] = row_to_img(m0 + tid);

    constexpr int KF4 = KPAD / 4;
    for (int idx = tid; idx < 128 * KF4; idx += 256) {
        int row = idx / KF4, c4 = idx % KF4;
        *(uint2*)(As + row * LDA + c4 * 4) =
            *(const uint2*)(g_hid1_h + (long)(m0 + row) * HID_STR + c4 * 4);
    }

    constexpr int BU4 = KPAD / 8;
    for (int t = 0; t < NTILES; t++) {
        int n0 = t * 64;
        for (int idx = tid; idx < 64 * BU4; idx += 256) {
            int n = idx / BU4, c = idx % BU4;
            *(uint4*)(Bs + n * LDA + c * 8) = *(const uint4*)(g_wT_f2 + (long)(n0 + n) * KPAD + c * 8);
        }
        for (int idx = tid; idx < 128 * 16; idx += 256) {
            int row = idx >> 4, c4 = (idx & 15) * 4;
            int n = n0 + c4;
            float4 v = make_float4(0.f, 0.f, 0.f, 0.f);
            if (n + 4 <= CC) {
                const float4 bv = *(const float4*)(bias + n);
                const float4 yr = *(const float4*)(g_y + (long)(m0 + row) * Y_STR + n);
                v.x = bv.x + yr.x; v.y = bv.y + yr.y; v.z = bv.z + yr.z; v.w = bv.w + yr.w;
            }
            *(float4*)(resT + row * LDC + c4) = v;
        }
        __syncthreads();

        wmma::fragment<wmma::accumulator, 16, 16, 16, float> acc[2][2];
#pragma unroll
        for (int i = 0; i < 2; i++)
#pragma unroll
            for (int j = 0; j < 2; j++)
                wmma::load_matrix_sync(acc[i][j], resT + (wm + i * 16) * LDC + wn + j * 16, LDC, wmma::mem_row_major);
#pragma unroll
        for (int k = 0; k < KPAD; k += 16) {
            wmma::fragment<wmma::matrix_a, 16, 16, 16, __half, wmma::row_major> af[2];
            wmma::fragment<wmma::matrix_b, 16, 16, 16, __half, wmma::col_major> bf[2];
#pragma unroll
            for (int i = 0; i < 2; i++)
                wmma::load_matrix_sync(af[i], As + (wm + i * 16) * LDA + k, LDA);
#pragma unroll
            for (int j = 0; j < 2; j++)
                wmma::load_matrix_sync(bf[j], Bs + (wn + j * 16) * LDA + k, LDA);
#pragma unroll
            for (int i = 0; i < 2; i++)
#pragma unroll
                for (int j = 0; j < 2; j++)
                    wmma::mma_sync(acc[i][j], af[i], bf[j], acc[i][j]);
        }
#pragma unroll
        for (int i = 0; i < 2; i++)
#pragma unroll
            for (int j = 0; j < 2; j++)
                wmma::store_matrix_sync(Cs + (wm + i * 16) * LDC + wn + j * 16,
                                        acc[i][j], LDC, wmma::mem_row_major);
        __syncthreads();

        for (int idx = tid; idx < 128 * 16; idx += 256) {
            int row = idx >> 4, c4 = (idx & 15) * 4;
            int n = n0 + c4;
            if (n + 4 <= CC) {
                float4 v = *(float4*)(Cs + row * LDC + c4);
                *(float4*)(out + (long)imgIdx[row] * CC + n) = v;
            }
        }
        __syncthreads();
    }
}

// ---------------- self attention: 2-chunk keys, register O accum, 3 CTAs/SM ----------------
#define LQ 40
#define LSC 68   // chunked S stride (float)
#define LO 36
__global__ __launch_bounds__(256) void self_attn_kernel() {
    int h = blockIdx.x, w = blockIdx.y;
    int tid = threadIdx.x, wid = tid >> 5, lane = tid & 31;
    extern __shared__ __align__(16) char smraw[];
    __half* Qs = (__half*)smraw;
    __half* Ks = Qs + 128 * LQ;
    __half* Vs = Ks + 128 * LQ;
    float* S = (float*)(Vs + 128 * LQ);      // [128][LSC]
    __half* P = (__half*)S;                  // alias, half stride 2*LSC
    float* rsum = (float*)(S + 128 * LSC);   // [128]

    const __half* base = g_qkvS_h + (long)w * NTOK * QKV_STR + h * HDIM;
    const float scl = ATT_SCALE;

    for (int idx = tid; idx < 3 * 128 * 15; idx += 256) {
        int region = idx / (128 * 15);
        int rem = idx - region * (128 * 15);
        int row = rem / 15, c = rem - row * 15;
        uint32_t v = *(const uint32_t*)(base + (long)row * QKV_STR + region * 180 + c * 2);
        __half* dst = (region == 0) ? Qs : (region == 1) ? Ks : Vs;
        if (region == 0) {
            float2 f = __half22float2(*(__half2*)&v);
            __half2 r = __floats2half2_rn(f.x * scl, f.y * scl);
            v = *(uint32_t*)&r;
        }
        *(uint32_t*)(dst + row * LQ + c * 2) = v;
    }
    if (tid < 128) {
        uint32_t z = 0;
        *(uint32_t*)(Qs + tid * LQ + 30) = z;
        *(uint32_t*)(Ks + tid * LQ + 30) = z;
        *(uint32_t*)(Vs + tid * LQ + 30) = z;
        rsum[tid] = 0.f;
    }
    __syncthreads();

    wmma::fragment<wmma::accumulator, 16, 16, 16, float> oacc[2];
    wmma::fill_fragment(oacc[0], 0.f);
    wmma::fill_fragment(oacc[1], 0.f);

    const __half* bbase = g_bias6_h + h * (NTOK * NTOK);
    const __half* mbase = g_mask_h + (long)w * (NTOK * NTOK);

#pragma unroll
    for (int kc = 0; kc < 2; kc++) {
        int k0 = kc * 64;

        // S panel = Q @ K[k0:k0+64]^T ; warp wid: rows wid*16, 4 col tiles
        {
            wmma::fragment<wmma::accumulator, 16, 16, 16, float> acc[4];
#pragma unroll
            for (int j = 0; j < 4; j++) wmma::fill_fragment(acc[j], 0.f);
#pragma unroll
            for (int k = 0; k < 2; k++) {
                wmma::fragment<wmma::matrix_a, 16, 16, 16, __half, wmma::row_major> af;
                wmma::load_matrix_sync(af, Qs + (wid * 16) * LQ + k * 16, LQ);
#pragma unroll
                for (int j = 0; j < 4; j++) {
                    wmma::fragment<wmma::matrix_b, 16, 16, 16, __half, wmma::col_major> bf;
                    wmma::load_matrix_sync(bf, Ks + (k0 + j * 16) * LQ + k * 16, LQ);
                    wmma::mma_sync(acc[j], af, bf, acc[j]);
                }
            }
#pragma unroll
            for (int j = 0; j < 4; j++)
                wmma::store_matrix_sync(S + (wid * 16) * LSC + j * 16, acc[j], LSC, wmma::mem_row_major);
        }
        __syncthreads();

        // partial softmax: 16 rows per warp, 64 cols (lane*2)
        {
#pragma unroll
            for (int rr = 0; rr < 16; rr++) {
                int r = wid * 16 + rr;
                float2 s2 = *(float2*)(S + r * LSC + lane * 2);
                uint32_t bu = *(const uint32_t*)(bbase + r * NTOK + k0 + lane * 2);
                uint32_t mu = *(const uint32_t*)(mbase + r * NTOK + k0 + lane * 2);
                float2 b2 = __half22float2(*(__half2*)&bu);
                float2 m2 = __half22float2(*(__half2*)&mu);
                float p0 = __expf(s2.x + b2.x + m2.x);
                float p1 = __expf(s2.y + b2.y + m2.y);
                __half2 hp = __floats2half2_rn(p0, p1);
                *(uint32_t*)(P + r * (2 * LSC) + lane * 2) = *(uint32_t*)&hp;
                float psum = p0 + p1;
#pragma unroll
                for (int o = 16; o > 0; o >>= 1) psum += __shfl_xor_sync(0xffffffffu, psum, o);
                if (lane == 0) rsum[r] += psum;
            }
        }
        __syncthreads();

        // O += P_panel @ V[k0:k0+64]
        {
#pragma unroll
            for (int k = 0; k < 4; k++) {
                wmma::fragment<wmma::matrix_a, 16, 16, 16, __half, wmma::row_major> pf;
                wmma::load_matrix_sync(pf, P + (wid * 16) * (2 * LSC) + k * 16, 2 * LSC);
#pragma unroll
                for (int j = 0; j < 2; j++) {
                    wmma::fragment<wmma::matrix_b, 16, 16, 16, __half, wmma::row_major> vf;
                    wmma::load_matrix_sync(vf, Vs + (k0 + k * 16) * LQ + j * 16, LQ);
                    wmma::mma_sync(oacc[j], pf, vf, oacc[j]);
                }
            }
        }
        __syncthreads();
    }

    // store O to smem (reuse S region), scale, write out
    float* Of = S;
#pragma unroll
    for (int j = 0; j < 2; j++)
        wmma::store_matrix_sync(Of + (wid * 16) * LO + j * 16, oacc[j], LO, wmma::mem_row_major);
    __syncthreads();

    {
        int row = tid >> 1, part = tid & 1;
        float inv = 1.f / rsum[row];
        __half* orow = g_xo_h + (long)(w * NTOK + row) * C2 + CC + h * HDIM;
        int d0 = part * 15;
#pragma unroll
        for (int dd = 0; dd < 15; dd++)
            orow[d0 + dd] = __float2half(Of[row * LO + d0 + dd] * inv);
    }
}

// ---------------- mutual attention (unchanged from R12) ----------------
#define LSM 68
__global__ __launch_bounds__(256) void mut_attn_kernel() {
    int h = blockIdx.x, w = blockIdx.y;
    int tid = threadIdx.x, wid = tid >> 5, lane = tid & 31;
    extern __shared__ __align__(16) char smraw[];
    __half* Qs = (__half*)smraw;
    __half* Ks = Qs + 128 * LQ;
    __half* Vs = Ks + 128 * LQ;
    float* S = (float*)(Vs + 128 * LQ);
    __half* P = (__half*)S;
    float* rsum = (float*)(S + 2 * 64 * LSM);
    float* Of = (float*)Qs;

    const __half* base = g_qkvM_h + (long)w * NTOK * QKV_STR + h * HDIM;
    const float scl = ATT_SCALE;

    for (int idx = tid; idx < 3 * 128 * 15; idx += 256) {
        int region = idx / (128 * 15);
        int rem = idx - region * (128 * 15);
        int row = rem / 15, c = rem - row * 15;
        int srow = row;
        if (region == 0) srow = (row < 64) ? (64 + row) : (row - 64);
        uint32_t v = *(const uint32_t*)(base + (long)srow * QKV_STR + region * 180 + c * 2);
        __half* dst = (region == 0) ? Qs : (region == 1) ? Ks : Vs;
        if (region == 0) {
            float2 f = __half22float2(*(__half2*)&v);
            __half2 r = __floats2half2_rn(f.x * scl, f.y * scl);
            v = *(uint32_t*)&r;
        }
        *(uint32_t*)(dst + row * LQ + c * 2) = v;
    }
    if (tid < 128) {
        uint32_t z = 0;
        *(uint32_t*)(Qs + tid * LQ + 30) = z;
        *(uint32_t*)(Ks + tid * LQ + 30) = z;
        *(uint32_t*)(Vs + tid * LQ + 30) = z;
    }
    __syncthreads();

    int g = wid >> 2, mt = wid & 3;

    {
        wmma::fragment<wmma::accumulator, 16, 16, 16, float> acc[4];
#pragma unroll
        for (int j = 0; j < 4; j++) wmma::fill_fragment(acc[j], 0.f);
#pragma unroll
        for (int k = 0; k < 2; k++) {
            wmma::fragment<wmma::matrix_a, 16, 16, 16, __half, wmma::row_major> af;
            wmma::load_matrix_sync(af, Qs + (g * 64 + mt * 16) * LQ + k * 16, LQ);
#pragma unroll
            for (int j = 0; j < 4; j++) {
                wmma::fragment<wmma::matrix_b, 16, 16, 16, __half, wmma::col_major> bf;
                wmma::load_matrix_sync(bf, Ks + (g * 64 + j * 16) * LQ + k * 16, LQ);
                wmma::mma_sync(acc[j], af, bf, acc[j]);
            }
        }
#pragma unroll
        for (int j = 0; j < 4; j++)
            wmma::store_matrix_sync(S + g * 64 * LSM + (mt * 16) * LSM + j * 16, acc[j], LSM, wmma::mem_row_major);
    }
    __syncthreads();

    {
        const __half* mbase = g_mask_h + (long)w * (NTOK * NTOK);
        for (int rr = 0; rr < 16; rr++) {
            int r = wid * 16 + rr;
            int gg = r >> 6, i = r & 63;
            float2 s2 = *(float2*)(S + gg * 64 * LSM + i * LSM + lane * 2);
            uint32_t mu = *(const uint32_t*)(mbase + i * NTOK + lane * 2);
            float2 m2 = __half22float2(*(__half2*)&mu);
            float p0 = __expf(s2.x + m2.x);
            float p1 = __expf(s2.y + m2.y);
            __half2 hp = __floats2half2_rn(p0, p1);
            *(uint32_t*)(P + gg * 64 * (2 * LSM) + i * (2 * LSM) + lane * 2) = *(uint32_t*)&hp;
            float psum = p0 + p1;
#pragma unroll
            for (int o = 16; o > 0; o >>= 1) psum += __shfl_xor_sync(0xffffffffu, psum, o);
            if (lane == 0) rsum[r] = 1.f / psum;
        }
    }
    __syncthreads();

    {
        wmma::fragment<wmma::accumulator, 16, 16, 16, float> acc[2];
        wmma::fill_fragment(acc[0], 0.f);
        wmma::fill_fragment(acc[1], 0.f);
#pragma unroll
        for (int k = 0; k < 4; k++) {
            wmma::fragment<wmma::matrix_a, 16, 16, 16, __half, wmma::row_major> pf;
            wmma::load_matrix_sync(pf, P + g * 64 * (2 * LSM) + (mt * 16) * (2 * LSM) + k * 16, 2 * LSM);
#pragma unroll
            for (int j = 0; j < 2; j++) {
                wmma::fragment<wmma::matrix_b, 16, 16, 16, __half, wmma::row_major> vf;
                wmma::load_matrix_sync(vf, Vs + (g * 64 + k * 16) * LQ + j * 16, LQ);
                wmma::mma_sync(acc[j], pf, vf, acc[j]);
            }
        }
#pragma unroll
        for (int j = 0; j < 2; j++)
            wmma::store_matrix_sync(Of + (g * 64 + mt * 16) * LO + j * 16, acc[j], LO, wmma::mem_row_major);
    }
    __syncthreads();

    {
        int row = tid >> 1, part = tid & 1;
        float inv = rsum[row];
        __half* orow = g_xo_h + (long)(w * NTOK + row) * C2 + h * HDIM;
        int d0 = part * 15;
#pragma unroll
        for (int dd = 0; dd < 15; dd++)
            orow[d0 + dd] = __float2half(Of[row * LO + d0 + dd] * inv);
    }
}

// ---------------- launcher ----------------
extern "C" void kernel_launch(void* const* d_in, const int* in_sizes, int n_in,
                              void* d_out, int out_size) {
    const float* x     = (const float*)d_in[0];
    const float* mask  = (const float*)d_in[1];
    const float* g1    = (const float*)d_in[2];
    const float* b1    = (const float*)d_in[3];
    const float* g2    = (const float*)d_in[4];
    const float* b2    = (const float*)d_in[5];
    const float* wqs   = (const float*)d_in[6];
    const float* bqs   = (const float*)d_in[7];
    const float* wqm   = (const float*)d_in[8];
    const float* bqm   = (const float*)d_in[9];
    const float* rpb   = (const float*)d_in[10];
    const float* posb  = (const float*)d_in[11];
    const float* wproj = (const float*)d_in[12];
    const float* bproj = (const float*)d_in[13];
    const float* w11   = (const float*)d_in[14];
    const float* b11   = (const float*)d_in[15];
    const float* w12   = (const float*)d_in[16];
    const float* b12   = (const float*)d_in[17];
    const float* w2    = (const float*)d_in[18];
    const float* b2f   = (const float*)d_in[19];
    const int*   rpi   = (const int*)d_in[20];
    float* out = (float*)d_out;

    const int SMEM_QKV  = 128 * 200 * 2 + 2 * 64 * 200 * 2 + 2 * 16 * 68 * 4;            // 111104
    const int SMEM_PROJ = 128 * 392 * 2 + 64 * 392 * 2 + 128 * 68 * 4 + 128 * 4;         // 185856
    const int SMEM_MLP  = 128 * 200 * 2 + 64 * 200 * 2 + 2 * 128 * 68 * 4 + 16 * 68 * 4; // 150784
    const int SMEM_FC2  = 128 * 392 * 2 + 64 * 392 * 2 + 2 * 128 * 68 * 4 + 128 * 4;     // 220672
    const int SMEM_SELF = 3 * 128 * LQ * 2 + 128 * LSC * 4 + 128 * 4;                    // 66048 -> 3 CTAs/SM
    const int SMEM_MUT  = 3 * 128 * LQ * 2 + 2 * 64 * LSM * 4 + 128 * 4;                 // 66048

    cudaFuncSetAttribute(&gemm_qkv<0, 0, 0>, cudaFuncAttributeMaxDynamicSharedMemorySize, SMEM_QKV);
    cudaFuncSetAttribute(&gemm_qkv<1, 1, 1>, cudaFuncAttributeMaxDynamicSharedMemorySize, SMEM_QKV);
    cudaFuncSetAttribute(gemm_proj, cudaFuncAttributeMaxDynamicSharedMemorySize, SMEM_PROJ);
    cudaFuncSetAttribute(gemm_mlp,  cudaFuncAttributeMaxDynamicSharedMemorySize, SMEM_MLP);
    cudaFuncSetAttribute(gemm_fc2,  cudaFuncAttributeMaxDynamicSharedMemorySize, SMEM_FC2);
    cudaFuncSetAttribute(self_attn_kernel, cudaFuncAttributeMaxDynamicSharedMemorySize, SMEM_SELF);
    cudaFuncSetAttribute(mut_attn_kernel,  cudaFuncAttributeMaxDynamicSharedMemorySize, SMEM_MUT);

    dim3 ga(NHD, NWIN);
    int prep_n = 2 * 576 * 192 + NHD * NTOK * NTOK + NWIN * NTOK * NTOK;
    prep_qkv_kernel<<<(prep_n + 255) / 256, 256>>>(wqs, wqm, rpb, rpi, mask);   // 0
    ln_kernel<0><<<(M_ROWS * 32) / 256, 256>>>(x, g1, b1);                      // 1
    gemm_qkv<0, 0, 0><<<768, 256, SMEM_QKV>>>(bqs, nullptr);                    // 2
    self_attn_kernel<<<ga, 256, SMEM_SELF>>>();                                 // 3 <- ncu slot
    prep_rest_kernel<<<(4 * 192 * 384 + 255) / 256, 256>>>(wproj, w11, w12, w2);// 4
    gemm_qkv<1, 1, 1><<<768, 256, SMEM_QKV>>>(bqm, posb);                       // 5
    mut_attn_kernel<<<ga, 256, SMEM_MUT>>>();                                   // 6
    gemm_proj<<<768, 256, SMEM_PROJ>>>(bproj, x);                               // 7
    ln_kernel<1><<<(M_ROWS * 32) / 256, 256>>>(nullptr, g2, b2);                // 8
    gemm_mlp<<<768, 256, SMEM_MLP>>>(b11, b12);                                 // 9
    gemm_fc2<<<768, 256, SMEM_FC2>>>(b2f, out);                                 // 10
}

// round 14
// speedup vs baseline: 1.3880x; 1.0997x over previous
#include <cuda_runtime.h>
#include <cuda_fp16.h>
#include <mma.h>
#include <cstdint>
#include <math_constants.h>
#include <math.h>

using namespace nvcuda;

// ---------------- problem constants ----------------
#define CC 180
#define NHD 6
#define HDIM 30
#define NWIN 768
#define NTOK 128
#define M_ROWS 98304
#define C3 540
#define C2 360
#define HID 360
#define QKV_STR 576
#define HID_STR 384
#define Y_STR 192
#define ATT_SCALE 0.18257418583505536f

// ---------------- scratch ----------------
__device__ __half g_xw_h[M_ROWS * CC];
__device__ __half g_qkvS_h[M_ROWS * QKV_STR];
__device__ __half g_qkvM_h[M_ROWS * QKV_STR];
__device__ __half g_xo_h[M_ROWS * C2];
__device__ float  g_y[M_ROWS * Y_STR];
__device__ __half g_h2_h[M_ROWS * CC];
__device__ __half g_hid1_h[M_ROWS * HID_STR];
__device__ __half g_bias6_h[NHD * NTOK * NTOK];
__device__ __half g_mask_h[NWIN * NTOK * NTOK];
__device__ __half g_wT_qs[576 * 192];
__device__ __half g_wT_qm[576 * 192];
__device__ __half g_wT_pr[192 * 384];
__device__ __half g_wT_f11[384 * 192];
__device__ __half g_wT_f12[384 * 192];
__device__ __half g_wT_f2[192 * 384];

__device__ __forceinline__ int row_to_img(int r) {
    int win = r >> 7, n = r & 127;
    int dwin = win >> 8, rem = win & 255;
    int hwin = rem >> 4, wwin = rem & 15;
    int nd = n >> 6, nh = (n >> 3) & 7, nw = n & 7;
    int sd = dwin * 2 + nd + 1; if (sd >= 6) sd -= 6;
    int sh = (hwin * 8 + nh + 4) & 127;
    int sw = (wwin * 8 + nw + 4) & 127;
    return (sd * 128 + sh) * 128 + sw;
}

// ---------------- prep kernels ----------------
__device__ __forceinline__ void prep_one(const float* w, __half* wt, int idx,
                                         int K, int N, int Kpad, int Npad) {
    int n = idx / Kpad, k = idx % Kpad;
    wt[idx] = (n < N && k < K) ? __float2half(w[(long)k * N + n]) : __float2half(0.f);
}
__global__ void prep_qkv_kernel(const float* __restrict__ wqs, const float* __restrict__ wqm,
                                const float* __restrict__ rpb, const int* __restrict__ rpi,
                                const float* __restrict__ mask) {
    int idx = blockIdx.x * blockDim.x + threadIdx.x;
    const int S1 = 576 * 192;
    if (idx < S1) { prep_one(wqs, g_wT_qs, idx, CC, C3, 192, 576); return; }
    idx -= S1;
    if (idx < S1) { prep_one(wqm, g_wT_qm, idx, CC, C3, 192, 576); return; }
    idx -= S1;
    if (idx < NHD * NTOK * NTOK) {
        int h = idx / (NTOK * NTOK), ij = idx % (NTOK * NTOK);
        g_bias6_h[idx] = __float2half(rpb[rpi[ij] * NHD + h]);
        return;
    }
    idx -= NHD * NTOK * NTOK;
    if (idx < NWIN * NTOK * NTOK)
        g_mask_h[idx] = __float2half(mask[idx]);
}
__global__ void prep_rest_kernel(const float* __restrict__ wproj, const float* __restrict__ w11,
                                 const float* __restrict__ w12, const float* __restrict__ w2) {
    int idx = blockIdx.x * blockDim.x + threadIdx.x;
    const int S = 192 * 384;
    if (idx < S) prep_one(wproj, g_wT_pr, idx, C2, CC, 384, 192);
    else if (idx < 2 * S) prep_one(w11, g_wT_f11, idx - S, CC, HID, 192, 384);
    else if (idx < 3 * S) prep_one(w12, g_wT_f12, idx - 2 * S, CC, HID, 192, 384);
    else if (idx < 4 * S) prep_one(w2, g_wT_f2, idx - 3 * S, HID, CC, 384, 192);
}

// ---------------- LayerNorm ----------------
template <int MODE>
__global__ __launch_bounds__(256) void ln_kernel(const float* __restrict__ in,
                                                 const float* __restrict__ gg,
                                                 const float* __restrict__ bb) {
    int gw = (blockIdx.x * blockDim.x + threadIdx.x) >> 5;
    int lane = threadIdx.x & 31;
    if (gw >= M_ROWS) return;
    const float* rowp;
    __half* orow;
    if (MODE == 0) {
        rowp = in + (long)row_to_img(gw) * CC;
        orow = g_xw_h + (long)gw * CC;
    } else {
        rowp = g_y + (long)gw * Y_STR;
        orow = g_h2_h + (long)gw * CC;
    }
    float vals[6];
    float s = 0.f, ss = 0.f;
    int cnt = 0;
    for (int c = lane; c < CC; c += 32) { float v = rowp[c]; vals[cnt++] = v; s += v; ss += v * v; }
#pragma unroll
    for (int o = 16; o > 0; o >>= 1) {
        s  += __shfl_xor_sync(0xffffffffu, s, o);
        ss += __shfl_xor_sync(0xffffffffu, ss, o);
    }
    float mean = s * (1.f / CC);
    float var = ss * (1.f / CC) - mean * mean;
    float rstd = rsqrtf(var + 1e-5f);
    cnt = 0;
    for (int c = lane; c < CC; c += 32)
        orow[c] = __float2half((vals[cnt++] - mean) * rstd * gg[c] + bb[c]);
}

// ---------------- qkv GEMM (unchanged from R13) ----------------
template <int WID, int ADD_PB, int DSTID>
__global__ __launch_bounds__(256) void gemm_qkv(const float* __restrict__ bias,
                                                const float* __restrict__ pb) {
    constexpr int KPAD = 192, LDA = 200, LDC = 68, NTILES = 9;
    const __half* A = g_xw_h;
    const __half* BT = (WID == 0) ? g_wT_qs : g_wT_qm;
    __half* Cout = (DSTID == 0) ? g_qkvS_h : g_qkvM_h;
    extern __shared__ __align__(16) char smem[];
    __half* As = (__half*)smem;
    __half* Bs0 = As + 128 * LDA;
    __half* Bs1 = Bs0 + 64 * LDA;
    float* bias0 = (float*)(Bs1 + 64 * LDA);
    float* bias1 = bias0 + 16 * LDC;

    int tid = threadIdx.x, wid = tid >> 5;
    int m0 = blockIdx.x * 128;
    int wm = (wid & 3) * 32, wn = (wid >> 2) * 32;

    constexpr int KF4 = KPAD / 4;
    constexpr int KR4 = CC / 4;
    for (int idx = tid; idx < 128 * KF4; idx += 256) {
        int row = idx / KF4, c4 = idx % KF4;
        uint2 val = make_uint2(0u, 0u);
        if (c4 < KR4) {
            val = *(const uint2*)(A + (long)(m0 + row) * CC + c4 * 4);
            if (ADD_PB) {
                __half2 h0 = *(__half2*)&val.x, h1 = *(__half2*)&val.y;
                float4 p = *(const float4*)(pb + ((m0 + row) & 63) * CC + c4 * 4);
                float2 f0 = __half22float2(h0), f1 = __half22float2(h1);
                __half2 r0 = __floats2half2_rn(f0.x + p.x, f0.y + p.y);
                __half2 r1 = __floats2half2_rn(f1.x + p.z, f1.y + p.w);
                val.x = *(uint32_t*)&r0; val.y = *(uint32_t*)&r1;
            }
        }
        *(uint2*)(As + row * LDA + c4 * 4) = val;
    }

    constexpr int BU4 = KPAD / 8;
    constexpr int NB = (64 * BU4) / 256;
    for (int i = 0; i < NB; i++) {
        int idx = tid + i * 256;
        int n = idx / BU4, c = idx % BU4;
        *(uint4*)(Bs0 + n * LDA + c * 8) = *(const uint4*)(BT + (long)n * KPAD + c * 8);
    }
    for (int i = 0; i < 4; i++) {
        int idx = tid + i * 256;
        int row = idx >> 6, c = idx & 63;
        bias0[row * LDC + c] = bias[c];
    }
    __syncthreads();

    for (int t = 0; t < NTILES; t++) {
        __half* Bcur = (t & 1) ? Bs1 : Bs0;
        __half* Bnxt = (t & 1) ? Bs0 : Bs1;
        float* bcur = (t & 1) ? bias1 : bias0;
        float* bnxt = (t & 1) ? bias0 : bias1;
        int n0 = t * 64;
        bool has_next = (t + 1 < NTILES);

        uint4 breg[NB];
        float creg[4];
        if (has_next) {
            int n0n = n0 + 64;
#pragma unroll
            for (int i = 0; i < NB; i++) {
                int idx = tid + i * 256;
                int n = idx / BU4, c = idx % BU4;
                breg[i] = *(const uint4*)(BT + (long)(n0n + n) * KPAD + c * 8);
            }
#pragma unroll
            for (int i = 0; i < 4; i++) {
                int idx = tid + i * 256;
                int c = idx & 63;
                creg[i] = (n0n + c < C3) ? bias[n0n + c] : 0.f;
            }
        }

        wmma::fragment<wmma::accumulator, 16, 16, 16, float> acc[2][2];
#pragma unroll
        for (int i = 0; i < 2; i++)
#pragma unroll
            for (int j = 0; j < 2; j++)
                wmma::load_matrix_sync(acc[i][j], bcur + wn + j * 16, LDC, wmma::mem_row_major);
#pragma unroll
        for (int k = 0; k < KPAD; k += 16) {
            wmma::fragment<wmma::matrix_a, 16, 16, 16, __half, wmma::row_major> af[2];
            wmma::fragment<wmma::matrix_b, 16, 16, 16, __half, wmma::col_major> bf[2];
#pragma unroll
            for (int i = 0; i < 2; i++)
                wmma::load_matrix_sync(af[i], As + (wm + i * 16) * LDA + k, LDA);
#pragma unroll
            for (int j = 0; j < 2; j++)
                wmma::load_matrix_sync(bf[j], Bcur + (wn + j * 16) * LDA + k, LDA);
#pragma unroll
            for (int i = 0; i < 2; i++)
#pragma unroll
                for (int j = 0; j < 2; j++)
                    wmma::mma_sync(acc[i][j], af[i], bf[j], acc[i][j]);
        }
#pragma unroll
        for (int i = 0; i < 2; i++)
#pragma unroll
            for (int j = 0; j < 2; j++) {
                wmma::fragment<wmma::accumulator, 16, 16, 16, __half> hacc;
#pragma unroll
                for (int e = 0; e < hacc.num_elements; e++)
                    hacc.x[e] = __float2half(acc[i][j].x[e]);
                wmma::store_matrix_sync(Cout + (long)(m0 + wm + i * 16) * QKV_STR + n0 + wn + j * 16,
                                        hacc, QKV_STR, wmma::mem_row_major);
            }
        if (has_next) {
#pragma unroll
            for (int i = 0; i < NB; i++) {
                int idx = tid + i * 256;
                int n = idx / BU4, c = idx % BU4;
                *(uint4*)(Bnxt + n * LDA + c * 8) = breg[i];
            }
#pragma unroll
            for (int i = 0; i < 4; i++) {
                int idx = tid + i * 256;
                int row = idx >> 6, c = idx & 63;
                bnxt[row * LDC + c] = creg[i];
            }
        }
        __syncthreads();
    }
}

// ---------------- proj GEMM (unchanged) ----------------
__global__ __launch_bounds__(256) void gemm_proj(const float* __restrict__ bias,
                                                 const float* __restrict__ x) {
    constexpr int KPAD = 384, LDA = 392, LDC = 68, NTILES = 3;
    extern __shared__ __align__(16) char smem[];
    __half* As = (__half*)smem;
    __half* Bs = As + 128 * LDA;
    float* resT = (float*)(Bs + 64 * LDA);
    int* imgIdx = (int*)(resT + 128 * LDC);

    int tid = threadIdx.x, wid = tid >> 5;
    int m0 = blockIdx.x * 128;
    int wm = (wid & 3) * 32, wn = (wid >> 2) * 32;

    if (tid < 128) imgIdx[tid] = row_to_img(m0 + tid);

    constexpr int KF4 = KPAD / 4;
    constexpr int KR4 = C2 / 4;
    for (int idx = tid; idx < 128 * KF4; idx += 256) {
        int row = idx / KF4, c4 = idx % KF4;
        uint2 val = make_uint2(0u, 0u);
        if (c4 < KR4)
            val = *(const uint2*)(g_xo_h + (long)(m0 + row) * C2 + c4 * 4);
        *(uint2*)(As + row * LDA + c4 * 4) = val;
    }

    constexpr int BU4 = KPAD / 8;
    for (int t = 0; t < NTILES; t++) {
        int n0 = t * 64;
        for (int idx = tid; idx < 64 * BU4; idx += 256) {
            int n = idx / BU4, c = idx % BU4;
            *(uint4*)(Bs + n * LDA + c * 8) = *(const uint4*)(g_wT_pr + (long)(n0 + n) * KPAD + c * 8);
        }
        for (int idx = tid; idx < 128 * 16; idx += 256) {
            int row = idx >> 4, c4 = (idx & 15) * 4;
            int n = n0 + c4;
            float4 v = make_float4(0.f, 0.f, 0.f, 0.f);
            if (n + 4 <= CC) {
                const float4 bv = *(const float4*)(bias + n);
                const float4 xr = *(const float4*)(x + (long)imgIdx[row] * CC + n);
                v.x = bv.x + xr.x; v.y = bv.y + xr.y; v.z = bv.z + xr.z; v.w = bv.w + xr.w;
            }
            *(float4*)(resT + row * LDC + c4) = v;
        }
        __syncthreads();

        wmma::fragment<wmma::accumulator, 16, 16, 16, float> acc[2][2];
#pragma unroll
        for (int i = 0; i < 2; i++)
#pragma unroll
            for (int j = 0; j < 2; j++)
                wmma::load_matrix_sync(acc[i][j], resT + (wm + i * 16) * LDC + wn + j * 16, LDC, wmma::mem_row_major);
#pragma unroll
        for (int k = 0; k < KPAD; k += 16) {
            wmma::fragment<wmma::matrix_a, 16, 16, 16, __half, wmma::row_major> af[2];
            wmma::fragment<wmma::matrix_b, 16, 16, 16, __half, wmma::col_major> bf[2];
#pragma unroll
            for (int i = 0; i < 2; i++)
                wmma::load_matrix_sync(af[i], As + (wm + i * 16) * LDA + k, LDA);
#pragma unroll
            for (int j = 0; j < 2; j++)
                wmma::load_matrix_sync(bf[j], Bs + (wn + j * 16) * LDA + k, LDA);
#pragma unroll
            for (int i = 0; i < 2; i++)
#pragma unroll
                for (int j = 0; j < 2; j++)
                    wmma::mma_sync(acc[i][j], af[i], bf[j], acc[i][j]);
        }
#pragma unroll
        for (int i = 0; i < 2; i++)
#pragma unroll
            for (int j = 0; j < 2; j++)
                wmma::store_matrix_sync(g_y + (long)(m0 + wm + i * 16) * Y_STR + n0 + wn + j * 16,
                                        acc[i][j], Y_STR, wmma::mem_row_major);
        __syncthreads();
    }
}

// ---------------- fused MLP GEMM: fp16 C tiles, epilogue bias -> 2 CTAs/SM ----------------
__global__ __launch_bounds__(256, 2) void gemm_mlp(const float* __restrict__ bias1,
                                                   const float* __restrict__ bias2) {
    constexpr int KPAD = 192, LDA = 200, LDCH = 72, NTILES = 6;
    extern __shared__ __align__(16) char smem[];
    __half* As = (__half*)smem;
    __half* Bs = As + 128 * LDA;
    __half* Cs = Bs + 64 * LDA;          // [128][72] half
    __half* Cs2 = Cs + 128 * LDCH;       // [128][72] half

    int tid = threadIdx.x, wid = tid >> 5;
    int m0 = blockIdx.x * 128;
    int wm = (wid & 3) * 32, wn = (wid >> 2) * 32;

    constexpr int KF4 = KPAD / 4;
    constexpr int KR4 = CC / 4;
    for (int idx = tid; idx < 128 * KF4; idx += 256) {
        int row = idx / KF4, c4 = idx % KF4;
        uint2 val = make_uint2(0u, 0u);
        if (c4 < KR4)
            val = *(const uint2*)(g_h2_h + (long)(m0 + row) * CC + c4 * 4);
        *(uint2*)(As + row * LDA + c4 * 4) = val;
    }

    constexpr int BU4 = KPAD / 8;
    for (int t = 0; t < NTILES; t++) {
        int n0 = t * 64;
#pragma unroll
        for (int pass = 0; pass < 2; pass++) {
            const __half* Bp = (pass == 0) ? g_wT_f11 : g_wT_f12;
            __half* Cdst = (pass == 0) ? Cs : Cs2;
            for (int idx = tid; idx < 64 * BU4; idx += 256) {
                int n = idx / BU4, c = idx % BU4;
                *(uint4*)(Bs + n * LDA + c * 8) = *(const uint4*)(Bp + (long)(n0 + n) * KPAD + c * 8);
            }
            __syncthreads();
            wmma::fragment<wmma::accumulator, 16, 16, 16, float> acc[2][2];
#pragma unroll
            for (int i = 0; i < 2; i++)
#pragma unroll
                for (int j = 0; j < 2; j++) wmma::fill_fragment(acc[i][j], 0.f);
#pragma unroll
            for (int k = 0; k < KPAD; k += 16) {
                wmma::fragment<wmma::matrix_a, 16, 16, 16, __half, wmma::row_major> af[2];
                wmma::fragment<wmma::matrix_b, 16, 16, 16, __half, wmma::col_major> bf[2];
#pragma unroll
                for (int i = 0; i < 2; i++)
                    wmma::load_matrix_sync(af[i], As + (wm + i * 16) * LDA + k, LDA);
#pragma unroll
                for (int j = 0; j < 2; j++)
                    wmma::load_matrix_sync(bf[j], Bs + (wn + j * 16) * LDA + k, LDA);
#pragma unroll
                for (int i = 0; i < 2; i++)
#pragma unroll
                    for (int j = 0; j < 2; j++)
                        wmma::mma_sync(acc[i][j], af[i], bf[j], acc[i][j]);
            }
#pragma unroll
            for (int i = 0; i < 2; i++)
#pragma unroll
                for (int j = 0; j < 2; j++) {
                    wmma::fragment<wmma::accumulator, 16, 16, 16, __half> hacc;
#pragma unroll
                    for (int e = 0; e < hacc.num_elements; e++)
                        hacc.x[e] = __float2half(acc[i][j].x[e]);
                    wmma::store_matrix_sync(Cdst + (wm + i * 16) * LDCH + wn + j * 16,
                                            hacc, LDCH, wmma::mem_row_major);
                }
            __syncthreads();
        }
        // epilogue: bias + gelu gate, fp16 out
        for (int idx = tid; idx < 128 * 16; idx += 256) {
            int row = idx >> 4, c4 = (idx & 15) * 4;
            int n = n0 + c4;
            uint2 u1 = *(uint2*)(Cs + row * LDCH + c4);
            uint2 u2 = *(uint2*)(Cs2 + row * LDCH + c4);
            float2 a0 = __half22float2(*(__half2*)&u1.x), a1 = __half22float2(*(__half2*)&u1.y);
            float2 g0 = __half22float2(*(__half2*)&u2.x), g1v = __half22float2(*(__half2*)&u2.y);
            float b1v[4], b2v[4];
#pragma unroll
            for (int e = 0; e < 4; e++) {
                b1v[e] = (n + e < HID) ? bias1[n + e] : 0.f;
                b2v[e] = (n + e < HID) ? bias2[n + e] : 0.f;
            }
            float v[4] = {a0.x + b1v[0], a0.y + b1v[1], a1.x + b1v[2], a1.y + b1v[3]};
            float v2[4] = {g0.x + b2v[0], g0.y + b2v[1], g1v.x + b2v[2], g1v.y + b2v[3]};
            float o[4];
#pragma unroll
            for (int e = 0; e < 4; e++)
                o[e] = 0.5f * v[e] * (1.f + erff(v[e] * 0.70710678f)) * v2[e];
            __half2 ha = __floats2half2_rn(o[0], o[1]);
            __half2 hb = __floats2half2_rn(o[2], o[3]);
            *(uint2*)(g_hid1_h + (long)(m0 + row) * HID_STR + n0 + c4) =
                make_uint2(*(uint32_t*)&ha, *(uint32_t*)&hb);
        }
        __syncthreads();
    }
}

// ---------------- fc2 GEMM (unchanged) ----------------
__global__ __launch_bounds__(256) void gemm_fc2(const float* __restrict__ bias,
                                                float* __restrict__ out) {
    constexpr int KPAD = 384, LDA = 392, LDC = 68, NTILES = 3;
    extern __shared__ __align__(16) char smem[];
    __half* As = (__half*)smem;
    __half* Bs = As + 128 * LDA;
    float* resT = (float*)(Bs + 64 * LDA);
    float* Cs = resT + 128 * LDC;
    int* imgIdx = (int*)(Cs + 128 * LDC);

    int tid = threadIdx.x, wid = tid >> 5;
    int m0 = blockIdx.x * 128;
    int wm = (wid & 3) * 32, wn = (wid >> 2) * 32;

    if (tid < 128) imgIdx[tid] = row_to_img(m0 + tid);

    constexpr int KF4 = KPAD / 4;
    for (int idx = tid; idx < 128 * KF4; idx += 256) {
        int row = idx / KF4, c4 = idx % KF4;
        *(uint2*)(As + row * LDA + c4 * 4) =
            *(const uint2*)(g_hid1_h + (long)(m0 + row) * HID_STR + c4 * 4);
    }

    constexpr int BU4 = KPAD / 8;
    for (int t = 0; t < NTILES; t++) {
        int n0 = t * 64;
        for (int idx = tid; idx < 64 * BU4; idx += 256) {
            int n = idx / BU4, c = idx % BU4;
            *(uint4*)(Bs + n * LDA + c * 8) = *(const uint4*)(g_wT_f2 + (long)(n0 + n) * KPAD + c * 8);
        }
        for (int idx = tid; idx < 128 * 16; idx += 256) {
            int row = idx >> 4, c4 = (idx & 15) * 4;
            int n = n0 + c4;
            float4 v = make_float4(0.f, 0.f, 0.f, 0.f);
            if (n + 4 <= CC) {
                const float4 bv = *(const float4*)(bias + n);
                const float4 yr = *(const float4*)(g_y + (long)(m0 + row) * Y_STR + n);
                v.x = bv.x + yr.x; v.y = bv.y + yr.y; v.z = bv.z + yr.z; v.w = bv.w + yr.w;
            }
            *(float4*)(resT + row * LDC + c4) = v;
        }
        __syncthreads();

        wmma::fragment<wmma::accumulator, 16, 16, 16, float> acc[2][2];
#pragma unroll
        for (int i = 0; i < 2; i++)
#pragma unroll
            for (int j = 0; j < 2; j++)
                wmma::load_matrix_sync(acc[i][j], resT + (wm + i * 16) * LDC + wn + j * 16, LDC, wmma::mem_row_major);
#pragma unroll
        for (int k = 0; k < KPAD; k += 16) {
            wmma::fragment<wmma::matrix_a, 16, 16, 16, __half, wmma::row_major> af[2];
            wmma::fragment<wmma::matrix_b, 16, 16, 16, __half, wmma::col_major> bf[2];
#pragma unroll
            for (int i = 0; i < 2; i++)
                wmma::load_matrix_sync(af[i], As + (wm + i * 16) * LDA + k, LDA);
#pragma unroll
            for (int j = 0; j < 2; j++)
                wmma::load_matrix_sync(bf[j], Bs + (wn + j * 16) * LDA + k, LDA);
#pragma unroll
            for (int i = 0; i < 2; i++)
#pragma unroll
                for (int j = 0; j < 2; j++)
                    wmma::mma_sync(acc[i][j], af[i], bf[j], acc[i][j]);
        }
#pragma unroll
        for (int i = 0; i < 2; i++)
#pragma unroll
            for (int j = 0; j < 2; j++)
                wmma::store_matrix_sync(Cs + (wm + i * 16) * LDC + wn + j * 16,
                                        acc[i][j], LDC, wmma::mem_row_major);
        __syncthreads();

        for (int idx = tid; idx < 128 * 16; idx += 256) {
            int row = idx >> 4, c4 = (idx & 15) * 4;
            int n = n0 + c4;
            if (n + 4 <= CC) {
                float4 v = *(float4*)(Cs + row * LDC + c4);
                *(float4*)(out + (long)imgIdx[row] * CC + n) = v;
            }
        }
        __syncthreads();
    }
}

// ---------------- self attention: 4 x 32-key chunks, 4 CTAs/SM target ----------------
#define LQ 40
#define LS2 36   // chunked S stride (float); P half stride 72
#define LO 36
__global__ __launch_bounds__(256, 4) void self_attn_kernel() {
    int h = blockIdx.x, w = blockIdx.y;
    int tid = threadIdx.x, wid = tid >> 5, lane = tid & 31;
    extern __shared__ __align__(16) char smraw[];
    __half* Qs = (__half*)smraw;
    __half* Ks = Qs + 128 * LQ;
    __half* Vs = Ks + 128 * LQ;
    float* S = (float*)(Vs + 128 * LQ);      // [128][36]
    __half* P = (__half*)S;                  // alias, half stride 72
    float* rsum = (float*)(S + 128 * LS2);   // [128]

    const __half* base = g_qkvS_h + (long)w * NTOK * QKV_STR + h * HDIM;
    const float scl = ATT_SCALE;

    for (int idx = tid; idx < 3 * 128 * 15; idx += 256) {
        int region = idx / (128 * 15);
        int rem = idx - region * (128 * 15);
        int row = rem / 15, c = rem - row * 15;
        uint32_t v = *(const uint32_t*)(base + (long)row * QKV_STR + region * 180 + c * 2);
        __half* dst = (region == 0) ? Qs : (region == 1) ? Ks : Vs;
        if (region == 0) {
            float2 f = __half22float2(*(__half2*)&v);
            __half2 r = __floats2half2_rn(f.x * scl, f.y * scl);
            v = *(uint32_t*)&r;
        }
        *(uint32_t*)(dst + row * LQ + c * 2) = v;
    }
    if (tid < 128) {
        uint32_t z = 0;
        *(uint32_t*)(Qs + tid * LQ + 30) = z;
        *(uint32_t*)(Ks + tid * LQ + 30) = z;
        *(uint32_t*)(Vs + tid * LQ + 30) = z;
        rsum[tid] = 0.f;
    }
    __syncthreads();

    wmma::fragment<wmma::accumulator, 16, 16, 16, float> oacc[2];
    wmma::fill_fragment(oacc[0], 0.f);
    wmma::fill_fragment(oacc[1], 0.f);

    const __half* bbase = g_bias6_h + h * (NTOK * NTOK);
    const __half* mbase = g_mask_h + (long)w * (NTOK * NTOK);

#pragma unroll
    for (int kc = 0; kc < 4; kc++) {
        int k0 = kc * 32;

        // S panel = Q @ K[k0:k0+32]^T
        {
            wmma::fragment<wmma::accumulator, 16, 16, 16, float> acc[2];
            wmma::fill_fragment(acc[0], 0.f);
            wmma::fill_fragment(acc[1], 0.f);
#pragma unroll
            for (int k = 0; k < 2; k++) {
                wmma::fragment<wmma::matrix_a, 16, 16, 16, __half, wmma::row_major> af;
                wmma::load_matrix_sync(af, Qs + (wid * 16) * LQ + k * 16, LQ);
#pragma unroll
                for (int j = 0; j < 2; j++) {
                    wmma::fragment<wmma::matrix_b, 16, 16, 16, __half, wmma::col_major> bf;
                    wmma::load_matrix_sync(bf, Ks + (k0 + j * 16) * LQ + k * 16, LQ);
                    wmma::mma_sync(acc[j], af, bf, acc[j]);
                }
            }
#pragma unroll
            for (int j = 0; j < 2; j++)
                wmma::store_matrix_sync(S + (wid * 16) * LS2 + j * 16, acc[j], LS2, wmma::mem_row_major);
        }
        __syncthreads();

        // partial softmax: 16 rows/warp, 32 cols (1/lane)
        {
#pragma unroll
            for (int rr = 0; rr < 16; rr++) {
                int r = wid * 16 + rr;
                float s = S[r * LS2 + lane];
                float b = __half2float(bbase[r * NTOK + k0 + lane]);
                float m = __half2float(mbase[r * NTOK + k0 + lane]);
                float p = __expf(s + b + m);
                P[r * 72 + lane] = __float2half(p);
                float psum = p;
#pragma unroll
                for (int o = 16; o > 0; o >>= 1) psum += __shfl_xor_sync(0xffffffffu, psum, o);
                if (lane == 0) rsum[r] += psum;
            }
        }
        __syncthreads();

        // O += P_panel @ V[k0:k0+32]
        {
#pragma unroll
            for (int k = 0; k < 2; k++) {
                wmma::fragment<wmma::matrix_a, 16, 16, 16, __half, wmma::row_major> pf;
                wmma::load_matrix_sync(pf, P + (wid * 16) * 72 + k * 16, 72);
#pragma unroll
                for (int j = 0; j < 2; j++) {
                    wmma::fragment<wmma::matrix_b, 16, 16, 16, __half, wmma::row_major> vf;
                    wmma::load_matrix_sync(vf, Vs + (k0 + k * 16) * LQ + j * 16, LQ);
                    wmma::mma_sync(oacc[j], pf, vf, oacc[j]);
                }
            }
        }
        __syncthreads();
    }

    float* Of = S;
#pragma unroll
    for (int j = 0; j < 2; j++)
        wmma::store_matrix_sync(Of + (wid * 16) * LO + j * 16, oacc[j], LO, wmma::mem_row_major);
    __syncthreads();

    {
        int row = tid >> 1, part = tid & 1;
        float inv = 1.f / rsum[row];
        __half* orow = g_xo_h + (long)(w * NTOK + row) * C2 + CC + h * HDIM;
        int d0 = part * 15;
#pragma unroll
        for (int dd = 0; dd < 15; dd++)
            orow[d0 + dd] = __float2half(Of[row * LO + d0 + dd] * inv);
    }
}

// ---------------- mutual attention: 2 x 32-key chunks per group, 4 CTAs/SM target ----------------
__global__ __launch_bounds__(256, 4) void mut_attn_kernel() {
    int h = blockIdx.x, w = blockIdx.y;
    int tid = threadIdx.x, wid = tid >> 5, lane = tid & 31;
    extern __shared__ __align__(16) char smraw[];
    __half* Qs = (__half*)smraw;
    __half* Ks = Qs + 128 * LQ;
    __half* Vs = Ks + 128 * LQ;
    float* S = (float*)(Vs + 128 * LQ);      // [128][36]
    __half* P = (__half*)S;                  // alias, half stride 72
    float* rsum = (float*)(S + 128 * LS2);   // [128]

    const __half* base = g_qkvM_h + (long)w * NTOK * QKV_STR + h * HDIM;
    const float scl = ATT_SCALE;

    for (int idx = tid; idx < 3 * 128 * 15; idx += 256) {
        int region = idx / (128 * 15);
        int rem = idx - region * (128 * 15);
        int row = rem / 15, c = rem - row * 15;
        int srow = row;
        if (region == 0) srow = (row < 64) ? (64 + row) : (row - 64);
        uint32_t v = *(const uint32_t*)(base + (long)srow * QKV_STR + region * 180 + c * 2);
        __half* dst = (region == 0) ? Qs : (region == 1) ? Ks : Vs;
        if (region == 0) {
            float2 f = __half22float2(*(__half2*)&v);
            __half2 r = __floats2half2_rn(f.x * scl, f.y * scl);
            v = *(uint32_t*)&r;
        }
        *(uint32_t*)(dst + row * LQ + c * 2) = v;
    }
    if (tid < 128) {
        uint32_t z = 0;
        *(uint32_t*)(Qs + tid * LQ + 30) = z;
        *(uint32_t*)(Ks + tid * LQ + 30) = z;
        *(uint32_t*)(Vs + tid * LQ + 30) = z;
        rsum[tid] = 0.f;
    }
    __syncthreads();

    int g = wid >> 2, mt = wid & 3;

    wmma::fragment<wmma::accumulator, 16, 16, 16, float> oacc[2];
    wmma::fill_fragment(oacc[0], 0.f);
    wmma::fill_fragment(oacc[1], 0.f);

    const __half* mbase = g_mask_h + (long)w * (NTOK * NTOK);

#pragma unroll
    for (int kc = 0; kc < 2; kc++) {
        // S panel: warp (g, mt) rows g*64+mt*16 (16), group-local cols kc*32..+32
        {
            wmma::fragment<wmma::accumulator, 16, 16, 16, float> acc[2];
            wmma::fill_fragment(acc[0], 0.f);
            wmma::fill_fragment(acc[1], 0.f);
#pragma unroll
            for (int k = 0; k < 2; k++) {
                wmma::fragment<wmma::matrix_a, 16, 16, 16, __half, wmma::row_major> af;
                wmma::load_matrix_sync(af, Qs + (g * 64 + mt * 16) * LQ + k * 16, LQ);
#pragma unroll
                for (int j = 0; j < 2; j++) {
                    wmma::fragment<wmma::matrix_b, 16, 16, 16, __half, wmma::col_major> bf;
                    wmma::load_matrix_sync(bf, Ks + (g * 64 + kc * 32 + j * 16) * LQ + k * 16, LQ);
                    wmma::mma_sync(acc[j], af, bf, acc[j]);
                }
            }
#pragma unroll
            for (int j = 0; j < 2; j++)
                wmma::store_matrix_sync(S + (g * 64 + mt * 16) * LS2 + j * 16, acc[j], LS2, wmma::mem_row_major);
        }
        __syncthreads();

        // partial softmax: 16 rows/warp (global rows), 32 group-local cols
        {
#pragma unroll
            for (int rr = 0; rr < 16; rr++) {
                int r = wid * 16 + rr;
                int i = r & 63;
                float s = S[r * LS2 + lane];
                float m = __half2float(mbase[i * NTOK + kc * 32 + lane]);
                float p = __expf(s + m);
                P[r * 72 + lane] = __float2half(p);
                float psum = p;
#pragma unroll
                for (int o = 16; o > 0; o >>= 1) psum += __shfl_xor_sync(0xffffffffu, psum, o);
                if (lane == 0) rsum[r] += psum;
            }
        }
        __syncthreads();

        // O += P_panel @ V[group keys kc*32..]
        {
#pragma unroll
            for (int k = 0; k < 2; k++) {
                wmma::fragment<wmma::matrix_a, 16, 16, 16, __half, wmma::row_major> pf;
                wmma::load_matrix_sync(pf, P + (g * 64 + mt * 16) * 72 + k * 16, 72);
#pragma unroll
                for (int j = 0; j < 2; j++) {
                    wmma::fragment<wmma::matrix_b, 16, 16, 16, __half, wmma::row_major> vf;
                    wmma::load_matrix_sync(vf, Vs + (g * 64 + kc * 32 + k * 16) * LQ + j * 16, LQ);
                    wmma::mma_sync(oacc[j], pf, vf, oacc[j]);
                }
            }
        }
        __syncthreads();
    }

    float* Of = S;
#pragma unroll
    for (int j = 0; j < 2; j++)
        wmma::store_matrix_sync(Of + (g * 64 + mt * 16) * LO + j * 16, oacc[j], LO, wmma::mem_row_major);
    __syncthreads();

    {
        int row = tid >> 1, part = tid & 1;
        float inv = 1.f / rsum[row];
        __half* orow = g_xo_h + (long)(w * NTOK + row) * C2 + h * HDIM;
        int d0 = part * 15;
#pragma unroll
        for (int dd = 0; dd < 15; dd++)
            orow[d0 + dd] = __float2half(Of[row * LO + d0 + dd] * inv);
    }
}

// ---------------- launcher ----------------
extern "C" void kernel_launch(void* const* d_in, const int* in_sizes, int n_in,
                              void* d_out, int out_size) {
    const float* x     = (const float*)d_in[0];
    const float* mask  = (const float*)d_in[1];
    const float* g1    = (const float*)d_in[2];
    const float* b1    = (const float*)d_in[3];
    const float* g2    = (const float*)d_in[4];
    const float* b2    = (const float*)d_in[5];
    const float* wqs   = (const float*)d_in[6];
    const float* bqs   = (const float*)d_in[7];
    const float* wqm   = (const float*)d_in[8];
    const float* bqm   = (const float*)d_in[9];
    const float* rpb   = (const float*)d_in[10];
    const float* posb  = (const float*)d_in[11];
    const float* wproj = (const float*)d_in[12];
    const float* bproj = (const float*)d_in[13];
    const float* w11   = (const float*)d_in[14];
    const float* b11   = (const float*)d_in[15];
    const float* w12   = (const float*)d_in[16];
    const float* b12   = (const float*)d_in[17];
    const float* w2    = (const float*)d_in[18];
    const float* b2f   = (const float*)d_in[19];
    const int*   rpi   = (const int*)d_in[20];
    float* out = (float*)d_out;

    const int SMEM_QKV  = 128 * 200 * 2 + 2 * 64 * 200 * 2 + 2 * 16 * 68 * 4;     // 111104
    const int SMEM_PROJ = 128 * 392 * 2 + 64 * 392 * 2 + 128 * 68 * 4 + 128 * 4;  // 185856
    const int SMEM_MLP  = 128 * 200 * 2 + 64 * 200 * 2 + 2 * 128 * 72 * 2;        // 113664 -> 2 CTAs
    const int SMEM_FC2  = 128 * 392 * 2 + 64 * 392 * 2 + 2 * 128 * 68 * 4 + 128 * 4; // 220672
    const int SMEM_ATT  = 3 * 128 * LQ * 2 + 128 * LS2 * 4 + 128 * 4;             // 49664 -> 4 CTAs

    cudaFuncSetAttribute(&gemm_qkv<0, 0, 0>, cudaFuncAttributeMaxDynamicSharedMemorySize, SMEM_QKV);
    cudaFuncSetAttribute(&gemm_qkv<1, 1, 1>, cudaFuncAttributeMaxDynamicSharedMemorySize, SMEM_QKV);
    cudaFuncSetAttribute(gemm_proj, cudaFuncAttributeMaxDynamicSharedMemorySize, SMEM_PROJ);
    cudaFuncSetAttribute(gemm_mlp,  cudaFuncAttributeMaxDynamicSharedMemorySize, SMEM_MLP);
    cudaFuncSetAttribute(gemm_fc2,  cudaFuncAttributeMaxDynamicSharedMemorySize, SMEM_FC2);
    cudaFuncSetAttribute(self_attn_kernel, cudaFuncAttributeMaxDynamicSharedMemorySize, SMEM_ATT);
    cudaFuncSetAttribute(mut_attn_kernel,  cudaFuncAttributeMaxDynamicSharedMemorySize, SMEM_ATT);

    dim3 ga(NHD, NWIN);
    int prep_n = 2 * 576 * 192 + NHD * NTOK * NTOK + NWIN * NTOK * NTOK;
    prep_qkv_kernel<<<(prep_n + 255) / 256, 256>>>(wqs, wqm, rpb, rpi, mask);   // 0
    ln_kernel<0><<<(M_ROWS * 32) / 256, 256>>>(x, g1, b1);                      // 1
    gemm_qkv<0, 0, 0><<<768, 256, SMEM_QKV>>>(bqs, nullptr);                    // 2
    self_attn_kernel<<<ga, 256, SMEM_ATT>>>();                                  // 3 <- ncu slot
    prep_rest_kernel<<<(4 * 192 * 384 + 255) / 256, 256>>>(wproj, w11, w12, w2);// 4
    gemm_qkv<1, 1, 1><<<768, 256, SMEM_QKV>>>(bqm, posb);                       // 5
    mut_attn_kernel<<<ga, 256, SMEM_ATT>>>();                                   // 6
    gemm_proj<<<768, 256, SMEM_PROJ>>>(bproj, x);                               // 7
    ln_kernel<1><<<(M_ROWS * 32) / 256, 256>>>(nullptr, g2, b2);                // 8
    gemm_mlp<<<768, 256, SMEM_MLP>>>(b11, b12);                                 // 9
    gemm_fc2<<<768, 256, SMEM_FC2>>>(b2f, out);                                 // 10
}

// round 15
// speedup vs baseline: 1.3998x; 1.0085x over previous
#include <cuda_runtime.h>
#include <cuda_fp16.h>
#include <mma.h>
#include <cstdint>
#include <math_constants.h>
#include <math.h>

using namespace nvcuda;

// ---------------- problem constants ----------------
#define CC 180
#define NHD 6
#define HDIM 30
#define NWIN 768
#define NTOK 128
#define M_ROWS 98304
#define C3 540
#define C2 360
#define HID 360
#define QKV_STR 576
#define HID_STR 384
#define Y_STR 192
#define ATT_SCALE 0.18257418583505536f

// ---------------- scratch ----------------
__device__ __half g_xw_h[M_ROWS * CC];
__device__ __half g_qkvS_h[M_ROWS * QKV_STR];
__device__ __half g_qkvM_h[M_ROWS * QKV_STR];
__device__ __half g_xo_h[M_ROWS * C2];
__device__ float  g_y[M_ROWS * Y_STR];
__device__ __half g_h2_h[M_ROWS * CC];
__device__ __half g_hid1_h[M_ROWS * HID_STR];
__device__ __half g_bias6_h[NHD * NTOK * NTOK];
__device__ __half g_mask_h[NWIN * NTOK * NTOK];
__device__ __half g_wT_qs[576 * 192];
__device__ __half g_wT_qm[576 * 192];
__device__ __half g_wT_pr[192 * 384];
__device__ __half g_wT_f11[384 * 192];
__device__ __half g_wT_f12[384 * 192];
__device__ __half g_wT_f2[192 * 384];

__device__ __forceinline__ int row_to_img(int r) {
    int win = r >> 7, n = r & 127;
    int dwin = win >> 8, rem = win & 255;
    int hwin = rem >> 4, wwin = rem & 15;
    int nd = n >> 6, nh = (n >> 3) & 7, nw = n & 7;
    int sd = dwin * 2 + nd + 1; if (sd >= 6) sd -= 6;
    int sh = (hwin * 8 + nh + 4) & 127;
    int sw = (wwin * 8 + nw + 4) & 127;
    return (sd * 128 + sh) * 128 + sw;
}

// ---------------- prep kernels ----------------
__device__ __forceinline__ void prep_one(const float* w, __half* wt, int idx,
                                         int K, int N, int Kpad, int Npad) {
    int n = idx / Kpad, k = idx % Kpad;
    wt[idx] = (n < N && k < K) ? __float2half(w[(long)k * N + n]) : __float2half(0.f);
}
__global__ void prep_qkv_kernel(const float* __restrict__ wqs, const float* __restrict__ wqm,
                                const float* __restrict__ rpb, const int* __restrict__ rpi,
                                const float* __restrict__ mask) {
    int idx = blockIdx.x * blockDim.x + threadIdx.x;
    const int S1 = 576 * 192;
    if (idx < S1) { prep_one(wqs, g_wT_qs, idx, CC, C3, 192, 576); return; }
    idx -= S1;
    if (idx < S1) { prep_one(wqm, g_wT_qm, idx, CC, C3, 192, 576); return; }
    idx -= S1;
    if (idx < NHD * NTOK * NTOK) {
        int h = idx / (NTOK * NTOK), ij = idx % (NTOK * NTOK);
        g_bias6_h[idx] = __float2half(rpb[rpi[ij] * NHD + h]);
        return;
    }
    idx -= NHD * NTOK * NTOK;
    if (idx < NWIN * NTOK * NTOK)
        g_mask_h[idx] = __float2half(mask[idx]);
}
__global__ void prep_rest_kernel(const float* __restrict__ wproj, const float* __restrict__ w11,
                                 const float* __restrict__ w12, const float* __restrict__ w2) {
    int idx = blockIdx.x * blockDim.x + threadIdx.x;
    const int S = 192 * 384;
    if (idx < S) prep_one(wproj, g_wT_pr, idx, C2, CC, 384, 192);
    else if (idx < 2 * S) prep_one(w11, g_wT_f11, idx - S, CC, HID, 192, 384);
    else if (idx < 3 * S) prep_one(w12, g_wT_f12, idx - 2 * S, CC, HID, 192, 384);
    else if (idx < 4 * S) prep_one(w2, g_wT_f2, idx - 3 * S, HID, CC, 384, 192);
}

// ---------------- LayerNorm ----------------
template <int MODE>
__global__ __launch_bounds__(256) void ln_kernel(const float* __restrict__ in,
                                                 const float* __restrict__ gg,
                                                 const float* __restrict__ bb) {
    int gw = (blockIdx.x * blockDim.x + threadIdx.x) >> 5;
    int lane = threadIdx.x & 31;
    if (gw >= M_ROWS) return;
    const float* rowp;
    __half* orow;
    if (MODE == 0) {
        rowp = in + (long)row_to_img(gw) * CC;
        orow = g_xw_h + (long)gw * CC;
    } else {
        rowp = g_y + (long)gw * Y_STR;
        orow = g_h2_h + (long)gw * CC;
    }
    float vals[6];
    float s = 0.f, ss = 0.f;
    int cnt = 0;
    for (int c = lane; c < CC; c += 32) { float v = rowp[c]; vals[cnt++] = v; s += v; ss += v * v; }
#pragma unroll
    for (int o = 16; o > 0; o >>= 1) {
        s  += __shfl_xor_sync(0xffffffffu, s, o);
        ss += __shfl_xor_sync(0xffffffffu, ss, o);
    }
    float mean = s * (1.f / CC);
    float var = ss * (1.f / CC) - mean * mean;
    float rstd = rsqrtf(var + 1e-5f);
    cnt = 0;
    for (int c = lane; c < CC; c += 32)
        orow[c] = __float2half((vals[cnt++] - mean) * rstd * gg[c] + bb[c]);
}

// ---------------- qkv GEMM (unchanged) ----------------
template <int WID, int ADD_PB, int DSTID>
__global__ __launch_bounds__(256) void gemm_qkv(const float* __restrict__ bias,
                                                const float* __restrict__ pb) {
    constexpr int KPAD = 192, LDA = 200, LDC = 68, NTILES = 9;
    const __half* A = g_xw_h;
    const __half* BT = (WID == 0) ? g_wT_qs : g_wT_qm;
    __half* Cout = (DSTID == 0) ? g_qkvS_h : g_qkvM_h;
    extern __shared__ __align__(16) char smem[];
    __half* As = (__half*)smem;
    __half* Bs0 = As + 128 * LDA;
    __half* Bs1 = Bs0 + 64 * LDA;
    float* bias0 = (float*)(Bs1 + 64 * LDA);
    float* bias1 = bias0 + 16 * LDC;

    int tid = threadIdx.x, wid = tid >> 5;
    int m0 = blockIdx.x * 128;
    int wm = (wid & 3) * 32, wn = (wid >> 2) * 32;

    constexpr int KF4 = KPAD / 4;
    constexpr int KR4 = CC / 4;
    for (int idx = tid; idx < 128 * KF4; idx += 256) {
        int row = idx / KF4, c4 = idx % KF4;
        uint2 val = make_uint2(0u, 0u);
        if (c4 < KR4) {
            val = *(const uint2*)(A + (long)(m0 + row) * CC + c4 * 4);
            if (ADD_PB) {
                __half2 h0 = *(__half2*)&val.x, h1 = *(__half2*)&val.y;
                float4 p = *(const float4*)(pb + ((m0 + row) & 63) * CC + c4 * 4);
                float2 f0 = __half22float2(h0), f1 = __half22float2(h1);
                __half2 r0 = __floats2half2_rn(f0.x + p.x, f0.y + p.y);
                __half2 r1 = __floats2half2_rn(f1.x + p.z, f1.y + p.w);
                val.x = *(uint32_t*)&r0; val.y = *(uint32_t*)&r1;
            }
        }
        *(uint2*)(As + row * LDA + c4 * 4) = val;
    }

    constexpr int BU4 = KPAD / 8;
    constexpr int NB = (64 * BU4) / 256;
    for (int i = 0; i < NB; i++) {
        int idx = tid + i * 256;
        int n = idx / BU4, c = idx % BU4;
        *(uint4*)(Bs0 + n * LDA + c * 8) = *(const uint4*)(BT + (long)n * KPAD + c * 8);
    }
    for (int i = 0; i < 4; i++) {
        int idx = tid + i * 256;
        int row = idx >> 6, c = idx & 63;
        bias0[row * LDC + c] = bias[c];
    }
    __syncthreads();

    for (int t = 0; t < NTILES; t++) {
        __half* Bcur = (t & 1) ? Bs1 : Bs0;
        __half* Bnxt = (t & 1) ? Bs0 : Bs1;
        float* bcur = (t & 1) ? bias1 : bias0;
        float* bnxt = (t & 1) ? bias0 : bias1;
        int n0 = t * 64;
        bool has_next = (t + 1 < NTILES);

        uint4 breg[NB];
        float creg[4];
        if (has_next) {
            int n0n = n0 + 64;
#pragma unroll
            for (int i = 0; i < NB; i++) {
                int idx = tid + i * 256;
                int n = idx / BU4, c = idx % BU4;
                breg[i] = *(const uint4*)(BT + (long)(n0n + n) * KPAD + c * 8);
            }
#pragma unroll
            for (int i = 0; i < 4; i++) {
                int idx = tid + i * 256;
                int c = idx & 63;
                creg[i] = (n0n + c < C3) ? bias[n0n + c] : 0.f;
            }
        }

        wmma::fragment<wmma::accumulator, 16, 16, 16, float> acc[2][2];
#pragma unroll
        for (int i = 0; i < 2; i++)
#pragma unroll
            for (int j = 0; j < 2; j++)
                wmma::load_matrix_sync(acc[i][j], bcur + wn + j * 16, LDC, wmma::mem_row_major);
#pragma unroll
        for (int k = 0; k < KPAD; k += 16) {
            wmma::fragment<wmma::matrix_a, 16, 16, 16, __half, wmma::row_major> af[2];
            wmma::fragment<wmma::matrix_b, 16, 16, 16, __half, wmma::col_major> bf[2];
#pragma unroll
            for (int i = 0; i < 2; i++)
                wmma::load_matrix_sync(af[i], As + (wm + i * 16) * LDA + k, LDA);
#pragma unroll
            for (int j = 0; j < 2; j++)
                wmma::load_matrix_sync(bf[j], Bcur + (wn + j * 16) * LDA + k, LDA);
#pragma unroll
            for (int i = 0; i < 2; i++)
#pragma unroll
                for (int j = 0; j < 2; j++)
                    wmma::mma_sync(acc[i][j], af[i], bf[j], acc[i][j]);
        }
#pragma unroll
        for (int i = 0; i < 2; i++)
#pragma unroll
            for (int j = 0; j < 2; j++) {
                wmma::fragment<wmma::accumulator, 16, 16, 16, __half> hacc;
#pragma unroll
                for (int e = 0; e < hacc.num_elements; e++)
                    hacc.x[e] = __float2half(acc[i][j].x[e]);
                wmma::store_matrix_sync(Cout + (long)(m0 + wm + i * 16) * QKV_STR + n0 + wn + j * 16,
                                        hacc, QKV_STR, wmma::mem_row_major);
            }
        if (has_next) {
#pragma unroll
            for (int i = 0; i < NB; i++) {
                int idx = tid + i * 256;
                int n = idx / BU4, c = idx % BU4;
                *(uint4*)(Bnxt + n * LDA + c * 8) = breg[i];
            }
#pragma unroll
            for (int i = 0; i < 4; i++) {
                int idx = tid + i * 256;
                int row = idx >> 6, c = idx & 63;
                bnxt[row * LDC + c] = creg[i];
            }
        }
        __syncthreads();
    }
}

// ---------------- proj GEMM (unchanged) ----------------
__global__ __launch_bounds__(256) void gemm_proj(const float* __restrict__ bias,
                                                 const float* __restrict__ x) {
    constexpr int KPAD = 384, LDA = 392, LDC = 68, NTILES = 3;
    extern __shared__ __align__(16) char smem[];
    __half* As = (__half*)smem;
    __half* Bs = As + 128 * LDA;
    float* resT = (float*)(Bs + 64 * LDA);
    int* imgIdx = (int*)(resT + 128 * LDC);

    int tid = threadIdx.x, wid = tid >> 5;
    int m0 = blockIdx.x * 128;
    int wm = (wid & 3) * 32, wn = (wid >> 2) * 32;

    if (tid < 128) imgIdx[tid] = row_to_img(m0 + tid);

    constexpr int KF4 = KPAD / 4;
    constexpr int KR4 = C2 / 4;
    for (int idx = tid; idx < 128 * KF4; idx += 256) {
        int row = idx / KF4, c4 = idx % KF4;
        uint2 val = make_uint2(0u, 0u);
        if (c4 < KR4)
            val = *(const uint2*)(g_xo_h + (long)(m0 + row) * C2 + c4 * 4);
        *(uint2*)(As + row * LDA + c4 * 4) = val;
    }

    constexpr int BU4 = KPAD / 8;
    for (int t = 0; t < NTILES; t++) {
        int n0 = t * 64;
        for (int idx = tid; idx < 64 * BU4; idx += 256) {
            int n = idx / BU4, c = idx % BU4;
            *(uint4*)(Bs + n * LDA + c * 8) = *(const uint4*)(g_wT_pr + (long)(n0 + n) * KPAD + c * 8);
        }
        for (int idx = tid; idx < 128 * 16; idx += 256) {
            int row = idx >> 4, c4 = (idx & 15) * 4;
            int n = n0 + c4;
            float4 v = make_float4(0.f, 0.f, 0.f, 0.f);
            if (n + 4 <= CC) {
                const float4 bv = *(const float4*)(bias + n);
                const float4 xr = *(const float4*)(x + (long)imgIdx[row] * CC + n);
                v.x = bv.x + xr.x; v.y = bv.y + xr.y; v.z = bv.z + xr.z; v.w = bv.w + xr.w;
            }
            *(float4*)(resT + row * LDC + c4) = v;
        }
        __syncthreads();

        wmma::fragment<wmma::accumulator, 16, 16, 16, float> acc[2][2];
#pragma unroll
        for (int i = 0; i < 2; i++)
#pragma unroll
            for (int j = 0; j < 2; j++)
                wmma::load_matrix_sync(acc[i][j], resT + (wm + i * 16) * LDC + wn + j * 16, LDC, wmma::mem_row_major);
#pragma unroll
        for (int k = 0; k < KPAD; k += 16) {
            wmma::fragment<wmma::matrix_a, 16, 16, 16, __half, wmma::row_major> af[2];
            wmma::fragment<wmma::matrix_b, 16, 16, 16, __half, wmma::col_major> bf[2];
#pragma unroll
            for (int i = 0; i < 2; i++)
                wmma::load_matrix_sync(af[i], As + (wm + i * 16) * LDA + k, LDA);
#pragma unroll
            for (int j = 0; j < 2; j++)
                wmma::load_matrix_sync(bf[j], Bs + (wn + j * 16) * LDA + k, LDA);
#pragma unroll
            for (int i = 0; i < 2; i++)
#pragma unroll
                for (int j = 0; j < 2; j++)
                    wmma::mma_sync(acc[i][j], af[i], bf[j], acc[i][j]);
        }
#pragma unroll
        for (int i = 0; i < 2; i++)
#pragma unroll
            for (int j = 0; j < 2; j++)
                wmma::store_matrix_sync(g_y + (long)(m0 + wm + i * 16) * Y_STR + n0 + wn + j * 16,
                                        acc[i][j], Y_STR, wmma::mem_row_major);
        __syncthreads();
    }
}

// ---------------- fused MLP GEMM (unchanged from R14) ----------------
__global__ __launch_bounds__(256, 2) void gemm_mlp(const float* __restrict__ bias1,
                                                   const float* __restrict__ bias2) {
    constexpr int KPAD = 192, LDA = 200, LDCH = 72, NTILES = 6;
    extern __shared__ __align__(16) char smem[];
    __half* As = (__half*)smem;
    __half* Bs = As + 128 * LDA;
    __half* Cs = Bs + 64 * LDA;
    __half* Cs2 = Cs + 128 * LDCH;

    int tid = threadIdx.x, wid = tid >> 5;
    int m0 = blockIdx.x * 128;
    int wm = (wid & 3) * 32, wn = (wid >> 2) * 32;

    constexpr int KF4 = KPAD / 4;
    constexpr int KR4 = CC / 4;
    for (int idx = tid; idx < 128 * KF4; idx += 256) {
        int row = idx / KF4, c4 = idx % KF4;
        uint2 val = make_uint2(0u, 0u);
        if (c4 < KR4)
            val = *(const uint2*)(g_h2_h + (long)(m0 + row) * CC + c4 * 4);
        *(uint2*)(As + row * LDA + c4 * 4) = val;
    }

    constexpr int BU4 = KPAD / 8;
    for (int t = 0; t < NTILES; t++) {
        int n0 = t * 64;
#pragma unroll
        for (int pass = 0; pass < 2; pass++) {
            const __half* Bp = (pass == 0) ? g_wT_f11 : g_wT_f12;
            __half* Cdst = (pass == 0) ? Cs : Cs2;
            for (int idx = tid; idx < 64 * BU4; idx += 256) {
                int n = idx / BU4, c = idx % BU4;
                *(uint4*)(Bs + n * LDA + c * 8) = *(const uint4*)(Bp + (long)(n0 + n) * KPAD + c * 8);
            }
            __syncthreads();
            wmma::fragment<wmma::accumulator, 16, 16, 16, float> acc[2][2];
#pragma unroll
            for (int i = 0; i < 2; i++)
#pragma unroll
                for (int j = 0; j < 2; j++) wmma::fill_fragment(acc[i][j], 0.f);
#pragma unroll
            for (int k = 0; k < KPAD; k += 16) {
                wmma::fragment<wmma::matrix_a, 16, 16, 16, __half, wmma::row_major> af[2];
                wmma::fragment<wmma::matrix_b, 16, 16, 16, __half, wmma::col_major> bf[2];
#pragma unroll
                for (int i = 0; i < 2; i++)
                    wmma::load_matrix_sync(af[i], As + (wm + i * 16) * LDA + k, LDA);
#pragma unroll
                for (int j = 0; j < 2; j++)
                    wmma::load_matrix_sync(bf[j], Bs + (wn + j * 16) * LDA + k, LDA);
#pragma unroll
                for (int i = 0; i < 2; i++)
#pragma unroll
                    for (int j = 0; j < 2; j++)
                        wmma::mma_sync(acc[i][j], af[i], bf[j], acc[i][j]);
            }
#pragma unroll
            for (int i = 0; i < 2; i++)
#pragma unroll
                for (int j = 0; j < 2; j++) {
                    wmma::fragment<wmma::accumulator, 16, 16, 16, __half> hacc;
#pragma unroll
                    for (int e = 0; e < hacc.num_elements; e++)
                        hacc.x[e] = __float2half(acc[i][j].x[e]);
                    wmma::store_matrix_sync(Cdst + (wm + i * 16) * LDCH + wn + j * 16,
                                            hacc, LDCH, wmma::mem_row_major);
                }
            __syncthreads();
        }
        for (int idx = tid; idx < 128 * 16; idx += 256) {
            int row = idx >> 4, c4 = (idx & 15) * 4;
            int n = n0 + c4;
            uint2 u1 = *(uint2*)(Cs + row * LDCH + c4);
            uint2 u2 = *(uint2*)(Cs2 + row * LDCH + c4);
            float2 a0 = __half22float2(*(__half2*)&u1.x), a1 = __half22float2(*(__half2*)&u1.y);
            float2 g0 = __half22float2(*(__half2*)&u2.x), g1v = __half22float2(*(__half2*)&u2.y);
            float b1v[4], b2v[4];
#pragma unroll
            for (int e = 0; e < 4; e++) {
                b1v[e] = (n + e < HID) ? bias1[n + e] : 0.f;
                b2v[e] = (n + e < HID) ? bias2[n + e] : 0.f;
            }
            float v[4] = {a0.x + b1v[0], a0.y + b1v[1], a1.x + b1v[2], a1.y + b1v[3]};
            float v2[4] = {g0.x + b2v[0], g0.y + b2v[1], g1v.x + b2v[2], g1v.y + b2v[3]};
            float o[4];
#pragma unroll
            for (int e = 0; e < 4; e++)
                o[e] = 0.5f * v[e] * (1.f + erff(v[e] * 0.70710678f)) * v2[e];
            __half2 ha = __floats2half2_rn(o[0], o[1]);
            __half2 hb = __floats2half2_rn(o[2], o[3]);
            *(uint2*)(g_hid1_h + (long)(m0 + row) * HID_STR + n0 + c4) =
                make_uint2(*(uint32_t*)&ha, *(uint32_t*)&hb);
        }
        __syncthreads();
    }
}

// ---------------- fc2 GEMM (unchanged) ----------------
__global__ __launch_bounds__(256) void gemm_fc2(const float* __restrict__ bias,
                                                float* __restrict__ out) {
    constexpr int KPAD = 384, LDA = 392, LDC = 68, NTILES = 3;
    extern __shared__ __align__(16) char smem[];
    __half* As = (__half*)smem;
    __half* Bs = As + 128 * LDA;
    float* resT = (float*)(Bs + 64 * LDA);
    float* Cs = resT + 128 * LDC;
    int* imgIdx = (int*)(Cs + 128 * LDC);

    int tid = threadIdx.x, wid = tid >> 5;
    int m0 = blockIdx.x * 128;
    int wm = (wid & 3) * 32, wn = (wid >> 2) * 32;

    if (tid < 128) imgIdx[tid] = row_to_img(m0 + tid);

    constexpr int KF4 = KPAD / 4;
    for (int idx = tid; idx < 128 * KF4; idx += 256) {
        int row = idx / KF4, c4 = idx % KF4;
        *(uint2*)(As + row * LDA + c4 * 4) =
            *(const uint2*)(g_hid1_h + (long)(m0 + row) * HID_STR + c4 * 4);
    }

    constexpr int BU4 = KPAD / 8;
    for (int t = 0; t < NTILES; t++) {
        int n0 = t * 64;
        for (int idx = tid; idx < 64 * BU4; idx += 256) {
            int n = idx / BU4, c = idx % BU4;
            *(uint4*)(Bs + n * LDA + c * 8) = *(const uint4*)(g_wT_f2 + (long)(n0 + n) * KPAD + c * 8);
        }
        for (int idx = tid; idx < 128 * 16; idx += 256) {
            int row = idx >> 4, c4 = (idx & 15) * 4;
            int n = n0 + c4;
            float4 v = make_float4(0.f, 0.f, 0.f, 0.f);
            if (n + 4 <= CC) {
                const float4 bv = *(const float4*)(bias + n);
                const float4 yr = *(const float4*)(g_y + (long)(m0 + row) * Y_STR + n);
                v.x = bv.x + yr.x; v.y = bv.y + yr.y; v.z = bv.z + yr.z; v.w = bv.w + yr.w;
            }
            *(float4*)(resT + row * LDC + c4) = v;
        }
        __syncthreads();

        wmma::fragment<wmma::accumulator, 16, 16, 16, float> acc[2][2];
#pragma unroll
        for (int i = 0; i < 2; i++)
#pragma unroll
            for (int j = 0; j < 2; j++)
                wmma::load_matrix_sync(acc[i][j], resT + (wm + i * 16) * LDC + wn + j * 16, LDC, wmma::mem_row_major);
#pragma unroll
        for (int k = 0; k < KPAD; k += 16) {
            wmma::fragment<wmma::matrix_a, 16, 16, 16, __half, wmma::row_major> af[2];
            wmma::fragment<wmma::matrix_b, 16, 16, 16, __half, wmma::col_major> bf[2];
#pragma unroll
            for (int i = 0; i < 2; i++)
                wmma::load_matrix_sync(af[i], As + (wm + i * 16) * LDA + k, LDA);
#pragma unroll
            for (int j = 0; j < 2; j++)
                wmma::load_matrix_sync(bf[j], Bs + (wn + j * 16) * LDA + k, LDA);
#pragma unroll
            for (int i = 0; i < 2; i++)
#pragma unroll
                for (int j = 0; j < 2; j++)
                    wmma::mma_sync(acc[i][j], af[i], bf[j], acc[i][j]);
        }
#pragma unroll
        for (int i = 0; i < 2; i++)
#pragma unroll
            for (int j = 0; j < 2; j++)
                wmma::store_matrix_sync(Cs + (wm + i * 16) * LDC + wn + j * 16,
                                        acc[i][j], LDC, wmma::mem_row_major);
        __syncthreads();

        for (int idx = tid; idx < 128 * 16; idx += 256) {
            int row = idx >> 4, c4 = (idx & 15) * 4;
            int n = n0 + c4;
            if (n + 4 <= CC) {
                float4 v = *(float4*)(Cs + row * LDC + c4);
                *(float4*)(out + (long)imgIdx[row] * CC + n) = v;
            }
        }
        __syncthreads();
    }
}

// ---------------- self attention: 4 x 32-key chunks, warp-private phases (__syncwarp) ----------------
#define LQ 40
#define LS2 36
#define LO 36
__global__ __launch_bounds__(256, 4) void self_attn_kernel() {
    int h = blockIdx.x, w = blockIdx.y;
    int tid = threadIdx.x, wid = tid >> 5, lane = tid & 31;
    extern __shared__ __align__(16) char smraw[];
    __half* Qs = (__half*)smraw;
    __half* Ks = Qs + 128 * LQ;
    __half* Vs = Ks + 128 * LQ;
    float* S = (float*)(Vs + 128 * LQ);      // [128][36]
    __half* P = (__half*)S;                  // alias, half stride 72
    float* rsum = (float*)(S + 128 * LS2);   // [128]

    const __half* base = g_qkvS_h + (long)w * NTOK * QKV_STR + h * HDIM;
    const float scl = ATT_SCALE;

    for (int idx = tid; idx < 3 * 128 * 15; idx += 256) {
        int region = idx / (128 * 15);
        int rem = idx - region * (128 * 15);
        int row = rem / 15, c = rem - row * 15;
        uint32_t v = *(const uint32_t*)(base + (long)row * QKV_STR + region * 180 + c * 2);
        __half* dst = (region == 0) ? Qs : (region == 1) ? Ks : Vs;
        if (region == 0) {
            float2 f = __half22float2(*(__half2*)&v);
            __half2 r = __floats2half2_rn(f.x * scl, f.y * scl);
            v = *(uint32_t*)&r;
        }
        *(uint32_t*)(dst + row * LQ + c * 2) = v;
    }
    if (tid < 128) {
        uint32_t z = 0;
        *(uint32_t*)(Qs + tid * LQ + 30) = z;
        *(uint32_t*)(Ks + tid * LQ + 30) = z;
        *(uint32_t*)(Vs + tid * LQ + 30) = z;
        rsum[tid] = 0.f;
    }
    __syncthreads();

    wmma::fragment<wmma::accumulator, 16, 16, 16, float> oacc[2];
    wmma::fill_fragment(oacc[0], 0.f);
    wmma::fill_fragment(oacc[1], 0.f);

    const __half* bbase = g_bias6_h + h * (NTOK * NTOK);
    const __half* mbase = g_mask_h + (long)w * (NTOK * NTOK);

#pragma unroll
    for (int kc = 0; kc < 4; kc++) {
        int k0 = kc * 32;

        // S panel = Q @ K[k0:k0+32]^T (warp-private rows wid*16)
        {
            wmma::fragment<wmma::accumulator, 16, 16, 16, float> acc[2];
            wmma::fill_fragment(acc[0], 0.f);
            wmma::fill_fragment(acc[1], 0.f);
#pragma unroll
            for (int k = 0; k < 2; k++) {
                wmma::fragment<wmma::matrix_a, 16, 16, 16, __half, wmma::row_major> af;
                wmma::load_matrix_sync(af, Qs + (wid * 16) * LQ + k * 16, LQ);
#pragma unroll
                for (int j = 0; j < 2; j++) {
                    wmma::fragment<wmma::matrix_b, 16, 16, 16, __half, wmma::col_major> bf;
                    wmma::load_matrix_sync(bf, Ks + (k0 + j * 16) * LQ + k * 16, LQ);
                    wmma::mma_sync(acc[j], af, bf, acc[j]);
                }
            }
#pragma unroll
            for (int j = 0; j < 2; j++)
                wmma::store_matrix_sync(S + (wid * 16) * LS2 + j * 16, acc[j], LS2, wmma::mem_row_major);
        }
        __syncwarp();

        // partial softmax: warp-private rows
        {
#pragma unroll
            for (int rr = 0; rr < 16; rr++) {
                int r = wid * 16 + rr;
                float s = S[r * LS2 + lane];
                float b = __half2float(bbase[r * NTOK + k0 + lane]);
                float m = __half2float(mbase[r * NTOK + k0 + lane]);
                float p = __expf(s + b + m);
                P[r * 72 + lane] = __float2half(p);
                float psum = p;
#pragma unroll
                for (int o = 16; o > 0; o >>= 1) psum += __shfl_xor_sync(0xffffffffu, psum, o);
                if (lane == 0) rsum[r] += psum;
            }
        }
        __syncwarp();

        // O += P_panel @ V[k0:k0+32] (warp-private P rows; Vs read-only)
        {
#pragma unroll
            for (int k = 0; k < 2; k++) {
                wmma::fragment<wmma::matrix_a, 16, 16, 16, __half, wmma::row_major> pf;
                wmma::load_matrix_sync(pf, P + (wid * 16) * 72 + k * 16, 72);
#pragma unroll
                for (int j = 0; j < 2; j++) {
                    wmma::fragment<wmma::matrix_b, 16, 16, 16, __half, wmma::row_major> vf;
                    wmma::load_matrix_sync(vf, Vs + (k0 + k * 16) * LQ + j * 16, LQ);
                    wmma::mma_sync(oacc[j], pf, vf, oacc[j]);
                }
            }
        }
        __syncwarp();
    }

    float* Of = S;
#pragma unroll
    for (int j = 0; j < 2; j++)
        wmma::store_matrix_sync(Of + (wid * 16) * LO + j * 16, oacc[j], LO, wmma::mem_row_major);
    __syncthreads();

    {
        int row = tid >> 1, part = tid & 1;
        float inv = 1.f / rsum[row];
        __half* orow = g_xo_h + (long)(w * NTOK + row) * C2 + CC + h * HDIM;
        int d0 = part * 15;
#pragma unroll
        for (int dd = 0; dd < 15; dd++)
            orow[d0 + dd] = __float2half(Of[row * LO + d0 + dd] * inv);
    }
}

// ---------------- mutual attention: 2 x 32-key chunks, warp-private phases ----------------
__global__ __launch_bounds__(256, 4) void mut_attn_kernel() {
    int h = blockIdx.x, w = blockIdx.y;
    int tid = threadIdx.x, wid = tid >> 5, lane = tid & 31;
    extern __shared__ __align__(16) char smraw[];
    __half* Qs = (__half*)smraw;
    __half* Ks = Qs + 128 * LQ;
    __half* Vs = Ks + 128 * LQ;
    float* S = (float*)(Vs + 128 * LQ);
    __half* P = (__half*)S;
    float* rsum = (float*)(S + 128 * LS2);

    const __half* base = g_qkvM_h + (long)w * NTOK * QKV_STR + h * HDIM;
    const float scl = ATT_SCALE;

    for (int idx = tid; idx < 3 * 128 * 15; idx += 256) {
        int region = idx / (128 * 15);
        int rem = idx - region * (128 * 15);
        int row = rem / 15, c = rem - row * 15;
        int srow = row;
        if (region == 0) srow = (row < 64) ? (64 + row) : (row - 64);
        uint32_t v = *(const uint32_t*)(base + (long)srow * QKV_STR + region * 180 + c * 2);
        __half* dst = (region == 0) ? Qs : (region == 1) ? Ks : Vs;
        if (region == 0) {
            float2 f = __half22float2(*(__half2*)&v);
            __half2 r = __floats2half2_rn(f.x * scl, f.y * scl);
            v = *(uint32_t*)&r;
        }
        *(uint32_t*)(dst + row * LQ + c * 2) = v;
    }
    if (tid < 128) {
        uint32_t z = 0;
        *(uint32_t*)(Qs + tid * LQ + 30) = z;
        *(uint32_t*)(Ks + tid * LQ + 30) = z;
        *(uint32_t*)(Vs + tid * LQ + 30) = z;
        rsum[tid] = 0.f;
    }
    __syncthreads();

    int g = wid >> 2, mt = wid & 3;

    wmma::fragment<wmma::accumulator, 16, 16, 16, float> oacc[2];
    wmma::fill_fragment(oacc[0], 0.f);
    wmma::fill_fragment(oacc[1], 0.f);

    const __half* mbase = g_mask_h + (long)w * (NTOK * NTOK);

#pragma unroll
    for (int kc = 0; kc < 2; kc++) {
        // rows g*64+mt*16 == wid*16 (warp-private)
        {
            wmma::fragment<wmma::accumulator, 16, 16, 16, float> acc[2];
            wmma::fill_fragment(acc[0], 0.f);
            wmma::fill_fragment(acc[1], 0.f);
#pragma unroll
            for (int k = 0; k < 2; k++) {
                wmma::fragment<wmma::matrix_a, 16, 16, 16, __half, wmma::row_major> af;
                wmma::load_matrix_sync(af, Qs + (g * 64 + mt * 16) * LQ + k * 16, LQ);
#pragma unroll
                for (int j = 0; j < 2; j++) {
                    wmma::fragment<wmma::matrix_b, 16, 16, 16, __half, wmma::col_major> bf;
                    wmma::load_matrix_sync(bf, Ks + (g * 64 + kc * 32 + j * 16) * LQ + k * 16, LQ);
                    wmma::mma_sync(acc[j], af, bf, acc[j]);
                }
            }
#pragma unroll
            for (int j = 0; j < 2; j++)
                wmma::store_matrix_sync(S + (g * 64 + mt * 16) * LS2 + j * 16, acc[j], LS2, wmma::mem_row_major);
        }
        __syncwarp();

        {
#pragma unroll
            for (int rr = 0; rr < 16; rr++) {
                int r = wid * 16 + rr;
                int i = r & 63;
                float s = S[r * LS2 + lane];
                float m = __half2float(mbase[i * NTOK + kc * 32 + lane]);
                float p = __expf(s + m);
                P[r * 72 + lane] = __float2half(p);
                float psum = p;
#pragma unroll
                for (int o = 16; o > 0; o >>= 1) psum += __shfl_xor_sync(0xffffffffu, psum, o);
                if (lane == 0) rsum[r] += psum;
            }
        }
        __syncwarp();

        {
#pragma unroll
            for (int k = 0; k < 2; k++) {
                wmma::fragment<wmma::matrix_a, 16, 16, 16, __half, wmma::row_major> pf;
                wmma::load_matrix_sync(pf, P + (g * 64 + mt * 16) * 72 + k * 16, 72);
#pragma unroll
                for (int j = 0; j < 2; j++) {
                    wmma::fragment<wmma::matrix_b, 16, 16, 16, __half, wmma::row_major> vf;
                    wmma::load_matrix_sync(vf, Vs + (g * 64 + kc * 32 + k * 16) * LQ + j * 16, LQ);
                    wmma::mma_sync(oacc[j], pf, vf, oacc[j]);
                }
            }
        }
        __syncwarp();
    }

    float* Of = S;
#pragma unroll
    for (int j = 0; j < 2; j++)
        wmma::store_matrix_sync(Of + (g * 64 + mt * 16) * LO + j * 16, oacc[j], LO, wmma::mem_row_major);
    __syncthreads();

    {
        int row = tid >> 1, part = tid & 1;
        float inv = 1.f / rsum[row];
        __half* orow = g_xo_h + (long)(w * NTOK + row) * C2 + h * HDIM;
        int d0 = part * 15;
#pragma unroll
        for (int dd = 0; dd < 15; dd++)
            orow[d0 + dd] = __float2half(Of[row * LO + d0 + dd] * inv);
    }
}

// ---------------- launcher ----------------
extern "C" void kernel_launch(void* const* d_in, const int* in_sizes, int n_in,
                              void* d_out, int out_size) {
    const float* x     = (const float*)d_in[0];
    const float* mask  = (const float*)d_in[1];
    const float* g1    = (const float*)d_in[2];
    const float* b1    = (const float*)d_in[3];
    const float* g2    = (const float*)d_in[4];
    const float* b2    = (const float*)d_in[5];
    const float* wqs   = (const float*)d_in[6];
    const float* bqs   = (const float*)d_in[7];
    const float* wqm   = (const float*)d_in[8];
    const float* bqm   = (const float*)d_in[9];
    const float* rpb   = (const float*)d_in[10];
    const float* posb  = (const float*)d_in[11];
    const float* wproj = (const float*)d_in[12];
    const float* bproj = (const float*)d_in[13];
    const float* w11   = (const float*)d_in[14];
    const float* b11   = (const float*)d_in[15];
    const float* w12   = (const float*)d_in[16];
    const float* b12   = (const float*)d_in[17];
    const float* w2    = (const float*)d_in[18];
    const float* b2f   = (const float*)d_in[19];
    const int*   rpi   = (const int*)d_in[20];
    float* out = (float*)d_out;

    const int SMEM_QKV  = 128 * 200 * 2 + 2 * 64 * 200 * 2 + 2 * 16 * 68 * 4;
    const int SMEM_PROJ = 128 * 392 * 2 + 64 * 392 * 2 + 128 * 68 * 4 + 128 * 4;
    const int SMEM_MLP  = 128 * 200 * 2 + 64 * 200 * 2 + 2 * 128 * 72 * 2;
    const int SMEM_FC2  = 128 * 392 * 2 + 64 * 392 * 2 + 2 * 128 * 68 * 4 + 128 * 4;
    const int SMEM_ATT  = 3 * 128 * LQ * 2 + 128 * LS2 * 4 + 128 * 4;

    cudaFuncSetAttribute(&gemm_qkv<0, 0, 0>, cudaFuncAttributeMaxDynamicSharedMemorySize, SMEM_QKV);
    cudaFuncSetAttribute(&gemm_qkv<1, 1, 1>, cudaFuncAttributeMaxDynamicSharedMemorySize, SMEM_QKV);
    cudaFuncSetAttribute(gemm_proj, cudaFuncAttributeMaxDynamicSharedMemorySize, SMEM_PROJ);
    cudaFuncSetAttribute(gemm_mlp,  cudaFuncAttributeMaxDynamicSharedMemorySize, SMEM_MLP);
    cudaFuncSetAttribute(gemm_fc2,  cudaFuncAttributeMaxDynamicSharedMemorySize, SMEM_FC2);
    cudaFuncSetAttribute(self_attn_kernel, cudaFuncAttributeMaxDynamicSharedMemorySize, SMEM_ATT);
    cudaFuncSetAttribute(mut_attn_kernel,  cudaFuncAttributeMaxDynamicSharedMemorySize, SMEM_ATT);

    dim3 ga(NHD, NWIN);
    int prep_n = 2 * 576 * 192 + NHD * NTOK * NTOK + NWIN * NTOK * NTOK;
    prep_qkv_kernel<<<(prep_n + 255) / 256, 256>>>(wqs, wqm, rpb, rpi, mask);   // 0
    ln_kernel<0><<<(M_ROWS * 32) / 256, 256>>>(x, g1, b1);                      // 1
    gemm_qkv<0, 0, 0><<<768, 256, SMEM_QKV>>>(bqs, nullptr);                    // 2
    self_attn_kernel<<<ga, 256, SMEM_ATT>>>();                                  // 3 <- ncu slot
    prep_rest_kernel<<<(4 * 192 * 384 + 255) / 256, 256>>>(wproj, w11, w12, w2);// 4
    gemm_qkv<1, 1, 1><<<768, 256, SMEM_QKV>>>(bqm, posb);                       // 5
    mut_attn_kernel<<<ga, 256, SMEM_ATT>>>();                                   // 6
    gemm_proj<<<768, 256, SMEM_PROJ>>>(bproj, x);                               // 7
    ln_kernel<1><<<(M_ROWS * 32) / 256, 256>>>(nullptr, g2, b2);                // 8
    gemm_mlp<<<768, 256, SMEM_MLP>>>(b11, b12);                                 // 9
    gemm_fc2<<<768, 256, SMEM_FC2>>>(b2f, out);                                 // 10
}

// round 16
// speedup vs baseline: 1.5016x; 1.0728x over previous
#include <cuda_runtime.h>
#include <cuda_fp16.h>
#include <mma.h>
#include <cstdint>
#include <math_constants.h>
#include <math.h>

using namespace nvcuda;

// ---------------- problem constants ----------------
#define CC 180
#define NHD 6
#define HDIM 30
#define NWIN 768
#define NTOK 128
#define M_ROWS 98304
#define C3 540
#define C2 360
#define HID 360
#define QKV_STR 576
#define HID_STR 384
#define Y_STR 192
#define ATT_SCALE 0.18257418583505536f

// ---------------- scratch ----------------
__device__ __half g_xw_h[M_ROWS * CC];
__device__ __half g_qkvS_h[M_ROWS * QKV_STR];
__device__ __half g_qkvM_h[M_ROWS * QKV_STR];
__device__ __half g_xo_h[M_ROWS * C2];
__device__ float  g_y[M_ROWS * Y_STR];
__device__ __half g_h2_h[M_ROWS * CC];
__device__ __half g_hid1_h[M_ROWS * HID_STR];
__device__ __half g_bias6_h[NHD * NTOK * NTOK];
__device__ __half g_mask_h[NWIN * NTOK * NTOK];
__device__ __half g_wT_qs[576 * 192];
__device__ __half g_wT_qm[576 * 192];
__device__ __half g_wT_pr[192 * 384];
__device__ __half g_wT_f11[384 * 192];
__device__ __half g_wT_f12[384 * 192];
__device__ __half g_wT_f2[192 * 384];

__device__ __forceinline__ int row_to_img(int r) {
    int win = r >> 7, n = r & 127;
    int dwin = win >> 8, rem = win & 255;
    int hwin = rem >> 4, wwin = rem & 15;
    int nd = n >> 6, nh = (n >> 3) & 7, nw = n & 7;
    int sd = dwin * 2 + nd + 1; if (sd >= 6) sd -= 6;
    int sh = (hwin * 8 + nh + 4) & 127;
    int sw = (wwin * 8 + nw + 4) & 127;
    return (sd * 128 + sh) * 128 + sw;
}

// ---------------- prep kernels ----------------
__device__ __forceinline__ void prep_one(const float* w, __half* wt, int idx,
                                         int K, int N, int Kpad, int Npad) {
    int n = idx / Kpad, k = idx % Kpad;
    wt[idx] = (n < N && k < K) ? __float2half(w[(long)k * N + n]) : __float2half(0.f);
}
__global__ void prep_qkv_kernel(const float* __restrict__ wqs, const float* __restrict__ wqm,
                                const float* __restrict__ rpb, const int* __restrict__ rpi,
                                const float* __restrict__ mask) {
    int idx = blockIdx.x * blockDim.x + threadIdx.x;
    const int S1 = 576 * 192;
    if (idx < S1) { prep_one(wqs, g_wT_qs, idx, CC, C3, 192, 576); return; }
    idx -= S1;
    if (idx < S1) { prep_one(wqm, g_wT_qm, idx, CC, C3, 192, 576); return; }
    idx -= S1;
    if (idx < NHD * NTOK * NTOK) {
        int h = idx / (NTOK * NTOK), ij = idx % (NTOK * NTOK);
        g_bias6_h[idx] = __float2half(rpb[rpi[ij] * NHD + h]);
        return;
    }
    idx -= NHD * NTOK * NTOK;
    if (idx < NWIN * NTOK * NTOK)
        g_mask_h[idx] = __float2half(mask[idx]);
}
__global__ void prep_rest_kernel(const float* __restrict__ wproj, const float* __restrict__ w11,
                                 const float* __restrict__ w12, const float* __restrict__ w2) {
    int idx = blockIdx.x * blockDim.x + threadIdx.x;
    const int S = 192 * 384;
    if (idx < S) prep_one(wproj, g_wT_pr, idx, C2, CC, 384, 192);
    else if (idx < 2 * S) prep_one(w11, g_wT_f11, idx - S, CC, HID, 192, 384);
    else if (idx < 3 * S) prep_one(w12, g_wT_f12, idx - 2 * S, CC, HID, 192, 384);
    else if (idx < 4 * S) prep_one(w2, g_wT_f2, idx - 3 * S, HID, CC, 384, 192);
}

// ---------------- LayerNorm ----------------
template <int MODE>
__global__ __launch_bounds__(256) void ln_kernel(const float* __restrict__ in,
                                                 const float* __restrict__ gg,
                                                 const float* __restrict__ bb) {
    int gw = (blockIdx.x * blockDim.x + threadIdx.x) >> 5;
    int lane = threadIdx.x & 31;
    if (gw >= M_ROWS) return;
    const float* rowp;
    __half* orow;
    if (MODE == 0) {
        rowp = in + (long)row_to_img(gw) * CC;
        orow = g_xw_h + (long)gw * CC;
    } else {
        rowp = g_y + (long)gw * Y_STR;
        orow = g_h2_h + (long)gw * CC;
    }
    float vals[6];
    float s = 0.f, ss = 0.f;
    int cnt = 0;
    for (int c = lane; c < CC; c += 32) { float v = rowp[c]; vals[cnt++] = v; s += v; ss += v * v; }
#pragma unroll
    for (int o = 16; o > 0; o >>= 1) {
        s  += __shfl_xor_sync(0xffffffffu, s, o);
        ss += __shfl_xor_sync(0xffffffffu, ss, o);
    }
    float mean = s * (1.f / CC);
    float var = ss * (1.f / CC) - mean * mean;
    float rstd = rsqrtf(var + 1e-5f);
    cnt = 0;
    for (int c = lane; c < CC; c += 32)
        orow[c] = __float2half((vals[cnt++] - mean) * rstd * gg[c] + bb[c]);
}

// ---------------- qkv GEMM (unchanged) ----------------
template <int WID, int ADD_PB, int DSTID>
__global__ __launch_bounds__(256) void gemm_qkv(const float* __restrict__ bias,
                                                const float* __restrict__ pb) {
    constexpr int KPAD = 192, LDA = 200, LDC = 68, NTILES = 9;
    const __half* A = g_xw_h;
    const __half* BT = (WID == 0) ? g_wT_qs : g_wT_qm;
    __half* Cout = (DSTID == 0) ? g_qkvS_h : g_qkvM_h;
    extern __shared__ __align__(16) char smem[];
    __half* As = (__half*)smem;
    __half* Bs0 = As + 128 * LDA;
    __half* Bs1 = Bs0 + 64 * LDA;
    float* bias0 = (float*)(Bs1 + 64 * LDA);
    float* bias1 = bias0 + 16 * LDC;

    int tid = threadIdx.x, wid = tid >> 5;
    int m0 = blockIdx.x * 128;
    int wm = (wid & 3) * 32, wn = (wid >> 2) * 32;

    constexpr int KF4 = KPAD / 4;
    constexpr int KR4 = CC / 4;
    for (int idx = tid; idx < 128 * KF4; idx += 256) {
        int row = idx / KF4, c4 = idx % KF4;
        uint2 val = make_uint2(0u, 0u);
        if (c4 < KR4) {
            val = *(const uint2*)(A + (long)(m0 + row) * CC + c4 * 4);
            if (ADD_PB) {
                __half2 h0 = *(__half2*)&val.x, h1 = *(__half2*)&val.y;
                float4 p = *(const float4*)(pb + ((m0 + row) & 63) * CC + c4 * 4);
                float2 f0 = __half22float2(h0), f1 = __half22float2(h1);
                __half2 r0 = __floats2half2_rn(f0.x + p.x, f0.y + p.y);
                __half2 r1 = __floats2half2_rn(f1.x + p.z, f1.y + p.w);
                val.x = *(uint32_t*)&r0; val.y = *(uint32_t*)&r1;
            }
        }
        *(uint2*)(As + row * LDA + c4 * 4) = val;
    }

    constexpr int BU4 = KPAD / 8;
    constexpr int NB = (64 * BU4) / 256;
    for (int i = 0; i < NB; i++) {
        int idx = tid + i * 256;
        int n = idx / BU4, c = idx % BU4;
        *(uint4*)(Bs0 + n * LDA + c * 8) = *(const uint4*)(BT + (long)n * KPAD + c * 8);
    }
    for (int i = 0; i < 4; i++) {
        int idx = tid + i * 256;
        int row = idx >> 6, c = idx & 63;
        bias0[row * LDC + c] = bias[c];
    }
    __syncthreads();

    for (int t = 0; t < NTILES; t++) {
        __half* Bcur = (t & 1) ? Bs1 : Bs0;
        __half* Bnxt = (t & 1) ? Bs0 : Bs1;
        float* bcur = (t & 1) ? bias1 : bias0;
        float* bnxt = (t & 1) ? bias0 : bias1;
        int n0 = t * 64;
        bool has_next = (t + 1 < NTILES);

        uint4 breg[NB];
        float creg[4];
        if (has_next) {
            int n0n = n0 + 64;
#pragma unroll
            for (int i = 0; i < NB; i++) {
                int idx = tid + i * 256;
                int n = idx / BU4, c = idx % BU4;
                breg[i] = *(const uint4*)(BT + (long)(n0n + n) * KPAD + c * 8);
            }
#pragma unroll
            for (int i = 0; i < 4; i++) {
                int idx = tid + i * 256;
                int c = idx & 63;
                creg[i] = (n0n + c < C3) ? bias[n0n + c] : 0.f;
            }
        }

        wmma::fragment<wmma::accumulator, 16, 16, 16, float> acc[2][2];
#pragma unroll
        for (int i = 0; i < 2; i++)
#pragma unroll
            for (int j = 0; j < 2; j++)
                wmma::load_matrix_sync(acc[i][j], bcur + wn + j * 16, LDC, wmma::mem_row_major);
#pragma unroll
        for (int k = 0; k < KPAD; k += 16) {
            wmma::fragment<wmma::matrix_a, 16, 16, 16, __half, wmma::row_major> af[2];
            wmma::fragment<wmma::matrix_b, 16, 16, 16, __half, wmma::col_major> bf[2];
#pragma unroll
            for (int i = 0; i < 2; i++)
                wmma::load_matrix_sync(af[i], As + (wm + i * 16) * LDA + k, LDA);
#pragma unroll
            for (int j = 0; j < 2; j++)
                wmma::load_matrix_sync(bf[j], Bcur + (wn + j * 16) * LDA + k, LDA);
#pragma unroll
            for (int i = 0; i < 2; i++)
#pragma unroll
                for (int j = 0; j < 2; j++)
                    wmma::mma_sync(acc[i][j], af[i], bf[j], acc[i][j]);
        }
#pragma unroll
        for (int i = 0; i < 2; i++)
#pragma unroll
            for (int j = 0; j < 2; j++) {
                wmma::fragment<wmma::accumulator, 16, 16, 16, __half> hacc;
#pragma unroll
                for (int e = 0; e < hacc.num_elements; e++)
                    hacc.x[e] = __float2half(acc[i][j].x[e]);
                wmma::store_matrix_sync(Cout + (long)(m0 + wm + i * 16) * QKV_STR + n0 + wn + j * 16,
                                        hacc, QKV_STR, wmma::mem_row_major);
            }
        if (has_next) {
#pragma unroll
            for (int i = 0; i < NB; i++) {
                int idx = tid + i * 256;
                int n = idx / BU4, c = idx % BU4;
                *(uint4*)(Bnxt + n * LDA + c * 8) = breg[i];
            }
#pragma unroll
            for (int i = 0; i < 4; i++) {
                int idx = tid + i * 256;
                int row = idx >> 6, c = idx & 63;
                bnxt[row * LDC + c] = creg[i];
            }
        }
        __syncthreads();
    }
}

// ---------------- proj GEMM (unchanged) ----------------
__global__ __launch_bounds__(256) void gemm_proj(const float* __restrict__ bias,
                                                 const float* __restrict__ x) {
    constexpr int KPAD = 384, LDA = 392, LDC = 68, NTILES = 3;
    extern __shared__ __align__(16) char smem[];
    __half* As = (__half*)smem;
    __half* Bs = As + 128 * LDA;
    float* resT = (float*)(Bs + 64 * LDA);
    int* imgIdx = (int*)(resT + 128 * LDC);

    int tid = threadIdx.x, wid = tid >> 5;
    int m0 = blockIdx.x * 128;
    int wm = (wid & 3) * 32, wn = (wid >> 2) * 32;

    if (tid < 128) imgIdx[tid] = row_to_img(m0 + tid);

    constexpr int KF4 = KPAD / 4;
    constexpr int KR4 = C2 / 4;
    for (int idx = tid; idx < 128 * KF4; idx += 256) {
        int row = idx / KF4, c4 = idx % KF4;
        uint2 val = make_uint2(0u, 0u);
        if (c4 < KR4)
            val = *(const uint2*)(g_xo_h + (long)(m0 + row) * C2 + c4 * 4);
        *(uint2*)(As + row * LDA + c4 * 4) = val;
    }

    constexpr int BU4 = KPAD / 8;
    for (int t = 0; t < NTILES; t++) {
        int n0 = t * 64;
        for (int idx = tid; idx < 64 * BU4; idx += 256) {
            int n = idx / BU4, c = idx % BU4;
            *(uint4*)(Bs + n * LDA + c * 8) = *(const uint4*)(g_wT_pr + (long)(n0 + n) * KPAD + c * 8);
        }
        for (int idx = tid; idx < 128 * 16; idx += 256) {
            int row = idx >> 4, c4 = (idx & 15) * 4;
            int n = n0 + c4;
            float4 v = make_float4(0.f, 0.f, 0.f, 0.f);
            if (n + 4 <= CC) {
                const float4 bv = *(const float4*)(bias + n);
                const float4 xr = *(const float4*)(x + (long)imgIdx[row] * CC + n);
                v.x = bv.x + xr.x; v.y = bv.y + xr.y; v.z = bv.z + xr.z; v.w = bv.w + xr.w;
            }
            *(float4*)(resT + row * LDC + c4) = v;
        }
        __syncthreads();

        wmma::fragment<wmma::accumulator, 16, 16, 16, float> acc[2][2];
#pragma unroll
        for (int i = 0; i < 2; i++)
#pragma unroll
            for (int j = 0; j < 2; j++)
                wmma::load_matrix_sync(acc[i][j], resT + (wm + i * 16) * LDC + wn + j * 16, LDC, wmma::mem_row_major);
#pragma unroll
        for (int k = 0; k < KPAD; k += 16) {
            wmma::fragment<wmma::matrix_a, 16, 16, 16, __half, wmma::row_major> af[2];
            wmma::fragment<wmma::matrix_b, 16, 16, 16, __half, wmma::col_major> bf[2];
#pragma unroll
            for (int i = 0; i < 2; i++)
                wmma::load_matrix_sync(af[i], As + (wm + i * 16) * LDA + k, LDA);
#pragma unroll
            for (int j = 0; j < 2; j++)
                wmma::load_matrix_sync(bf[j], Bs + (wn + j * 16) * LDA + k, LDA);
#pragma unroll
            for (int i = 0; i < 2; i++)
#pragma unroll
                for (int j = 0; j < 2; j++)
                    wmma::mma_sync(acc[i][j], af[i], bf[j], acc[i][j]);
        }
#pragma unroll
        for (int i = 0; i < 2; i++)
#pragma unroll
            for (int j = 0; j < 2; j++)
                wmma::store_matrix_sync(g_y + (long)(m0 + wm + i * 16) * Y_STR + n0 + wn + j * 16,
                                        acc[i][j], Y_STR, wmma::mem_row_major);
        __syncthreads();
    }
}

// ---------------- fused MLP GEMM (unchanged) ----------------
__global__ __launch_bounds__(256, 2) void gemm_mlp(const float* __restrict__ bias1,
                                                   const float* __restrict__ bias2) {
    constexpr int KPAD = 192, LDA = 200, LDCH = 72, NTILES = 6;
    extern __shared__ __align__(16) char smem[];
    __half* As = (__half*)smem;
    __half* Bs = As + 128 * LDA;
    __half* Cs = Bs + 64 * LDA;
    __half* Cs2 = Cs + 128 * LDCH;

    int tid = threadIdx.x, wid = tid >> 5;
    int m0 = blockIdx.x * 128;
    int wm = (wid & 3) * 32, wn = (wid >> 2) * 32;

    constexpr int KF4 = KPAD / 4;
    constexpr int KR4 = CC / 4;
    for (int idx = tid; idx < 128 * KF4; idx += 256) {
        int row = idx / KF4, c4 = idx % KF4;
        uint2 val = make_uint2(0u, 0u);
        if (c4 < KR4)
            val = *(const uint2*)(g_h2_h + (long)(m0 + row) * CC + c4 * 4);
        *(uint2*)(As + row * LDA + c4 * 4) = val;
    }

    constexpr int BU4 = KPAD / 8;
    for (int t = 0; t < NTILES; t++) {
        int n0 = t * 64;
#pragma unroll
        for (int pass = 0; pass < 2; pass++) {
            const __half* Bp = (pass == 0) ? g_wT_f11 : g_wT_f12;
            __half* Cdst = (pass == 0) ? Cs : Cs2;
            for (int idx = tid; idx < 64 * BU4; idx += 256) {
                int n = idx / BU4, c = idx % BU4;
                *(uint4*)(Bs + n * LDA + c * 8) = *(const uint4*)(Bp + (long)(n0 + n) * KPAD + c * 8);
            }
            __syncthreads();
            wmma::fragment<wmma::accumulator, 16, 16, 16, float> acc[2][2];
#pragma unroll
            for (int i = 0; i < 2; i++)
#pragma unroll
                for (int j = 0; j < 2; j++) wmma::fill_fragment(acc[i][j], 0.f);
#pragma unroll
            for (int k = 0; k < KPAD; k += 16) {
                wmma::fragment<wmma::matrix_a, 16, 16, 16, __half, wmma::row_major> af[2];
                wmma::fragment<wmma::matrix_b, 16, 16, 16, __half, wmma::col_major> bf[2];
#pragma unroll
                for (int i = 0; i < 2; i++)
                    wmma::load_matrix_sync(af[i], As + (wm + i * 16) * LDA + k, LDA);
#pragma unroll
                for (int j = 0; j < 2; j++)
                    wmma::load_matrix_sync(bf[j], Bs + (wn + j * 16) * LDA + k, LDA);
#pragma unroll
                for (int i = 0; i < 2; i++)
#pragma unroll
                    for (int j = 0; j < 2; j++)
                        wmma::mma_sync(acc[i][j], af[i], bf[j], acc[i][j]);
            }
#pragma unroll
            for (int i = 0; i < 2; i++)
#pragma unroll
                for (int j = 0; j < 2; j++) {
                    wmma::fragment<wmma::accumulator, 16, 16, 16, __half> hacc;
#pragma unroll
                    for (int e = 0; e < hacc.num_elements; e++)
                        hacc.x[e] = __float2half(acc[i][j].x[e]);
                    wmma::store_matrix_sync(Cdst + (wm + i * 16) * LDCH + wn + j * 16,
                                            hacc, LDCH, wmma::mem_row_major);
                }
            __syncthreads();
        }
        for (int idx = tid; idx < 128 * 16; idx += 256) {
            int row = idx >> 4, c4 = (idx & 15) * 4;
            int n = n0 + c4;
            uint2 u1 = *(uint2*)(Cs + row * LDCH + c4);
            uint2 u2 = *(uint2*)(Cs2 + row * LDCH + c4);
            float2 a0 = __half22float2(*(__half2*)&u1.x), a1 = __half22float2(*(__half2*)&u1.y);
            float2 g0 = __half22float2(*(__half2*)&u2.x), g1v = __half22float2(*(__half2*)&u2.y);
            float b1v[4], b2v[4];
#pragma unroll
            for (int e = 0; e < 4; e++) {
                b1v[e] = (n + e < HID) ? bias1[n + e] : 0.f;
                b2v[e] = (n + e < HID) ? bias2[n + e] : 0.f;
            }
            float v[4] = {a0.x + b1v[0], a0.y + b1v[1], a1.x + b1v[2], a1.y + b1v[3]};
            float v2[4] = {g0.x + b2v[0], g0.y + b2v[1], g1v.x + b2v[2], g1v.y + b2v[3]};
            float o[4];
#pragma unroll
            for (int e = 0; e < 4; e++)
                o[e] = 0.5f * v[e] * (1.f + erff(v[e] * 0.70710678f)) * v2[e];
            __half2 ha = __floats2half2_rn(o[0], o[1]);
            __half2 hb = __floats2half2_rn(o[2], o[3]);
            *(uint2*)(g_hid1_h + (long)(m0 + row) * HID_STR + n0 + c4) =
                make_uint2(*(uint32_t*)&ha, *(uint32_t*)&hb);
        }
        __syncthreads();
    }
}

// ---------------- fc2 GEMM (unchanged) ----------------
__global__ __launch_bounds__(256) void gemm_fc2(const float* __restrict__ bias,
                                                float* __restrict__ out) {
    constexpr int KPAD = 384, LDA = 392, LDC = 68, NTILES = 3;
    extern __shared__ __align__(16) char smem[];
    __half* As = (__half*)smem;
    __half* Bs = As + 128 * LDA;
    float* resT = (float*)(Bs + 64 * LDA);
    float* Cs = resT + 128 * LDC;
    int* imgIdx = (int*)(Cs + 128 * LDC);

    int tid = threadIdx.x, wid = tid >> 5;
    int m0 = blockIdx.x * 128;
    int wm = (wid & 3) * 32, wn = (wid >> 2) * 32;

    if (tid < 128) imgIdx[tid] = row_to_img(m0 + tid);

    constexpr int KF4 = KPAD / 4;
    for (int idx = tid; idx < 128 * KF4; idx += 256) {
        int row = idx / KF4, c4 = idx % KF4;
        *(uint2*)(As + row * LDA + c4 * 4) =
            *(const uint2*)(g_hid1_h + (long)(m0 + row) * HID_STR + c4 * 4);
    }

    constexpr int BU4 = KPAD / 8;
    for (int t = 0; t < NTILES; t++) {
        int n0 = t * 64;
        for (int idx = tid; idx < 64 * BU4; idx += 256) {
            int n = idx / BU4, c = idx % BU4;
            *(uint4*)(Bs + n * LDA + c * 8) = *(const uint4*)(g_wT_f2 + (long)(n0 + n) * KPAD + c * 8);
        }
        for (int idx = tid; idx < 128 * 16; idx += 256) {
            int row = idx >> 4, c4 = (idx & 15) * 4;
            int n = n0 + c4;
            float4 v = make_float4(0.f, 0.f, 0.f, 0.f);
            if (n + 4 <= CC) {
                const float4 bv = *(const float4*)(bias + n);
                const float4 yr = *(const float4*)(g_y + (long)(m0 + row) * Y_STR + n);
                v.x = bv.x + yr.x; v.y = bv.y + yr.y; v.z = bv.z + yr.z; v.w = bv.w + yr.w;
            }
            *(float4*)(resT + row * LDC + c4) = v;
        }
        __syncthreads();

        wmma::fragment<wmma::accumulator, 16, 16, 16, float> acc[2][2];
#pragma unroll
        for (int i = 0; i < 2; i++)
#pragma unroll
            for (int j = 0; j < 2; j++)
                wmma::load_matrix_sync(acc[i][j], resT + (wm + i * 16) * LDC + wn + j * 16, LDC, wmma::mem_row_major);
#pragma unroll
        for (int k = 0; k < KPAD; k += 16) {
            wmma::fragment<wmma::matrix_a, 16, 16, 16, __half, wmma::row_major> af[2];
            wmma::fragment<wmma::matrix_b, 16, 16, 16, __half, wmma::col_major> bf[2];
#pragma unroll
            for (int i = 0; i < 2; i++)
                wmma::load_matrix_sync(af[i], As + (wm + i * 16) * LDA + k, LDA);
#pragma unroll
            for (int j = 0; j < 2; j++)
                wmma::load_matrix_sync(bf[j], Bs + (wn + j * 16) * LDA + k, LDA);
#pragma unroll
            for (int i = 0; i < 2; i++)
#pragma unroll
                for (int j = 0; j < 2; j++)
                    wmma::mma_sync(acc[i][j], af[i], bf[j], acc[i][j]);
        }
#pragma unroll
        for (int i = 0; i < 2; i++)
#pragma unroll
            for (int j = 0; j < 2; j++)
                wmma::store_matrix_sync(Cs + (wm + i * 16) * LDC + wn + j * 16,
                                        acc[i][j], LDC, wmma::mem_row_major);
        __syncthreads();

        for (int idx = tid; idx < 128 * 16; idx += 256) {
            int row = idx >> 4, c4 = (idx & 15) * 4;
            int n = n0 + c4;
            if (n + 4 <= CC) {
                float4 v = *(float4*)(Cs + row * LDC + c4);
                *(float4*)(out + (long)imgIdx[row] * CC + n) = v;
            }
        }
        __syncthreads();
    }
}

// ---------------- self attention: rowsum via V column 31 (no shuffles) ----------------
#define LQ 40
#define LS2 36
#define LO 36
__global__ __launch_bounds__(256, 4) void self_attn_kernel() {
    int h = blockIdx.x, w = blockIdx.y;
    int tid = threadIdx.x, wid = tid >> 5, lane = tid & 31;
    extern __shared__ __align__(16) char smraw[];
    __half* Qs = (__half*)smraw;
    __half* Ks = Qs + 128 * LQ;
    __half* Vs = Ks + 128 * LQ;
    float* S = (float*)(Vs + 128 * LQ);      // [128][36]
    __half* P = (__half*)S;                  // alias, half stride 72

    const __half* base = g_qkvS_h + (long)w * NTOK * QKV_STR + h * HDIM;
    const float scl = ATT_SCALE;

    for (int idx = tid; idx < 3 * 128 * 15; idx += 256) {
        int region = idx / (128 * 15);
        int rem = idx - region * (128 * 15);
        int row = rem / 15, c = rem - row * 15;
        uint32_t v = *(const uint32_t*)(base + (long)row * QKV_STR + region * 180 + c * 2);
        __half* dst = (region == 0) ? Qs : (region == 1) ? Ks : Vs;
        if (region == 0) {
            float2 f = __half22float2(*(__half2*)&v);
            __half2 r = __floats2half2_rn(f.x * scl, f.y * scl);
            v = *(uint32_t*)&r;
        }
        *(uint32_t*)(dst + row * LQ + c * 2) = v;
    }
    if (tid < 128) {
        uint32_t z = 0;
        __half2 ones = __floats2half2_rn(0.f, 1.f);   // V[row][30]=0, V[row][31]=1 -> O[.][31] = rowsum(P)
        *(uint32_t*)(Qs + tid * LQ + 30) = z;
        *(uint32_t*)(Ks + tid * LQ + 30) = z;
        *(uint32_t*)(Vs + tid * LQ + 30) = *(uint32_t*)&ones;
    }
    __syncthreads();

    wmma::fragment<wmma::accumulator, 16, 16, 16, float> oacc[2];
    wmma::fill_fragment(oacc[0], 0.f);
    wmma::fill_fragment(oacc[1], 0.f);

    const __half* bbase = g_bias6_h + h * (NTOK * NTOK);
    const __half* mbase = g_mask_h + (long)w * (NTOK * NTOK);

#pragma unroll
    for (int kc = 0; kc < 4; kc++) {
        int k0 = kc * 32;

        // S panel = Q @ K[k0:k0+32]^T (warp-private rows wid*16)
        {
            wmma::fragment<wmma::accumulator, 16, 16, 16, float> acc[2];
            wmma::fill_fragment(acc[0], 0.f);
            wmma::fill_fragment(acc[1], 0.f);
#pragma unroll
            for (int k = 0; k < 2; k++) {
                wmma::fragment<wmma::matrix_a, 16, 16, 16, __half, wmma::row_major> af;
                wmma::load_matrix_sync(af, Qs + (wid * 16) * LQ + k * 16, LQ);
#pragma unroll
                for (int j = 0; j < 2; j++) {
                    wmma::fragment<wmma::matrix_b, 16, 16, 16, __half, wmma::col_major> bf;
                    wmma::load_matrix_sync(bf, Ks + (k0 + j * 16) * LQ + k * 16, LQ);
                    wmma::mma_sync(acc[j], af, bf, acc[j]);
                }
            }
#pragma unroll
            for (int j = 0; j < 2; j++)
                wmma::store_matrix_sync(S + (wid * 16) * LS2 + j * 16, acc[j], LS2, wmma::mem_row_major);
        }
        __syncwarp();

        // partial softmax (no reduction): exp + store P fp16
        {
#pragma unroll
            for (int rr = 0; rr < 16; rr++) {
                int r = wid * 16 + rr;
                float s = S[r * LS2 + lane];
                float b = __half2float(bbase[r * NTOK + k0 + lane]);
                float m = __half2float(mbase[r * NTOK + k0 + lane]);
                float p = __expf(s + b + m);
                P[r * 72 + lane] = __float2half(p);
            }
        }
        __syncwarp();

        // O += P_panel @ V[k0:k0+32]   (col 31 of V = 1 -> O[:,31] accumulates rowsum)
        {
#pragma unroll
            for (int k = 0; k < 2; k++) {
                wmma::fragment<wmma::matrix_a, 16, 16, 16, __half, wmma::row_major> pf;
                wmma::load_matrix_sync(pf, P + (wid * 16) * 72 + k * 16, 72);
#pragma unroll
                for (int j = 0; j < 2; j++) {
                    wmma::fragment<wmma::matrix_b, 16, 16, 16, __half, wmma::row_major> vf;
                    wmma::load_matrix_sync(vf, Vs + (k0 + k * 16) * LQ + j * 16, LQ);
                    wmma::mma_sync(oacc[j], pf, vf, oacc[j]);
                }
            }
        }
        __syncwarp();
    }

    float* Of = S;
#pragma unroll
    for (int j = 0; j < 2; j++)
        wmma::store_matrix_sync(Of + (wid * 16) * LO + j * 16, oacc[j], LO, wmma::mem_row_major);
    __syncthreads();

    {
        int row = tid >> 1, part = tid & 1;
        float inv = 1.f / Of[row * LO + 31];
        __half* orow = g_xo_h + (long)(w * NTOK + row) * C2 + CC + h * HDIM;
        int d0 = part * 15;
#pragma unroll
        for (int dd = 0; dd < 15; dd++)
            orow[d0 + dd] = __float2half(Of[row * LO + d0 + dd] * inv);
    }
}

// ---------------- mutual attention: rowsum via V column 31 ----------------
__global__ __launch_bounds__(256, 4) void mut_attn_kernel() {
    int h = blockIdx.x, w = blockIdx.y;
    int tid = threadIdx.x, wid = tid >> 5, lane = tid & 31;
    extern __shared__ __align__(16) char smraw[];
    __half* Qs = (__half*)smraw;
    __half* Ks = Qs + 128 * LQ;
    __half* Vs = Ks + 128 * LQ;
    float* S = (float*)(Vs + 128 * LQ);
    __half* P = (__half*)S;

    const __half* base = g_qkvM_h + (long)w * NTOK * QKV_STR + h * HDIM;
    const float scl = ATT_SCALE;

    for (int idx = tid; idx < 3 * 128 * 15; idx += 256) {
        int region = idx / (128 * 15);
        int rem = idx - region * (128 * 15);
        int row = rem / 15, c = rem - row * 15;
        int srow = row;
        if (region == 0) srow = (row < 64) ? (64 + row) : (row - 64);
        uint32_t v = *(const uint32_t*)(base + (long)srow * QKV_STR + region * 180 + c * 2);
        __half* dst = (region == 0) ? Qs : (region == 1) ? Ks : Vs;
        if (region == 0) {
            float2 f = __half22float2(*(__half2*)&v);
            __half2 r = __floats2half2_rn(f.x * scl, f.y * scl);
            v = *(uint32_t*)&r;
        }
        *(uint32_t*)(dst + row * LQ + c * 2) = v;
    }
    if (tid < 128) {
        uint32_t z = 0;
        __half2 ones = __floats2half2_rn(0.f, 1.f);
        *(uint32_t*)(Qs + tid * LQ + 30) = z;
        *(uint32_t*)(Ks + tid * LQ + 30) = z;
        *(uint32_t*)(Vs + tid * LQ + 30) = *(uint32_t*)&ones;
    }
    __syncthreads();

    int g = wid >> 2, mt = wid & 3;

    wmma::fragment<wmma::accumulator, 16, 16, 16, float> oacc[2];
    wmma::fill_fragment(oacc[0], 0.f);
    wmma::fill_fragment(oacc[1], 0.f);

    const __half* mbase = g_mask_h + (long)w * (NTOK * NTOK);

#pragma unroll
    for (int kc = 0; kc < 2; kc++) {
        {
            wmma::fragment<wmma::accumulator, 16, 16, 16, float> acc[2];
            wmma::fill_fragment(acc[0], 0.f);
            wmma::fill_fragment(acc[1], 0.f);
#pragma unroll
            for (int k = 0; k < 2; k++) {
                wmma::fragment<wmma::matrix_a, 16, 16, 16, __half, wmma::row_major> af;
                wmma::load_matrix_sync(af, Qs + (g * 64 + mt * 16) * LQ + k * 16, LQ);
#pragma unroll
                for (int j = 0; j < 2; j++) {
                    wmma::fragment<wmma::matrix_b, 16, 16, 16, __half, wmma::col_major> bf;
                    wmma::load_matrix_sync(bf, Ks + (g * 64 + kc * 32 + j * 16) * LQ + k * 16, LQ);
                    wmma::mma_sync(acc[j], af, bf, acc[j]);
                }
            }
#pragma unroll
            for (int j = 0; j < 2; j++)
                wmma::store_matrix_sync(S + (g * 64 + mt * 16) * LS2 + j * 16, acc[j], LS2, wmma::mem_row_major);
        }
        __syncwarp();

        {
#pragma unroll
            for (int rr = 0; rr < 16; rr++) {
                int r = wid * 16 + rr;
                int i = r & 63;
                float s = S[r * LS2 + lane];
                float m = __half2float(mbase[i * NTOK + kc * 32 + lane]);
                float p = __expf(s + m);
                P[r * 72 + lane] = __float2half(p);
            }
        }
        __syncwarp();

        {
#pragma unroll
            for (int k = 0; k < 2; k++) {
                wmma::fragment<wmma::matrix_a, 16, 16, 16, __half, wmma::row_major> pf;
                wmma::load_matrix_sync(pf, P + (g * 64 + mt * 16) * 72 + k * 16, 72);
#pragma unroll
                for (int j = 0; j < 2; j++) {
                    wmma::fragment<wmma::matrix_b, 16, 16, 16, __half, wmma::row_major> vf;
                    wmma::load_matrix_sync(vf, Vs + (g * 64 + kc * 32 + k * 16) * LQ + j * 16, LQ);
                    wmma::mma_sync(oacc[j], pf, vf, oacc[j]);
                }
            }
        }
        __syncwarp();
    }

    float* Of = S;
#pragma unroll
    for (int j = 0; j < 2; j++)
        wmma::store_matrix_sync(Of + (g * 64 + mt * 16) * LO + j * 16, oacc[j], LO, wmma::mem_row_major);
    __syncthreads();

    {
        int row = tid >> 1, part = tid & 1;
        float inv = 1.f / Of[row * LO + 31];
        __half* orow = g_xo_h + (long)(w * NTOK + row) * C2 + h * HDIM;
        int d0 = part * 15;
#pragma unroll
        for (int dd = 0; dd < 15; dd++)
            orow[d0 + dd] = __float2half(Of[row * LO + d0 + dd] * inv);
    }
}

// ---------------- launcher ----------------
extern "C" void kernel_launch(void* const* d_in, const int* in_sizes, int n_in,
                              void* d_out, int out_size) {
    const float* x     = (const float*)d_in[0];
    const float* mask  = (const float*)d_in[1];
    const float* g1    = (const float*)d_in[2];
    const float* b1    = (const float*)d_in[3];
    const float* g2    = (const float*)d_in[4];
    const float* b2    = (const float*)d_in[5];
    const float* wqs   = (const float*)d_in[6];
    const float* bqs   = (const float*)d_in[7];
    const float* wqm   = (const float*)d_in[8];
    const float* bqm   = (const float*)d_in[9];
    const float* rpb   = (const float*)d_in[10];
    const float* posb  = (const float*)d_in[11];
    const float* wproj = (const float*)d_in[12];
    const float* bproj = (const float*)d_in[13];
    const float* w11   = (const float*)d_in[14];
    const float* b11   = (const float*)d_in[15];
    const float* w12   = (const float*)d_in[16];
    const float* b12   = (const float*)d_in[17];
    const float* w2    = (const float*)d_in[18];
    const float* b2f   = (const float*)d_in[19];
    const int*   rpi   = (const int*)d_in[20];
    float* out = (float*)d_out;

    const int SMEM_QKV  = 128 * 200 * 2 + 2 * 64 * 200 * 2 + 2 * 16 * 68 * 4;
    const int SMEM_PROJ = 128 * 392 * 2 + 64 * 392 * 2 + 128 * 68 * 4 + 128 * 4;
    const int SMEM_MLP  = 128 * 200 * 2 + 64 * 200 * 2 + 2 * 128 * 72 * 2;
    const int SMEM_FC2  = 128 * 392 * 2 + 64 * 392 * 2 + 2 * 128 * 68 * 4 + 128 * 4;
    const int SMEM_ATT  = 3 * 128 * LQ * 2 + 128 * LS2 * 4;

    cudaFuncSetAttribute(&gemm_qkv<0, 0, 0>, cudaFuncAttributeMaxDynamicSharedMemorySize, SMEM_QKV);
    cudaFuncSetAttribute(&gemm_qkv<1, 1, 1>, cudaFuncAttributeMaxDynamicSharedMemorySize, SMEM_QKV);
    cudaFuncSetAttribute(gemm_proj, cudaFuncAttributeMaxDynamicSharedMemorySize, SMEM_PROJ);
    cudaFuncSetAttribute(gemm_mlp,  cudaFuncAttributeMaxDynamicSharedMemorySize, SMEM_MLP);
    cudaFuncSetAttribute(gemm_fc2,  cudaFuncAttributeMaxDynamicSharedMemorySize, SMEM_FC2);
    cudaFuncSetAttribute(self_attn_kernel, cudaFuncAttributeMaxDynamicSharedMemorySize, SMEM_ATT);
    cudaFuncSetAttribute(mut_attn_kernel,  cudaFuncAttributeMaxDynamicSharedMemorySize, SMEM_ATT);

    dim3 ga(NHD, NWIN);
    int prep_n = 2 * 576 * 192 + NHD * NTOK * NTOK + NWIN * NTOK * NTOK;
    prep_qkv_kernel<<<(prep_n + 255) / 256, 256>>>(wqs, wqm, rpb, rpi, mask);   // 0
    ln_kernel<0><<<(M_ROWS * 32) / 256, 256>>>(x, g1, b1);                      // 1
    gemm_qkv<0, 0, 0><<<768, 256, SMEM_QKV>>>(bqs, nullptr);                    // 2
    self_attn_kernel<<<ga, 256, SMEM_ATT>>>();                                  // 3 <- ncu slot
    prep_rest_kernel<<<(4 * 192 * 384 + 255) / 256, 256>>>(wproj, w11, w12, w2);// 4
    gemm_qkv<1, 1, 1><<<768, 256, SMEM_QKV>>>(bqm, posb);                       // 5
    mut_attn_kernel<<<ga, 256, SMEM_ATT>>>();                                   // 6
    gemm_proj<<<768, 256, SMEM_PROJ>>>(bproj, x);                               // 7
    ln_kernel<1><<<(M_ROWS * 32) / 256, 256>>>(nullptr, g2, b2);                // 8
    gemm_mlp<<<768, 256, SMEM_MLP>>>(b11, b12);                                 // 9
    gemm_fc2<<<768, 256, SMEM_FC2>>>(b2f, out);                                 // 10
}